// round 1
// baseline (speedup 1.0000x reference)
#include <cuda_runtime.h>
#include <cstddef>

// Problem constants
#define Bq    4
#define NTOK  4096
#define CDIM  768
#define Hh    8
#define HDd   96
#define MROWS (Bq * NTOK)          // 16384
#define SPLIT 8
#define BHn   (Bq * Hh)            // 32
#define SCALE_F 0.10206207261596577f   // 96^-0.5
#define EPSN 1e-12f

// -------- scratch (device globals; no allocation allowed) --------
__device__ float g_q [(size_t)MROWS * CDIM];          // [B,N,C]   q projection
__device__ float g_kv[(size_t)MROWS * 2 * CDIM];      // [B,N,2C]  k | v
__device__ float g_x [(size_t)MROWS * CDIM];          // [B,N,C]   attn output (token-major)
__device__ float g_attn[BHn * HDd * HDd];             // softmaxed attention
__device__ float g_part[SPLIT * BHn * HDd * HDd];     // Gram partials
__device__ float g_qsq [SPLIT * BHn * HDd];           // q row sumsq partials
__device__ float g_ksq [SPLIT * BHn * HDd];           // k row sumsq partials

// ============================================================
// Generic fp32 tiled GEMM: C[M,Nc] = A[M,K] @ B[K,Nc] (+bias)
// 128x128 tile, Ktile=8, 256 threads, 8x8 per-thread microtile
// ============================================================
__global__ __launch_bounds__(256) void gemm_kernel(
    const float* __restrict__ A, const float* __restrict__ Bm,
    const float* __restrict__ bias, float* __restrict__ Cout,
    int K, int Nc)
{
    __shared__ float As[8][132];   // [k][m], padded (132*4 % 16 == 0)
    __shared__ float Bs[8][128];   // [k][n]

    const int tid = threadIdx.x;
    const int m0 = blockIdx.y * 128;
    const int n0 = blockIdx.x * 128;
    const int tm = tid >> 4;       // 0..15
    const int tn = tid & 15;       // 0..15

    const int ar  = tid >> 1;          // A tile row 0..127
    const int akq = (tid & 1) * 4;     // A tile k offset 0 or 4
    const int br  = tid >> 5;          // B tile row 0..7
    const int bc  = (tid & 31) * 4;    // B tile col 0..124

    float acc[8][8];
    #pragma unroll
    for (int i = 0; i < 8; i++)
        #pragma unroll
        for (int j = 0; j < 8; j++) acc[i][j] = 0.f;

    for (int k0 = 0; k0 < K; k0 += 8) {
        float4 av = *reinterpret_cast<const float4*>(&A[(size_t)(m0 + ar) * K + k0 + akq]);
        float4 bv = *reinterpret_cast<const float4*>(&Bm[(size_t)(k0 + br) * Nc + n0 + bc]);
        __syncthreads();
        As[akq + 0][ar] = av.x;
        As[akq + 1][ar] = av.y;
        As[akq + 2][ar] = av.z;
        As[akq + 3][ar] = av.w;
        *reinterpret_cast<float4*>(&Bs[br][bc]) = bv;
        __syncthreads();

        #pragma unroll
        for (int kk = 0; kk < 8; kk++) {
            float a[8], b[8];
            #pragma unroll
            for (int i = 0; i < 8; i++) a[i] = As[kk][tm * 8 + i];
            #pragma unroll
            for (int j = 0; j < 8; j++) b[j] = Bs[kk][tn * 8 + j];
            #pragma unroll
            for (int i = 0; i < 8; i++)
                #pragma unroll
                for (int j = 0; j < 8; j++)
                    acc[i][j] += a[i] * b[j];
        }
    }

    // epilogue
    #pragma unroll
    for (int i = 0; i < 8; i++) {
        const int m = m0 + tm * 8 + i;
        #pragma unroll
        for (int j = 0; j < 8; j += 4) {
            float4 v;
            v.x = acc[i][j + 0];
            v.y = acc[i][j + 1];
            v.z = acc[i][j + 2];
            v.w = acc[i][j + 3];
            if (bias) {
                const int n = n0 + tn * 8 + j;
                v.x += bias[n + 0]; v.y += bias[n + 1];
                v.z += bias[n + 2]; v.w += bias[n + 3];
            }
            *reinterpret_cast<float4*>(&Cout[(size_t)m * Nc + n0 + tn * 8 + j]) = v;
        }
    }
}

// ============================================================
// Gram partials: per (b,h,split): part[d,e] = sum_n q[d,n]k[e,n]
// plus sum-of-squares partials of q rows / k rows.
// block 256 = 16(ty:d-groups) x 16(tx:e-groups), 6x6 microtile
// ============================================================
__global__ __launch_bounds__(256) void attn_part_kernel()
{
    const int bh = blockIdx.x;
    const int b  = bh >> 3;
    const int h  = bh & 7;
    const int split = blockIdx.y;

    __shared__ float qs[32][100];
    __shared__ float ks[32][100];

    const int tid = threadIdx.x;
    const int tx = tid & 15;
    const int ty = tid >> 4;

    float acc[6][6];
    #pragma unroll
    for (int i = 0; i < 6; i++)
        #pragma unroll
        for (int j = 0; j < 6; j++) acc[i][j] = 0.f;
    float sq[6] = {0.f, 0.f, 0.f, 0.f, 0.f, 0.f};
    float sk[6] = {0.f, 0.f, 0.f, 0.f, 0.f, 0.f};

    const float* qbase = g_q  + (size_t)(b * NTOK) * CDIM     + h * HDd;
    const float* kbase = g_kv + (size_t)(b * NTOK) * 2 * CDIM + h * HDd;

    const int nbeg = split * (NTOK / SPLIT);
    const int nend = nbeg + (NTOK / SPLIT);

    for (int n0 = nbeg; n0 < nend; n0 += 32) {
        __syncthreads();
        #pragma unroll
        for (int it = 0; it < 12; it++) {
            const int i = tid + it * 256;      // 32*96 = 3072 elements
            const int r = i / 96, c = i % 96;
            qs[r][c] = qbase[(size_t)(n0 + r) * CDIM + c];
            ks[r][c] = kbase[(size_t)(n0 + r) * 2 * CDIM + c];
        }
        __syncthreads();

        #pragma unroll 8
        for (int kk = 0; kk < 32; kk++) {
            float a[6], bb[6];
            #pragma unroll
            for (int i = 0; i < 6; i++) a[i]  = qs[kk][ty * 6 + i];
            #pragma unroll
            for (int j = 0; j < 6; j++) bb[j] = ks[kk][tx * 6 + j];
            #pragma unroll
            for (int i = 0; i < 6; i++)
                #pragma unroll
                for (int j = 0; j < 6; j++)
                    acc[i][j] += a[i] * bb[j];
            if (tx == 0) {
                #pragma unroll
                for (int i = 0; i < 6; i++) sq[i] += a[i] * a[i];
            }
            if (ty == 0) {
                #pragma unroll
                for (int j = 0; j < 6; j++) sk[j] += bb[j] * bb[j];
            }
        }
    }

    const int po = split * BHn + bh;
    float* op = g_part + (size_t)po * (HDd * HDd);
    #pragma unroll
    for (int i = 0; i < 6; i++)
        #pragma unroll
        for (int j = 0; j < 6; j++)
            op[(ty * 6 + i) * HDd + tx * 6 + j] = acc[i][j];
    if (tx == 0) {
        #pragma unroll
        for (int i = 0; i < 6; i++) g_qsq[po * HDd + ty * 6 + i] = sq[i];
    }
    if (ty == 0) {
        #pragma unroll
        for (int j = 0; j < 6; j++) g_ksq[po * HDd + tx * 6 + j] = sk[j];
    }
}

// ============================================================
// Reduce partials + cosine scale + softmax over e.
// grid = BH, block = 96 (thread d handles one row)
// ============================================================
__global__ __launch_bounds__(96) void softmax_kernel()
{
    const int bh = blockIdx.x;
    const int d  = threadIdx.x;

    __shared__ float nq[HDd], nk[HDd];
    {
        float sq = 0.f, sk = 0.f;
        #pragma unroll
        for (int p = 0; p < SPLIT; p++) {
            sq += g_qsq[(p * BHn + bh) * HDd + d];
            sk += g_ksq[(p * BHn + bh) * HDd + d];
        }
        nq[d] = fmaxf(sqrtf(sq), EPSN);
        nk[d] = fmaxf(sqrtf(sk), EPSN);
    }
    __syncthreads();

    float row[HDd];
    const float invq = SCALE_F / nq[d];
    float mx = -1e30f;
    for (int e = 0; e < HDd; e++) {
        float s = 0.f;
        #pragma unroll
        for (int p = 0; p < SPLIT; p++)
            s += g_part[(size_t)(p * BHn + bh) * (HDd * HDd) + d * HDd + e];
        const float a = s * invq / nk[e];
        row[e] = a;
        mx = fmaxf(mx, a);
    }
    float sum = 0.f;
    for (int e = 0; e < HDd; e++) {
        row[e] = __expf(row[e] - mx);
        sum += row[e];
    }
    const float inv = 1.f / sum;
    float* op = g_attn + (size_t)bh * (HDd * HDd) + d * HDd;
    for (int e = 0; e < HDd; e++) op[e] = row[e] * inv;
}

// ============================================================
// x[b,n,h,d] = sum_e attn[b,h,d,e] * v[b,n,h,e]
// grid (ntiles=64, bh=32); block 256 = 16 token-groups x 16 d-groups
// 64 tokens per block, microtile 4 tokens x 6 d
// ============================================================
__global__ __launch_bounds__(256) void av_kernel()
{
    const int bh = blockIdx.y;
    const int b  = bh >> 3;
    const int h  = bh & 7;
    const int n0 = blockIdx.x * 64;

    __shared__ float vs[64][33];
    __shared__ float at[96][33];

    const int tid = threadIdx.x;
    const int tg = tid >> 4;      // 0..15
    const int dg = tid & 15;      // 0..15
    const int t0 = tg * 4;
    const int d0 = dg * 6;

    float acc[4][6];
    #pragma unroll
    for (int i = 0; i < 4; i++)
        #pragma unroll
        for (int j = 0; j < 6; j++) acc[i][j] = 0.f;

    const float* vbase = g_kv + (size_t)(b * NTOK) * (2 * CDIM) + CDIM + h * HDd;
    const float* abase = g_attn + (size_t)bh * (HDd * HDd);

    for (int e0 = 0; e0 < HDd; e0 += 32) {
        __syncthreads();
        #pragma unroll
        for (int it = 0; it < 8; it++) {          // 64*32 = 2048
            const int i = tid + it * 256;
            const int r = i >> 5, c = i & 31;
            vs[r][c] = vbase[(size_t)(n0 + r) * (2 * CDIM) + e0 + c];
        }
        #pragma unroll
        for (int it = 0; it < 12; it++) {         // 96*32 = 3072
            const int i = tid + it * 256;
            const int r = i >> 5, c = i & 31;
            at[r][c] = abase[r * HDd + e0 + c];
        }
        __syncthreads();

        #pragma unroll 8
        for (int e = 0; e < 32; e++) {
            float vv[4], aa[6];
            #pragma unroll
            for (int i = 0; i < 4; i++) vv[i] = vs[t0 + i][e];
            #pragma unroll
            for (int j = 0; j < 6; j++) aa[j] = at[d0 + j][e];
            #pragma unroll
            for (int i = 0; i < 4; i++)
                #pragma unroll
                for (int j = 0; j < 6; j++)
                    acc[i][j] += vv[i] * aa[j];
        }
    }

    float* xbase = g_x + (size_t)(b * NTOK) * CDIM + h * HDd;
    #pragma unroll
    for (int i = 0; i < 4; i++)
        #pragma unroll
        for (int j = 0; j < 6; j++)
            xbase[(size_t)(n0 + t0 + i) * CDIM + d0 + j] = acc[i][j];
}

// ============================================================
extern "C" void kernel_launch(void* const* d_in, const int* in_sizes, int n_in,
                              void* d_out, int out_size)
{
    const float* cx  = (const float*)d_in[0];
    const float* dx  = (const float*)d_in[1];
    const float* Wq  = (const float*)d_in[2];
    const float* Wkv = (const float*)d_in[3];
    const float* Wp  = (const float*)d_in[4];
    const float* bp  = (const float*)d_in[5];
    float* out = (float*)d_out;

    float *qp, *kvp, *xp;
    cudaGetSymbolAddress((void**)&qp,  g_q);
    cudaGetSymbolAddress((void**)&kvp, g_kv);
    cudaGetSymbolAddress((void**)&xp,  g_x);

    // 1. q = context_x @ Wq          [16384,768] x [768,768]
    gemm_kernel<<<dim3(CDIM / 128, MROWS / 128), 256>>>(cx, Wq, nullptr, qp, CDIM, CDIM);
    // 2. kv = depth_x @ Wkv          [16384,768] x [768,1536]
    gemm_kernel<<<dim3(2 * CDIM / 128, MROWS / 128), 256>>>(dx, Wkv, nullptr, kvp, CDIM, 2 * CDIM);
    // 3. Gram partials + sumsq partials (split-K over tokens)
    attn_part_kernel<<<dim3(BHn, SPLIT), 256>>>();
    // 4. reduce + cosine scale + softmax
    softmax_kernel<<<BHn, 96>>>();
    // 5. x = attn @ v (token-major output)
    av_kernel<<<dim3(NTOK / 64, BHn), 256>>>();
    // 6. out = x @ Wproj + bproj
    gemm_kernel<<<dim3(CDIM / 128, MROWS / 128), 256>>>(xp, Wp, bp, out, CDIM, CDIM);
}

// round 3
// speedup vs baseline: 1.1621x; 1.1621x over previous
#include <cuda_runtime.h>
#include <cuda_bf16.h>
#include <cstdint>
#include <cstddef>

// ---------------- problem constants ----------------
#define Bq    4
#define NTOK  4096
#define CDIM  768
#define Hh    8
#define HDd   96
#define MROWS (Bq * NTOK)          // 16384
#define SPLIT 8
#define BHn   (Bq * Hh)            // 32
#define SCALE_F 0.10206207261596577f
#define EPSN 1e-12f

// ---------------- scratch (device globals) ----------------
__device__ __nv_bfloat16 g_a1h[(size_t)MROWS * CDIM];
__device__ __nv_bfloat16 g_a1l[(size_t)MROWS * CDIM];
__device__ __nv_bfloat16 g_a2h[(size_t)MROWS * CDIM];
__device__ __nv_bfloat16 g_a2l[(size_t)MROWS * CDIM];
__device__ __nv_bfloat16 g_xh [(size_t)MROWS * CDIM];
__device__ __nv_bfloat16 g_xl [(size_t)MROWS * CDIM];
__device__ __nv_bfloat16 g_wqh[CDIM * CDIM];
__device__ __nv_bfloat16 g_wql[CDIM * CDIM];
__device__ __nv_bfloat16 g_wkh[2 * CDIM * CDIM];
__device__ __nv_bfloat16 g_wkl[2 * CDIM * CDIM];
__device__ __nv_bfloat16 g_wph[CDIM * CDIM];
__device__ __nv_bfloat16 g_wpl[CDIM * CDIM];
__device__ float g_q [(size_t)MROWS * CDIM];
__device__ float g_kv[(size_t)MROWS * 2 * CDIM];
__device__ float g_attn[BHn * HDd * HDd];
__device__ float g_part[SPLIT * BHn * HDd * HDd];
__device__ float g_qsq [SPLIT * BHn * HDd];
__device__ float g_ksq [SPLIT * BHn * HDd];

// ---------------- helpers ----------------
__device__ __forceinline__ uint32_t s2u(const void* p) {
    uint32_t a;
    asm("{ .reg .u64 t; cvta.to.shared.u64 t, %1; cvt.u32.u64 %0, t; }" : "=r"(a) : "l"(p));
    return a;
}

__device__ __forceinline__ void cp16(uint32_t dst, const void* src) {
    asm volatile("cp.async.cg.shared.global [%0], [%1], 16;" :: "r"(dst), "l"(src));
}
__device__ __forceinline__ void cp_commit() {
    asm volatile("cp.async.commit_group;");
}
template <int N>
__device__ __forceinline__ void cp_wait() {
    asm volatile("cp.async.wait_group %0;" :: "n"(N));
}

__device__ __forceinline__ void ldsm4(uint32_t& r0, uint32_t& r1, uint32_t& r2, uint32_t& r3,
                                      uint32_t addr) {
    asm volatile("ldmatrix.sync.aligned.m8n8.x4.shared.b16 {%0,%1,%2,%3}, [%4];"
                 : "=r"(r0), "=r"(r1), "=r"(r2), "=r"(r3) : "r"(addr));
}

__device__ __forceinline__ void mma_bf16(float& c0, float& c1, float& c2, float& c3,
                                         uint32_t a0, uint32_t a1, uint32_t a2, uint32_t a3,
                                         uint32_t b0, uint32_t b1) {
    asm volatile(
        "mma.sync.aligned.m16n8k16.row.col.f32.bf16.bf16.f32 "
        "{%0,%1,%2,%3}, {%4,%5,%6,%7}, {%8,%9}, {%0,%1,%2,%3};"
        : "+f"(c0), "+f"(c1), "+f"(c2), "+f"(c3)
        : "r"(a0), "r"(a1), "r"(a2), "r"(a3), "r"(b0), "r"(b1));
}

// ============================================================
// mma.sync 3xBF16 GEMM: C[M,Nc] = A[M,768] @ B[Nc,768]^T (+bias)
// CTA 128x128, Ktile=64 (128B SW128 rows), 4-stage cp.async pipe
// 36 k-tiles: [0,12)=Ah*Bh, [12,24)=Ah*Bl, [24,36)=Al*Bh
// ============================================================
#define PIPE      4
#define TILE_B    16384                // one operand tile: 128 rows x 128B
#define STAGE_B   (2 * TILE_B)         // A + B
#define GSMEM     (PIPE * STAGE_B)     // 131072
#define NKT       36

__global__ __launch_bounds__(256, 1) void gemm_mma(
    const __nv_bfloat16* __restrict__ Ah, const __nv_bfloat16* __restrict__ Al,
    const __nv_bfloat16* __restrict__ Bh, const __nv_bfloat16* __restrict__ Bl,
    const float* __restrict__ bias, float* __restrict__ Cout, int Nc)
{
    extern __shared__ __align__(1024) char smem[];
    const uint32_t sbase = s2u(smem);

    const int tid  = threadIdx.x;
    const int lane = tid & 31;
    const int wid  = tid >> 5;
    const int m0 = blockIdx.y * 128;
    const int n0 = blockIdx.x * 128;
    const int wm = (wid >> 2) * 64;    // warp m offset (2 rows of warps)
    const int wn = (wid & 3) * 32;     // warp n offset (4 cols of warps)

    // cp.async assignment: 2048 16B-chunks per stage, 8 per thread
    // chunk c (0..2047): first 1024 A, next 1024 B; row=(c>>3)&127, x16=c&7
    const int cprow = (tid >> 3) & 127;        // careful: derive per i below
    (void)cprow;

    // ldmatrix A per-thread constants
    const uint32_t a_row   = wm + (lane & 15);
    const uint32_t a_swz   = (lane & 7) * 16;
    const uint32_t a_xhalf = (lane >> 4) * 16;
    // B LDS per-thread constants
    const uint32_t b_row = wn + (lane >> 2);
    const uint32_t b_swz = (lane >> 2 & 7) * 16;
    const uint32_t b_x0  = (lane & 3) * 4;

    float acc[4][4][4];
    #pragma unroll
    for (int i = 0; i < 4; i++)
        #pragma unroll
        for (int j = 0; j < 4; j++)
            #pragma unroll
            for (int c = 0; c < 4; c++) acc[i][j][c] = 0.f;

    // ---- stage issue helper (inlined via lambda) ----
    auto issue = [&](int kt, int slot) {
        const int pp = kt / 12;
        const int k0 = (kt % 12) * 64;
        const __nv_bfloat16* pa = (pp == 2) ? Al : Ah;
        const __nv_bfloat16* pb = (pp == 1) ? Bl : Bh;
        const uint32_t sA = sbase + slot * STAGE_B;
        const uint32_t sB = sA + TILE_B;
        #pragma unroll
        for (int i = 0; i < 8; i++) {
            const int c = tid + i * 256;           // 0..2047
            const int row = (c >> 3) & 127;
            const int x16 = c & 7;
            const uint32_t off = (uint32_t)(row * 128 + ((x16 * 16) ^ ((row & 7) * 16)));
            if (c < 1024) {
                cp16(sA + off, pa + (size_t)(m0 + row) * CDIM + k0 + x16 * 8);
            } else {
                cp16(sB + off, pb + (size_t)(n0 + row) * CDIM + k0 + x16 * 8);
            }
        }
        cp_commit();
    };

    // prologue: 3 stages
    issue(0, 0); issue(1, 1); issue(2, 2);

    for (int kt = 0; kt < NKT; kt++) {
        const int slot = kt & 3;
        cp_wait<PIPE - 2>();
        __syncthreads();

        const uint32_t sA = sbase + slot * STAGE_B;
        const uint32_t sB = sA + TILE_B;

        #pragma unroll
        for (int ks = 0; ks < 4; ks++) {
            // load A fragments (4x m16)
            uint32_t af[4][4];
            #pragma unroll
            for (int mi = 0; mi < 4; mi++) {
                const uint32_t addr = sA + (a_row + mi * 16) * 128
                                    + ((ks * 32 + a_xhalf) ^ a_swz);
                ldsm4(af[mi][0], af[mi][1], af[mi][2], af[mi][3], addr);
            }
            // load B fragments (4x n8) via LDS.32 pairs
            uint32_t bf[4][2];
            #pragma unroll
            for (int nj = 0; nj < 4; nj++) {
                const uint32_t r = sB + (b_row + nj * 8) * 128;
                const uint32_t x0 = (ks * 32 + b_x0) ^ b_swz;
                const uint32_t x1 = (ks * 32 + b_x0 + 16) ^ b_swz;
                asm volatile("ld.shared.b32 %0, [%1];" : "=r"(bf[nj][0]) : "r"(r + x0));
                asm volatile("ld.shared.b32 %0, [%1];" : "=r"(bf[nj][1]) : "r"(r + x1));
            }
            #pragma unroll
            for (int mi = 0; mi < 4; mi++)
                #pragma unroll
                for (int nj = 0; nj < 4; nj++)
                    mma_bf16(acc[mi][nj][0], acc[mi][nj][1], acc[mi][nj][2], acc[mi][nj][3],
                             af[mi][0], af[mi][1], af[mi][2], af[mi][3],
                             bf[nj][0], bf[nj][1]);
        }

        __syncthreads();
        if (kt + 3 < NKT) issue(kt + 3, (kt + 3) & 3);
    }

    // ---- epilogue: direct float2 stores ----
    #pragma unroll
    for (int mi = 0; mi < 4; mi++) {
        const int r0 = m0 + wm + mi * 16 + (lane >> 2);
        #pragma unroll
        for (int nj = 0; nj < 4; nj++) {
            const int c = n0 + wn + nj * 8 + (lane & 3) * 2;
            float b0 = 0.f, b1 = 0.f;
            if (bias) { b0 = bias[c]; b1 = bias[c + 1]; }
            float2 v0 = { acc[mi][nj][0] + b0, acc[mi][nj][1] + b1 };
            float2 v1 = { acc[mi][nj][2] + b0, acc[mi][nj][3] + b1 };
            *reinterpret_cast<float2*>(Cout + (size_t)r0 * Nc + c) = v0;
            *reinterpret_cast<float2*>(Cout + (size_t)(r0 + 8) * Nc + c) = v1;
        }
    }
}

// ============================================================
// fp32 -> (hi,lo) bf16 split, vectorized
// ============================================================
__global__ __launch_bounds__(256) void split_kernel(
    const float* __restrict__ in, __nv_bfloat16* __restrict__ hi,
    __nv_bfloat16* __restrict__ lo, int n4)
{
    const int i = blockIdx.x * 256 + threadIdx.x;
    if (i >= n4) return;
    const float4 v = reinterpret_cast<const float4*>(in)[i];
    __nv_bfloat16 h0 = __float2bfloat16(v.x), h1 = __float2bfloat16(v.y);
    __nv_bfloat16 h2 = __float2bfloat16(v.z), h3 = __float2bfloat16(v.w);
    __nv_bfloat16 l0 = __float2bfloat16(v.x - __bfloat162float(h0));
    __nv_bfloat16 l1 = __float2bfloat16(v.y - __bfloat162float(h1));
    __nv_bfloat16 l2 = __float2bfloat16(v.z - __bfloat162float(h2));
    __nv_bfloat16 l3 = __float2bfloat16(v.w - __bfloat162float(h3));
    __nv_bfloat162 hp0 = {h0, h1}, hp1 = {h2, h3};
    __nv_bfloat162 lp0 = {l0, l1}, lp1 = {l2, l3};
    reinterpret_cast<__nv_bfloat162*>(hi)[i * 2 + 0] = hp0;
    reinterpret_cast<__nv_bfloat162*>(hi)[i * 2 + 1] = hp1;
    reinterpret_cast<__nv_bfloat162*>(lo)[i * 2 + 0] = lp0;
    reinterpret_cast<__nv_bfloat162*>(lo)[i * 2 + 1] = lp1;
}

// ============================================================
// transpose W[K,Nc] -> T[Nc,K] with bf16 hi/lo split
// ============================================================
__global__ __launch_bounds__(256) void tsplit_kernel(
    const float* __restrict__ W, __nv_bfloat16* __restrict__ Th,
    __nv_bfloat16* __restrict__ Tl, int K, int Nc)
{
    __shared__ float t[32][33];
    const int n0 = blockIdx.x * 32, k0 = blockIdx.y * 32;
    const int tx = threadIdx.x & 31, ty = threadIdx.x >> 5;
    #pragma unroll
    for (int i = 0; i < 32; i += 8)
        t[ty + i][tx] = W[(size_t)(k0 + ty + i) * Nc + n0 + tx];
    __syncthreads();
    #pragma unroll
    for (int i = 0; i < 32; i += 8) {
        const float v = t[tx][ty + i];
        const __nv_bfloat16 h = __float2bfloat16(v);
        const __nv_bfloat16 l = __float2bfloat16(v - __bfloat162float(h));
        Th[(size_t)(n0 + ty + i) * K + k0 + tx] = h;
        Tl[(size_t)(n0 + ty + i) * K + k0 + tx] = l;
    }
}

// ============================================================
// Gram partials
// ============================================================
__global__ __launch_bounds__(256) void attn_part_kernel()
{
    const int bh = blockIdx.x;
    const int b  = bh >> 3;
    const int h  = bh & 7;
    const int split = blockIdx.y;

    __shared__ float qs[32][100];
    __shared__ float ks[32][100];

    const int tid = threadIdx.x;
    const int tx = tid & 15;
    const int ty = tid >> 4;

    float acc[6][6];
    #pragma unroll
    for (int i = 0; i < 6; i++)
        #pragma unroll
        for (int j = 0; j < 6; j++) acc[i][j] = 0.f;
    float sq[6] = {0.f,0.f,0.f,0.f,0.f,0.f};
    float sk[6] = {0.f,0.f,0.f,0.f,0.f,0.f};

    const float* qbase = g_q  + (size_t)(b * NTOK) * CDIM     + h * HDd;
    const float* kbase = g_kv + (size_t)(b * NTOK) * 2 * CDIM + h * HDd;

    const int nbeg = split * (NTOK / SPLIT);
    const int nend = nbeg + (NTOK / SPLIT);

    for (int n0 = nbeg; n0 < nend; n0 += 32) {
        __syncthreads();
        #pragma unroll
        for (int it = 0; it < 12; it++) {
            const int i = tid + it * 256;
            const int r = i / 96, c = i % 96;
            qs[r][c] = qbase[(size_t)(n0 + r) * CDIM + c];
            ks[r][c] = kbase[(size_t)(n0 + r) * 2 * CDIM + c];
        }
        __syncthreads();

        #pragma unroll 8
        for (int kk = 0; kk < 32; kk++) {
            float a[6], bb[6];
            #pragma unroll
            for (int i = 0; i < 6; i++) a[i]  = qs[kk][ty * 6 + i];
            #pragma unroll
            for (int j = 0; j < 6; j++) bb[j] = ks[kk][tx * 6 + j];
            #pragma unroll
            for (int i = 0; i < 6; i++)
                #pragma unroll
                for (int j = 0; j < 6; j++)
                    acc[i][j] += a[i] * bb[j];
            if (tx == 0) {
                #pragma unroll
                for (int i = 0; i < 6; i++) sq[i] += a[i] * a[i];
            }
            if (ty == 0) {
                #pragma unroll
                for (int j = 0; j < 6; j++) sk[j] += bb[j] * bb[j];
            }
        }
    }

    const int po = split * BHn + bh;
    float* op = g_part + (size_t)po * (HDd * HDd);
    #pragma unroll
    for (int i = 0; i < 6; i++)
        #pragma unroll
        for (int j = 0; j < 6; j++)
            op[(ty * 6 + i) * HDd + tx * 6 + j] = acc[i][j];
    if (tx == 0) {
        #pragma unroll
        for (int i = 0; i < 6; i++) g_qsq[po * HDd + ty * 6 + i] = sq[i];
    }
    if (ty == 0) {
        #pragma unroll
        for (int j = 0; j < 6; j++) g_ksq[po * HDd + tx * 6 + j] = sk[j];
    }
}

// ============================================================
// softmax: one block per (bh, d-row), 96 threads
// ============================================================
__global__ __launch_bounds__(96) void softmax2_kernel()
{
    const int bh = blockIdx.x;
    const int d  = blockIdx.y;
    const int e  = threadIdx.x;
    const int w  = e >> 5, lane = e & 31;

    __shared__ float s_nq;
    __shared__ float s_m[3], s_s[3];

    float sk = 0.f, sp = 0.f;
    #pragma unroll
    for (int p = 0; p < SPLIT; p++) {
        sk += g_ksq[(p * BHn + bh) * HDd + e];
        sp += g_part[(size_t)(p * BHn + bh) * (HDd * HDd) + d * HDd + e];
    }
    if (e == 0) {
        float sq = 0.f;
        #pragma unroll
        for (int p = 0; p < SPLIT; p++) sq += g_qsq[(p * BHn + bh) * HDd + d];
        s_nq = fmaxf(sqrtf(sq), EPSN);
    }
    __syncthreads();

    const float a = sp * (SCALE_F / s_nq) / fmaxf(sqrtf(sk), EPSN);

    float m = a;
    #pragma unroll
    for (int o = 16; o > 0; o >>= 1) m = fmaxf(m, __shfl_xor_sync(0xffffffffu, m, o));
    if (lane == 0) s_m[w] = m;
    __syncthreads();
    m = fmaxf(fmaxf(s_m[0], s_m[1]), s_m[2]);

    const float ex = __expf(a - m);
    float s = ex;
    #pragma unroll
    for (int o = 16; o > 0; o >>= 1) s += __shfl_xor_sync(0xffffffffu, s, o);
    if (lane == 0) s_s[w] = s;
    __syncthreads();
    s = s_s[0] + s_s[1] + s_s[2];

    g_attn[(size_t)bh * (HDd * HDd) + d * HDd + e] = ex / s;
}

// ============================================================
// x = attn @ v, output split into bf16 hi/lo planes
// ============================================================
__global__ __launch_bounds__(256) void av_kernel()
{
    const int bh = blockIdx.y;
    const int b  = bh >> 3;
    const int h  = bh & 7;
    const int n0 = blockIdx.x * 64;

    __shared__ float vs[64][33];
    __shared__ float at[96][33];

    const int tid = threadIdx.x;
    const int tg = tid >> 4;
    const int dg = tid & 15;
    const int t0 = tg * 4;
    const int d0 = dg * 6;

    float acc[4][6];
    #pragma unroll
    for (int i = 0; i < 4; i++)
        #pragma unroll
        for (int j = 0; j < 6; j++) acc[i][j] = 0.f;

    const float* vbase = g_kv + (size_t)(b * NTOK) * (2 * CDIM) + CDIM + h * HDd;
    const float* abase = g_attn + (size_t)bh * (HDd * HDd);

    for (int e0 = 0; e0 < HDd; e0 += 32) {
        __syncthreads();
        #pragma unroll
        for (int it = 0; it < 8; it++) {
            const int i = tid + it * 256;
            const int r = i >> 5, c = i & 31;
            vs[r][c] = vbase[(size_t)(n0 + r) * (2 * CDIM) + e0 + c];
        }
        #pragma unroll
        for (int it = 0; it < 12; it++) {
            const int i = tid + it * 256;
            const int r = i >> 5, c = i & 31;
            at[r][c] = abase[r * HDd + e0 + c];
        }
        __syncthreads();

        #pragma unroll 8
        for (int e = 0; e < 32; e++) {
            float vv[4], aa[6];
            #pragma unroll
            for (int i = 0; i < 4; i++) vv[i] = vs[t0 + i][e];
            #pragma unroll
            for (int j = 0; j < 6; j++) aa[j] = at[d0 + j][e];
            #pragma unroll
            for (int i = 0; i < 4; i++)
                #pragma unroll
                for (int j = 0; j < 6; j++)
                    acc[i][j] += vv[i] * aa[j];
        }
    }

    const size_t base = (size_t)(b * NTOK) * CDIM + h * HDd;
    #pragma unroll
    for (int i = 0; i < 4; i++)
        #pragma unroll
        for (int j = 0; j < 6; j++) {
            const size_t idx = base + (size_t)(n0 + t0 + i) * CDIM + d0 + j;
            const float v = acc[i][j];
            const __nv_bfloat16 hh = __float2bfloat16(v);
            g_xh[idx] = hh;
            g_xl[idx] = __float2bfloat16(v - __bfloat162float(hh));
        }
}

// ============================================================
extern "C" void kernel_launch(void* const* d_in, const int* in_sizes, int n_in,
                              void* d_out, int out_size)
{
    const float* cx  = (const float*)d_in[0];
    const float* dx  = (const float*)d_in[1];
    const float* Wq  = (const float*)d_in[2];
    const float* Wkv = (const float*)d_in[3];
    const float* Wp  = (const float*)d_in[4];
    const float* bp  = (const float*)d_in[5];
    float* out = (float*)d_out;

    cudaFuncSetAttribute(gemm_mma, cudaFuncAttributeMaxDynamicSharedMemorySize, GSMEM);

    __nv_bfloat16 *a1h, *a1l, *a2h, *a2l, *xh, *xl;
    __nv_bfloat16 *wqh, *wql, *wkh, *wkl, *wph, *wpl;
    float *qp, *kvp;
    cudaGetSymbolAddress((void**)&a1h, g_a1h); cudaGetSymbolAddress((void**)&a1l, g_a1l);
    cudaGetSymbolAddress((void**)&a2h, g_a2h); cudaGetSymbolAddress((void**)&a2l, g_a2l);
    cudaGetSymbolAddress((void**)&xh,  g_xh);  cudaGetSymbolAddress((void**)&xl,  g_xl);
    cudaGetSymbolAddress((void**)&wqh, g_wqh); cudaGetSymbolAddress((void**)&wql, g_wql);
    cudaGetSymbolAddress((void**)&wkh, g_wkh); cudaGetSymbolAddress((void**)&wkl, g_wkl);
    cudaGetSymbolAddress((void**)&wph, g_wph); cudaGetSymbolAddress((void**)&wpl, g_wpl);
    cudaGetSymbolAddress((void**)&qp,  g_q);   cudaGetSymbolAddress((void**)&kvp, g_kv);

    const int n4 = MROWS * CDIM / 4;
    split_kernel<<<(n4 + 255) / 256, 256>>>(cx, a1h, a1l, n4);
    split_kernel<<<(n4 + 255) / 256, 256>>>(dx, a2h, a2l, n4);
    tsplit_kernel<<<dim3(CDIM / 32, CDIM / 32), 256>>>(Wq,  wqh, wql, CDIM, CDIM);
    tsplit_kernel<<<dim3(2 * CDIM / 32, CDIM / 32), 256>>>(Wkv, wkh, wkl, CDIM, 2 * CDIM);
    tsplit_kernel<<<dim3(CDIM / 32, CDIM / 32), 256>>>(Wp,  wph, wpl, CDIM, CDIM);

    // q = cx @ Wq
    gemm_mma<<<dim3(CDIM / 128, MROWS / 128), 256, GSMEM>>>(a1h, a1l, wqh, wql, nullptr, qp, CDIM);
    // kv = dx @ Wkv
    gemm_mma<<<dim3(2 * CDIM / 128, MROWS / 128), 256, GSMEM>>>(a2h, a2l, wkh, wkl, nullptr, kvp, 2 * CDIM);
    // attention core
    attn_part_kernel<<<dim3(BHn, SPLIT), 256>>>();
    softmax2_kernel<<<dim3(BHn, HDd), 96>>>();
    av_kernel<<<dim3(NTOK / 64, BHn), 256>>>();
    // out = x @ Wproj + b
    gemm_mma<<<dim3(CDIM / 128, MROWS / 128), 256, GSMEM>>>(xh, xl, wph, wpl, bp, out, CDIM);
}

// round 4
// speedup vs baseline: 4.2769x; 3.6803x over previous
#include <cuda_runtime.h>
#include <cuda_fp16.h>
#include <cstdint>
#include <cstddef>

// ---------------- problem constants ----------------
#define Bq    4
#define NTOK  4096
#define CDIM  768
#define Hh    8
#define HDd   96
#define MROWS (Bq * NTOK)          // 16384
#define SPLIT 8
#define BHn   (Bq * Hh)            // 32
#define SCALE_F 0.10206207261596577f
#define EPSN 1e-12f

// ---------------- scratch (device globals) ----------------
__device__ __half g_a1f[(size_t)MROWS * CDIM];      // fp16 context_x
__device__ __half g_a2f[(size_t)MROWS * CDIM];      // fp16 depth_x
__device__ __half g_xf [(size_t)MROWS * CDIM];      // fp16 attn output
__device__ __half g_wqf[CDIM * CDIM];               // Wq^T fp16
__device__ __half g_wkf[2 * CDIM * CDIM];           // Wkv^T fp16
__device__ __half g_wpf[CDIM * CDIM];               // Wproj^T fp16
__device__ float g_q [(size_t)MROWS * CDIM];
__device__ float g_kv[(size_t)MROWS * 2 * CDIM];
__device__ float g_attn[BHn * HDd * HDd];
__device__ float g_part[SPLIT * BHn * HDd * HDd];
__device__ float g_qsq [SPLIT * BHn * HDd];
__device__ float g_ksq [SPLIT * BHn * HDd];

// ---------------- helpers ----------------
__device__ __forceinline__ uint32_t s2u(const void* p) {
    uint32_t a;
    asm("{ .reg .u64 t; cvta.to.shared.u64 t, %1; cvt.u32.u64 %0, t; }" : "=r"(a) : "l"(p));
    return a;
}

__device__ __forceinline__ void cp16(uint32_t dst, const void* src) {
    asm volatile("cp.async.cg.shared.global [%0], [%1], 16;" :: "r"(dst), "l"(src));
}
__device__ __forceinline__ void cp_commit() {
    asm volatile("cp.async.commit_group;");
}
template <int N>
__device__ __forceinline__ void cp_wait() {
    asm volatile("cp.async.wait_group %0;" :: "n"(N));
}

__device__ __forceinline__ void ldsm4(uint32_t& r0, uint32_t& r1, uint32_t& r2, uint32_t& r3,
                                      uint32_t addr) {
    asm volatile("ldmatrix.sync.aligned.m8n8.x4.shared.b16 {%0,%1,%2,%3}, [%4];"
                 : "=r"(r0), "=r"(r1), "=r"(r2), "=r"(r3) : "r"(addr));
}

__device__ __forceinline__ void mma_f16(float& c0, float& c1, float& c2, float& c3,
                                        uint32_t a0, uint32_t a1, uint32_t a2, uint32_t a3,
                                        uint32_t b0, uint32_t b1) {
    asm volatile(
        "mma.sync.aligned.m16n8k16.row.col.f32.f16.f16.f32 "
        "{%0,%1,%2,%3}, {%4,%5,%6,%7}, {%8,%9}, {%0,%1,%2,%3};"
        : "+f"(c0), "+f"(c1), "+f"(c2), "+f"(c3)
        : "r"(a0), "r"(a1), "r"(a2), "r"(a3), "r"(b0), "r"(b1));
}

// ============================================================
// fp16 mma.sync GEMM: C[M,Nc] = A[M,768] @ B[Nc,768]^T (+bias)
// CTA 128x128, Ktile=64 (128B SW128 rows), 4-stage cp.async pipe
// ============================================================
#define PIPE      4
#define TILE_B    16384                // one operand tile: 128 rows x 128B
#define STAGE_B   (2 * TILE_B)
#define GSMEM     (PIPE * STAGE_B)     // 131072
#define NKT       12                   // 768 / 64

__global__ __launch_bounds__(256, 1) void gemm_mma(
    const __half* __restrict__ A, const __half* __restrict__ B,
    const float* __restrict__ bias, float* __restrict__ Cout, int Nc)
{
    extern __shared__ __align__(1024) char smem[];
    const uint32_t sbase = s2u(smem);

    const int tid  = threadIdx.x;
    const int lane = tid & 31;
    const int wid  = tid >> 5;
    const int m0 = blockIdx.y * 128;
    const int n0 = blockIdx.x * 128;
    const int wm = (wid >> 2) * 64;    // warp m offset
    const int wn = (wid & 3) * 32;     // warp n offset

    // A ldmatrix per-lane constants: rows wm..wm+15, k halves by lane>>4
    const uint32_t a_row   = wm + (lane & 15);
    const uint32_t a_swz   = (lane & 7) * 16;
    const uint32_t a_xhalf = (lane >> 4) * 16;
    // B ldmatrix per-lane constants: g = lane>>3 selects (n_sub, k_half)
    const int l8 = lane & 7;
    const int lg = lane >> 3;
    const uint32_t b_row_base = wn + (lg >> 1) * 8 + l8;  // + p*16 per call
    const uint32_t b_khalf    = (lg & 1) * 16;
    const uint32_t b_swz      = l8 * 16;

    float acc[4][4][4];
    #pragma unroll
    for (int i = 0; i < 4; i++)
        #pragma unroll
        for (int j = 0; j < 4; j++)
            #pragma unroll
            for (int c = 0; c < 4; c++) acc[i][j][c] = 0.f;

    auto issue = [&](int kt, int slot) {
        const int k0 = kt * 64;
        const uint32_t sA = sbase + slot * STAGE_B;
        const uint32_t sB = sA + TILE_B;
        #pragma unroll
        for (int i = 0; i < 8; i++) {
            const int c = tid + i * 256;           // 0..2047
            const int row = (c >> 3) & 127;
            const int x16 = c & 7;
            const uint32_t off = (uint32_t)(row * 128 + ((x16 * 16) ^ ((row & 7) * 16)));
            if (c < 1024) {
                cp16(sA + off, A + (size_t)(m0 + row) * CDIM + k0 + x16 * 8);
            } else {
                cp16(sB + off, B + (size_t)(n0 + row) * CDIM + k0 + x16 * 8);
            }
        }
        cp_commit();
    };

    issue(0, 0); issue(1, 1); issue(2, 2);

    for (int kt = 0; kt < NKT; kt++) {
        const int slot = kt & 3;
        cp_wait<PIPE - 2>();
        __syncthreads();

        const uint32_t sA = sbase + slot * STAGE_B;
        const uint32_t sB = sA + TILE_B;

        #pragma unroll
        for (int ks = 0; ks < 4; ks++) {
            uint32_t af[4][4];
            #pragma unroll
            for (int mi = 0; mi < 4; mi++) {
                const uint32_t addr = sA + (a_row + mi * 16) * 128
                                    + ((ks * 32 + a_xhalf) ^ a_swz);
                ldsm4(af[mi][0], af[mi][1], af[mi][2], af[mi][3], addr);
            }
            uint32_t bf[4][2];
            #pragma unroll
            for (int p = 0; p < 2; p++) {
                const uint32_t addr = sB + (b_row_base + p * 16) * 128
                                    + ((ks * 32 + b_khalf) ^ b_swz);
                ldsm4(bf[2*p][0], bf[2*p][1], bf[2*p+1][0], bf[2*p+1][1], addr);
            }
            #pragma unroll
            for (int mi = 0; mi < 4; mi++)
                #pragma unroll
                for (int nj = 0; nj < 4; nj++)
                    mma_f16(acc[mi][nj][0], acc[mi][nj][1], acc[mi][nj][2], acc[mi][nj][3],
                            af[mi][0], af[mi][1], af[mi][2], af[mi][3],
                            bf[nj][0], bf[nj][1]);
        }

        __syncthreads();
        if (kt + 3 < NKT) issue(kt + 3, (kt + 3) & 3);
    }

    // ---- epilogue ----
    #pragma unroll
    for (int mi = 0; mi < 4; mi++) {
        const int r0 = m0 + wm + mi * 16 + (lane >> 2);
        #pragma unroll
        for (int nj = 0; nj < 4; nj++) {
            const int c = n0 + wn + nj * 8 + (lane & 3) * 2;
            float b0 = 0.f, b1 = 0.f;
            if (bias) { b0 = bias[c]; b1 = bias[c + 1]; }
            float2 v0 = { acc[mi][nj][0] + b0, acc[mi][nj][1] + b1 };
            float2 v1 = { acc[mi][nj][2] + b0, acc[mi][nj][3] + b1 };
            *reinterpret_cast<float2*>(Cout + (size_t)r0 * Nc + c) = v0;
            *reinterpret_cast<float2*>(Cout + (size_t)(r0 + 8) * Nc + c) = v1;
        }
    }
}

// ============================================================
// fp32 -> fp16 convert, vectorized
// ============================================================
__global__ __launch_bounds__(256) void tofp16_kernel(
    const float* __restrict__ in, __half* __restrict__ out, int n4)
{
    const int i = blockIdx.x * 256 + threadIdx.x;
    if (i >= n4) return;
    const float4 v = reinterpret_cast<const float4*>(in)[i];
    __half2 h0 = { __float2half_rn(v.x), __float2half_rn(v.y) };
    __half2 h1 = { __float2half_rn(v.z), __float2half_rn(v.w) };
    reinterpret_cast<__half2*>(out)[i * 2 + 0] = h0;
    reinterpret_cast<__half2*>(out)[i * 2 + 1] = h1;
}

// ============================================================
// transpose W[K,Nc] -> T[Nc,K] fp16
// ============================================================
__global__ __launch_bounds__(256) void tfp16_kernel(
    const float* __restrict__ W, __half* __restrict__ T, int K, int Nc)
{
    __shared__ float t[32][33];
    const int n0 = blockIdx.x * 32, k0 = blockIdx.y * 32;
    const int tx = threadIdx.x & 31, ty = threadIdx.x >> 5;
    #pragma unroll
    for (int i = 0; i < 32; i += 8)
        t[ty + i][tx] = W[(size_t)(k0 + ty + i) * Nc + n0 + tx];
    __syncthreads();
    #pragma unroll
    for (int i = 0; i < 32; i += 8)
        T[(size_t)(n0 + ty + i) * K + k0 + tx] = __float2half_rn(t[tx][ty + i]);
}

// ============================================================
// Gram partials
// ============================================================
__global__ __launch_bounds__(256) void attn_part_kernel()
{
    const int bh = blockIdx.x;
    const int b  = bh >> 3;
    const int h  = bh & 7;
    const int split = blockIdx.y;

    __shared__ float qs[32][100];
    __shared__ float ks[32][100];

    const int tid = threadIdx.x;
    const int tx = tid & 15;
    const int ty = tid >> 4;

    float acc[6][6];
    #pragma unroll
    for (int i = 0; i < 6; i++)
        #pragma unroll
        for (int j = 0; j < 6; j++) acc[i][j] = 0.f;
    float sq[6] = {0.f,0.f,0.f,0.f,0.f,0.f};
    float sk[6] = {0.f,0.f,0.f,0.f,0.f,0.f};

    const float* qbase = g_q  + (size_t)(b * NTOK) * CDIM     + h * HDd;
    const float* kbase = g_kv + (size_t)(b * NTOK) * 2 * CDIM + h * HDd;

    const int nbeg = split * (NTOK / SPLIT);
    const int nend = nbeg + (NTOK / SPLIT);

    for (int n0 = nbeg; n0 < nend; n0 += 32) {
        __syncthreads();
        #pragma unroll
        for (int it = 0; it < 12; it++) {
            const int i = tid + it * 256;
            const int r = i / 96, c = i % 96;
            qs[r][c] = qbase[(size_t)(n0 + r) * CDIM + c];
            ks[r][c] = kbase[(size_t)(n0 + r) * 2 * CDIM + c];
        }
        __syncthreads();

        #pragma unroll 8
        for (int kk = 0; kk < 32; kk++) {
            float a[6], bb[6];
            #pragma unroll
            for (int i = 0; i < 6; i++) a[i]  = qs[kk][ty * 6 + i];
            #pragma unroll
            for (int j = 0; j < 6; j++) bb[j] = ks[kk][tx * 6 + j];
            #pragma unroll
            for (int i = 0; i < 6; i++)
                #pragma unroll
                for (int j = 0; j < 6; j++)
                    acc[i][j] += a[i] * bb[j];
            if (tx == 0) {
                #pragma unroll
                for (int i = 0; i < 6; i++) sq[i] += a[i] * a[i];
            }
            if (ty == 0) {
                #pragma unroll
                for (int j = 0; j < 6; j++) sk[j] += bb[j] * bb[j];
            }
        }
    }

    const int po = split * BHn + bh;
    float* op = g_part + (size_t)po * (HDd * HDd);
    #pragma unroll
    for (int i = 0; i < 6; i++)
        #pragma unroll
        for (int j = 0; j < 6; j++)
            op[(ty * 6 + i) * HDd + tx * 6 + j] = acc[i][j];
    if (tx == 0) {
        #pragma unroll
        for (int i = 0; i < 6; i++) g_qsq[po * HDd + ty * 6 + i] = sq[i];
    }
    if (ty == 0) {
        #pragma unroll
        for (int j = 0; j < 6; j++) g_ksq[po * HDd + tx * 6 + j] = sk[j];
    }
}

// ============================================================
// softmax: one block per (bh, d-row), 96 threads
// ============================================================
__global__ __launch_bounds__(96) void softmax2_kernel()
{
    const int bh = blockIdx.x;
    const int d  = blockIdx.y;
    const int e  = threadIdx.x;
    const int w  = e >> 5, lane = e & 31;

    __shared__ float s_nq;
    __shared__ float s_m[3], s_s[3];

    float sk = 0.f, sp = 0.f;
    #pragma unroll
    for (int p = 0; p < SPLIT; p++) {
        sk += g_ksq[(p * BHn + bh) * HDd + e];
        sp += g_part[(size_t)(p * BHn + bh) * (HDd * HDd) + d * HDd + e];
    }
    if (e == 0) {
        float sq = 0.f;
        #pragma unroll
        for (int p = 0; p < SPLIT; p++) sq += g_qsq[(p * BHn + bh) * HDd + d];
        s_nq = fmaxf(sqrtf(sq), EPSN);
    }
    __syncthreads();

    const float a = sp * (SCALE_F / s_nq) / fmaxf(sqrtf(sk), EPSN);

    float m = a;
    #pragma unroll
    for (int o = 16; o > 0; o >>= 1) m = fmaxf(m, __shfl_xor_sync(0xffffffffu, m, o));
    if (lane == 0) s_m[w] = m;
    __syncthreads();
    m = fmaxf(fmaxf(s_m[0], s_m[1]), s_m[2]);

    const float ex = __expf(a - m);
    float s = ex;
    #pragma unroll
    for (int o = 16; o > 0; o >>= 1) s += __shfl_xor_sync(0xffffffffu, s, o);
    if (lane == 0) s_s[w] = s;
    __syncthreads();
    s = s_s[0] + s_s[1] + s_s[2];

    g_attn[(size_t)bh * (HDd * HDd) + d * HDd + e] = ex / s;
}

// ============================================================
// x = attn @ v, fp16 output for the final GEMM
// ============================================================
__global__ __launch_bounds__(256) void av_kernel()
{
    const int bh = blockIdx.y;
    const int b  = bh >> 3;
    const int h  = bh & 7;
    const int n0 = blockIdx.x * 64;

    __shared__ float vs[64][33];
    __shared__ float at[96][33];

    const int tid = threadIdx.x;
    const int tg = tid >> 4;
    const int dg = tid & 15;
    const int t0 = tg * 4;
    const int d0 = dg * 6;

    float acc[4][6];
    #pragma unroll
    for (int i = 0; i < 4; i++)
        #pragma unroll
        for (int j = 0; j < 6; j++) acc[i][j] = 0.f;

    const float* vbase = g_kv + (size_t)(b * NTOK) * (2 * CDIM) + CDIM + h * HDd;
    const float* abase = g_attn + (size_t)bh * (HDd * HDd);

    for (int e0 = 0; e0 < HDd; e0 += 32) {
        __syncthreads();
        #pragma unroll
        for (int it = 0; it < 8; it++) {
            const int i = tid + it * 256;
            const int r = i >> 5, c = i & 31;
            vs[r][c] = vbase[(size_t)(n0 + r) * (2 * CDIM) + e0 + c];
        }
        #pragma unroll
        for (int it = 0; it < 12; it++) {
            const int i = tid + it * 256;
            const int r = i >> 5, c = i & 31;
            at[r][c] = abase[r * HDd + e0 + c];
        }
        __syncthreads();

        #pragma unroll 8
        for (int e = 0; e < 32; e++) {
            float vv[4], aa[6];
            #pragma unroll
            for (int i = 0; i < 4; i++) vv[i] = vs[t0 + i][e];
            #pragma unroll
            for (int j = 0; j < 6; j++) aa[j] = at[d0 + j][e];
            #pragma unroll
            for (int i = 0; i < 4; i++)
                #pragma unroll
                for (int j = 0; j < 6; j++)
                    acc[i][j] += vv[i] * aa[j];
        }
    }

    const size_t base = (size_t)(b * NTOK) * CDIM + h * HDd;
    #pragma unroll
    for (int i = 0; i < 4; i++)
        #pragma unroll
        for (int j = 0; j < 6; j++)
            g_xf[base + (size_t)(n0 + t0 + i) * CDIM + d0 + j] =
                __float2half_rn(acc[i][j]);
}

// ============================================================
extern "C" void kernel_launch(void* const* d_in, const int* in_sizes, int n_in,
                              void* d_out, int out_size)
{
    const float* cx  = (const float*)d_in[0];
    const float* dx  = (const float*)d_in[1];
    const float* Wq  = (const float*)d_in[2];
    const float* Wkv = (const float*)d_in[3];
    const float* Wp  = (const float*)d_in[4];
    const float* bp  = (const float*)d_in[5];
    float* out = (float*)d_out;

    cudaFuncSetAttribute(gemm_mma, cudaFuncAttributeMaxDynamicSharedMemorySize, GSMEM);

    __half *a1f, *a2f, *xf, *wqf, *wkf, *wpf;
    float *qp, *kvp;
    cudaGetSymbolAddress((void**)&a1f, g_a1f);
    cudaGetSymbolAddress((void**)&a2f, g_a2f);
    cudaGetSymbolAddress((void**)&xf,  g_xf);
    cudaGetSymbolAddress((void**)&wqf, g_wqf);
    cudaGetSymbolAddress((void**)&wkf, g_wkf);
    cudaGetSymbolAddress((void**)&wpf, g_wpf);
    cudaGetSymbolAddress((void**)&qp,  g_q);
    cudaGetSymbolAddress((void**)&kvp, g_kv);

    const int n4 = MROWS * CDIM / 4;
    tofp16_kernel<<<(n4 + 255) / 256, 256>>>(cx, a1f, n4);
    tofp16_kernel<<<(n4 + 255) / 256, 256>>>(dx, a2f, n4);
    tfp16_kernel<<<dim3(CDIM / 32, CDIM / 32), 256>>>(Wq,  wqf, CDIM, CDIM);
    tfp16_kernel<<<dim3(2 * CDIM / 32, CDIM / 32), 256>>>(Wkv, wkf, CDIM, 2 * CDIM);
    tfp16_kernel<<<dim3(CDIM / 32, CDIM / 32), 256>>>(Wp,  wpf, CDIM, CDIM);

    // q = cx @ Wq
    gemm_mma<<<dim3(CDIM / 128, MROWS / 128), 256, GSMEM>>>(a1f, wqf, nullptr, qp, CDIM);
    // kv = dx @ Wkv
    gemm_mma<<<dim3(2 * CDIM / 128, MROWS / 128), 256, GSMEM>>>(a2f, wkf, nullptr, kvp, 2 * CDIM);
    // attention core
    attn_part_kernel<<<dim3(BHn, SPLIT), 256>>>();
    softmax2_kernel<<<dim3(BHn, HDd), 96>>>();
    av_kernel<<<dim3(NTOK / 64, BHn), 256>>>();
    // out = x @ Wproj + b
    gemm_mma<<<dim3(CDIM / 128, MROWS / 128), 256, GSMEM>>>(xf, wpf, bp, out, CDIM);
}

// round 5
// speedup vs baseline: 4.9631x; 1.1605x over previous
#include <cuda_runtime.h>
#include <cuda_fp16.h>
#include <cstdint>
#include <cstddef>

// ---------------- problem constants ----------------
#define Bq    4
#define NTOK  4096
#define CDIM  768
#define Hh    8
#define HDd   96
#define MROWS (Bq * NTOK)          // 16384
#define SPLIT 8
#define BHn   (Bq * Hh)            // 32
#define SCALE_F 0.10206207261596577f
#define EPSN 1e-12f

// ---------------- scratch (device globals) ----------------
__device__ __half g_a1f[(size_t)MROWS * CDIM];       // fp16 context_x
__device__ __half g_a2f[(size_t)MROWS * CDIM];       // fp16 depth_x
__device__ __half g_qh [(size_t)MROWS * CDIM];       // fp16 q
__device__ __half g_kvh[(size_t)MROWS * 2 * CDIM];   // fp16 kv
__device__ __half g_xf [(size_t)MROWS * CDIM];       // fp16 attn output
__device__ __half g_wqf[CDIM * CDIM];
__device__ __half g_wkf[2 * CDIM * CDIM];
__device__ __half g_wpf[CDIM * CDIM];
__device__ __half g_attnh[BHn * HDd * HDd];          // fp16 softmaxed attn
__device__ float g_part[SPLIT * BHn * HDd * HDd];
__device__ float g_qsq [SPLIT * BHn * HDd];
__device__ float g_ksq [SPLIT * BHn * HDd];

// ---------------- helpers ----------------
__device__ __forceinline__ uint32_t s2u(const void* p) {
    uint32_t a;
    asm("{ .reg .u64 t; cvta.to.shared.u64 t, %1; cvt.u32.u64 %0, t; }" : "=r"(a) : "l"(p));
    return a;
}
__device__ __forceinline__ void cp16(uint32_t dst, const void* src) {
    asm volatile("cp.async.cg.shared.global [%0], [%1], 16;" :: "r"(dst), "l"(src));
}
__device__ __forceinline__ void cp_commit() { asm volatile("cp.async.commit_group;"); }
template <int N>
__device__ __forceinline__ void cp_wait() { asm volatile("cp.async.wait_group %0;" :: "n"(N)); }

__device__ __forceinline__ void ldsm4(uint32_t& r0, uint32_t& r1, uint32_t& r2, uint32_t& r3,
                                      uint32_t addr) {
    asm volatile("ldmatrix.sync.aligned.m8n8.x4.shared.b16 {%0,%1,%2,%3}, [%4];"
                 : "=r"(r0), "=r"(r1), "=r"(r2), "=r"(r3) : "r"(addr));
}
__device__ __forceinline__ void ldsm4t(uint32_t& r0, uint32_t& r1, uint32_t& r2, uint32_t& r3,
                                       uint32_t addr) {
    asm volatile("ldmatrix.sync.aligned.m8n8.x4.trans.shared.b16 {%0,%1,%2,%3}, [%4];"
                 : "=r"(r0), "=r"(r1), "=r"(r2), "=r"(r3) : "r"(addr));
}
__device__ __forceinline__ void mma_f16(float& c0, float& c1, float& c2, float& c3,
                                        uint32_t a0, uint32_t a1, uint32_t a2, uint32_t a3,
                                        uint32_t b0, uint32_t b1) {
    asm volatile(
        "mma.sync.aligned.m16n8k16.row.col.f32.f16.f16.f32 "
        "{%0,%1,%2,%3}, {%4,%5,%6,%7}, {%8,%9}, {%0,%1,%2,%3};"
        : "+f"(c0), "+f"(c1), "+f"(c2), "+f"(c3)
        : "r"(a0), "r"(a1), "r"(a2), "r"(a3), "r"(b0), "r"(b1));
}

// ============================================================
// fp16 mma.sync GEMM: C[M,Nc] = A[M,768] @ B[Nc,768]^T (+bias)
// CTA 128x128, Ktile=64, 4-stage cp.async, single sync/ktile
// ============================================================
#define PIPE      4
#define TILE_B    16384
#define STAGE_B   (2 * TILE_B)
#define GSMEM     (PIPE * STAGE_B)     // 131072
#define NKT       12

template <bool HALF_OUT>
__global__ __launch_bounds__(256, 1) void gemm_mma(
    const __half* __restrict__ A, const __half* __restrict__ B,
    const float* __restrict__ bias, void* __restrict__ outv, int Nc)
{
    extern __shared__ __align__(1024) char smem[];
    const uint32_t sbase = s2u(smem);

    const int tid  = threadIdx.x;
    const int lane = tid & 31;
    const int wid  = tid >> 5;
    const int m0 = blockIdx.y * 128;
    const int n0 = blockIdx.x * 128;
    const int wm = (wid >> 2) * 64;
    const int wn = (wid & 3) * 32;

    const uint32_t a_row   = wm + (lane & 15);
    const uint32_t a_swz   = (lane & 7) * 16;
    const uint32_t a_xhalf = (lane >> 4) * 16;
    const int l8 = lane & 7;
    const int lg = lane >> 3;
    const uint32_t b_row_base = wn + (lg >> 1) * 8 + l8;
    const uint32_t b_khalf    = (lg & 1) * 16;
    const uint32_t b_swz      = l8 * 16;

    float acc[4][4][4];
    #pragma unroll
    for (int i = 0; i < 4; i++)
        #pragma unroll
        for (int j = 0; j < 4; j++)
            #pragma unroll
            for (int c = 0; c < 4; c++) acc[i][j][c] = 0.f;

    auto issue = [&](int kt, int slot) {
        const int k0 = kt * 64;
        const uint32_t sA = sbase + slot * STAGE_B;
        const uint32_t sB = sA + TILE_B;
        #pragma unroll
        for (int i = 0; i < 8; i++) {
            const int c = tid + i * 256;
            const int row = (c >> 3) & 127;
            const int x16 = c & 7;
            const uint32_t off = (uint32_t)(row * 128 + ((x16 * 16) ^ ((row & 7) * 16)));
            if (c < 1024) cp16(sA + off, A + (size_t)(m0 + row) * CDIM + k0 + x16 * 8);
            else          cp16(sB + off, B + (size_t)(n0 + row) * CDIM + k0 + x16 * 8);
        }
        cp_commit();
    };

    issue(0, 0); issue(1, 1); issue(2, 2);

    for (int kt = 0; kt < NKT; kt++) {
        const int slot = kt & 3;
        cp_wait<PIPE - 2>();
        __syncthreads();
        if (kt + 3 < NKT) issue(kt + 3, (kt + 3) & 3);

        const uint32_t sA = sbase + slot * STAGE_B;
        const uint32_t sB = sA + TILE_B;

        #pragma unroll
        for (int ks = 0; ks < 4; ks++) {
            uint32_t af[4][4];
            #pragma unroll
            for (int mi = 0; mi < 4; mi++) {
                const uint32_t addr = sA + (a_row + mi * 16) * 128
                                    + ((ks * 32 + a_xhalf) ^ a_swz);
                ldsm4(af[mi][0], af[mi][1], af[mi][2], af[mi][3], addr);
            }
            uint32_t bf[4][2];
            #pragma unroll
            for (int p = 0; p < 2; p++) {
                const uint32_t addr = sB + (b_row_base + p * 16) * 128
                                    + ((ks * 32 + b_khalf) ^ b_swz);
                ldsm4(bf[2*p][0], bf[2*p][1], bf[2*p+1][0], bf[2*p+1][1], addr);
            }
            #pragma unroll
            for (int mi = 0; mi < 4; mi++)
                #pragma unroll
                for (int nj = 0; nj < 4; nj++)
                    mma_f16(acc[mi][nj][0], acc[mi][nj][1], acc[mi][nj][2], acc[mi][nj][3],
                            af[mi][0], af[mi][1], af[mi][2], af[mi][3],
                            bf[nj][0], bf[nj][1]);
        }
    }

    #pragma unroll
    for (int mi = 0; mi < 4; mi++) {
        const int r0 = m0 + wm + mi * 16 + (lane >> 2);
        #pragma unroll
        for (int nj = 0; nj < 4; nj++) {
            const int c = n0 + wn + nj * 8 + (lane & 3) * 2;
            float b0 = 0.f, b1 = 0.f;
            if (bias) { b0 = bias[c]; b1 = bias[c + 1]; }
            if (HALF_OUT) {
                __half* H = (__half*)outv;
                __half2 v0 = { __float2half_rn(acc[mi][nj][0] + b0),
                               __float2half_rn(acc[mi][nj][1] + b1) };
                __half2 v1 = { __float2half_rn(acc[mi][nj][2] + b0),
                               __float2half_rn(acc[mi][nj][3] + b1) };
                *reinterpret_cast<__half2*>(H + (size_t)r0 * Nc + c) = v0;
                *reinterpret_cast<__half2*>(H + (size_t)(r0 + 8) * Nc + c) = v1;
            } else {
                float* F = (float*)outv;
                float2 v0 = { acc[mi][nj][0] + b0, acc[mi][nj][1] + b1 };
                float2 v1 = { acc[mi][nj][2] + b0, acc[mi][nj][3] + b1 };
                *reinterpret_cast<float2*>(F + (size_t)r0 * Nc + c) = v0;
                *reinterpret_cast<float2*>(F + (size_t)(r0 + 8) * Nc + c) = v1;
            }
        }
    }
}

// ============================================================
// fp32 -> fp16 convert
// ============================================================
__global__ __launch_bounds__(256) void tofp16_kernel(
    const float* __restrict__ in, __half* __restrict__ out, int n4)
{
    const int i = blockIdx.x * 256 + threadIdx.x;
    if (i >= n4) return;
    const float4 v = reinterpret_cast<const float4*>(in)[i];
    __half2 h0 = { __float2half_rn(v.x), __float2half_rn(v.y) };
    __half2 h1 = { __float2half_rn(v.z), __float2half_rn(v.w) };
    reinterpret_cast<__half2*>(out)[i * 2 + 0] = h0;
    reinterpret_cast<__half2*>(out)[i * 2 + 1] = h1;
}

// ============================================================
// transpose W[K,Nc] -> T[Nc,K] fp16
// ============================================================
__global__ __launch_bounds__(256) void tfp16_kernel(
    const float* __restrict__ W, __half* __restrict__ T, int K, int Nc)
{
    __shared__ float t[32][33];
    const int n0 = blockIdx.x * 32, k0 = blockIdx.y * 32;
    const int tx = threadIdx.x & 31, ty = threadIdx.x >> 5;
    #pragma unroll
    for (int i = 0; i < 32; i += 8)
        t[ty + i][tx] = W[(size_t)(k0 + ty + i) * Nc + n0 + tx];
    __syncthreads();
    #pragma unroll
    for (int i = 0; i < 32; i += 8)
        T[(size_t)(n0 + ty + i) * K + k0 + tx] = __float2half_rn(t[tx][ty + i]);
}

// ============================================================
// Column sum-of-squares partials over token splits
// grid (3, B, SPLIT), 256 thr: c = bx*256+tid, 512 tokens
// ============================================================
__global__ __launch_bounds__(256) void sumsq_kernel()
{
    const int c = blockIdx.x * 256 + threadIdx.x;
    const int b = blockIdx.y;
    const int sp = blockIdx.z;
    const int n0 = sp * (NTOK / SPLIT);

    const __half* qp = g_qh  + (size_t)(b * NTOK + n0) * CDIM + c;
    const __half* kp = g_kvh + (size_t)(b * NTOK + n0) * (2 * CDIM) + c;
    float sq = 0.f, sk = 0.f;
    #pragma unroll 4
    for (int n = 0; n < NTOK / SPLIT; n++) {
        const float qv = __half2float(qp[(size_t)n * CDIM]);
        const float kv = __half2float(kp[(size_t)n * 2 * CDIM]);
        sq += qv * qv;
        sk += kv * kv;
    }
    const int bh = b * Hh + c / HDd;
    const int d  = c % HDd;
    const int po = sp * BHn + bh;
    g_qsq[po * HDd + d] = sq;
    g_ksq[po * HDd + d] = sk;
}

// ============================================================
// Tensor-core Gram partials: part[d,e] = sum_n q[n,d] k[n,e]
// grid (BHn, SPLIT); 192 thr (6 warps, 16 e each); 3-stage cp.async
// ============================================================
#define GPITCH 104
#define GNI    32          // 512 tokens / 16

__global__ __launch_bounds__(192) void gram_tc()
{
    __shared__ __half qs[3][16][GPITCH];
    __shared__ __half ks[3][16][GPITCH];

    const int bh = blockIdx.x;
    const int b  = bh >> 3;
    const int h  = bh & 7;
    const int sp = blockIdx.y;
    const int nbase = b * NTOK + sp * (NTOK / SPLIT);

    const int tid  = threadIdx.x;
    const int lane = tid & 31;
    const int w    = tid >> 5;
    const int e0   = w * 16;

    const __half* qbase = g_qh  + (size_t)nbase * CDIM + h * HDd;
    const __half* kbase = g_kvh + (size_t)nbase * (2 * CDIM) + h * HDd;

    // per-thread load assignment: chunk tid of 192 = row*12 + x
    const int lrow = tid / 12;
    const int lx   = tid % 12;

    auto issue = [&](int it, int s) {
        const int n0 = it * 16;
        cp16(s2u(&qs[s][lrow][lx * 8]),
             qbase + (size_t)(n0 + lrow) * CDIM + lx * 8);
        cp16(s2u(&ks[s][lrow][lx * 8]),
             kbase + (size_t)(n0 + lrow) * (2 * CDIM) + lx * 8);
        cp_commit();
    };

    // fragment address constants
    const uint32_t a_row = (lane & 7) + ((lane >> 4) & 1) * 8;   // token row
    const uint32_t a_coff = ((lane >> 3) & 1) * 8;               // d offset
    const uint32_t b_row = (lane & 7) + ((lane >> 3) & 1) * 8;
    const uint32_t b_coff = ((lane >> 4) & 1) * 8;

    float acc[6][2][4];
    #pragma unroll
    for (int i = 0; i < 6; i++)
        #pragma unroll
        for (int j = 0; j < 2; j++)
            #pragma unroll
            for (int c = 0; c < 4; c++) acc[i][j][c] = 0.f;

    issue(0, 0); issue(1, 1);

    for (int it = 0; it < GNI; it++) {
        const int s = it % 3;
        if (it + 1 < GNI) cp_wait<1>(); else cp_wait<0>();
        __syncthreads();
        if (it + 2 < GNI) issue(it + 2, (it + 2) % 3);

        uint32_t bf[4];
        ldsm4t(bf[0], bf[1], bf[2], bf[3], s2u(&ks[s][b_row][e0 + b_coff]));
        uint32_t af[6][4];
        #pragma unroll
        for (int mi = 0; mi < 6; mi++)
            ldsm4t(af[mi][0], af[mi][1], af[mi][2], af[mi][3],
                   s2u(&qs[s][a_row][mi * 16 + a_coff]));
        #pragma unroll
        for (int mi = 0; mi < 6; mi++)
            #pragma unroll
            for (int nj = 0; nj < 2; nj++)
                mma_f16(acc[mi][nj][0], acc[mi][nj][1], acc[mi][nj][2], acc[mi][nj][3],
                        af[mi][0], af[mi][1], af[mi][2], af[mi][3],
                        bf[nj * 2], bf[nj * 2 + 1]);
    }

    float* op = g_part + (size_t)(sp * BHn + bh) * (HDd * HDd);
    #pragma unroll
    for (int mi = 0; mi < 6; mi++) {
        const int d = mi * 16 + (lane >> 2);
        #pragma unroll
        for (int nj = 0; nj < 2; nj++) {
            const int e = e0 + nj * 8 + (lane & 3) * 2;
            float2 v0 = { acc[mi][nj][0], acc[mi][nj][1] };
            float2 v1 = { acc[mi][nj][2], acc[mi][nj][3] };
            *reinterpret_cast<float2*>(op + d * HDd + e) = v0;
            *reinterpret_cast<float2*>(op + (d + 8) * HDd + e) = v1;
        }
    }
}

// ============================================================
// softmax -> fp16 attn
// ============================================================
__global__ __launch_bounds__(96) void softmax2_kernel()
{
    const int bh = blockIdx.x;
    const int d  = blockIdx.y;
    const int e  = threadIdx.x;
    const int w  = e >> 5, lane = e & 31;

    __shared__ float s_nq;
    __shared__ float s_m[3], s_s[3];

    float sk = 0.f, sp = 0.f;
    #pragma unroll
    for (int p = 0; p < SPLIT; p++) {
        sk += g_ksq[(p * BHn + bh) * HDd + e];
        sp += g_part[(size_t)(p * BHn + bh) * (HDd * HDd) + d * HDd + e];
    }
    if (e == 0) {
        float sq = 0.f;
        #pragma unroll
        for (int p = 0; p < SPLIT; p++) sq += g_qsq[(p * BHn + bh) * HDd + d];
        s_nq = fmaxf(sqrtf(sq), EPSN);
    }
    __syncthreads();

    const float a = sp * (SCALE_F / s_nq) / fmaxf(sqrtf(sk), EPSN);

    float m = a;
    #pragma unroll
    for (int o = 16; o > 0; o >>= 1) m = fmaxf(m, __shfl_xor_sync(0xffffffffu, m, o));
    if (lane == 0) s_m[w] = m;
    __syncthreads();
    m = fmaxf(fmaxf(s_m[0], s_m[1]), s_m[2]);

    const float ex = __expf(a - m);
    float s = ex;
    #pragma unroll
    for (int o = 16; o > 0; o >>= 1) s += __shfl_xor_sync(0xffffffffu, s, o);
    if (lane == 0) s_s[w] = s;
    __syncthreads();
    s = s_s[0] + s_s[1] + s_s[2];

    g_attnh[(size_t)bh * (HDd * HDd) + d * HDd + e] = __float2half_rn(ex / s);
}

// ============================================================
// Tensor-core AV: x[n,d] = sum_e attn[d,e] v[n,e]
// grid (128 token-tiles, 8 h); 128 thr (4 warps x 32 tokens)
// ============================================================
#define APITCH 104

__global__ __launch_bounds__(128) void av_tc()
{
    __shared__ __half vs_[128][APITCH];
    __shared__ __half as_[96][APITCH];

    const int tile = blockIdx.x;
    const int h    = blockIdx.y;
    const int b    = tile >> 5;
    const int bh   = b * Hh + h;
    const int row0 = tile * 128;       // global token row

    const int tid  = threadIdx.x;
    const int lane = tid & 31;
    const int w    = tid >> 5;

    // loads: V 1536 chunks (12/thread), attn 1152 chunks (9/thread)
    const __half* vsrc = g_kvh + (size_t)row0 * (2 * CDIM) + CDIM + h * HDd;
    const __half* asrc = g_attnh + (size_t)bh * (HDd * HDd);
    #pragma unroll
    for (int i = 0; i < 12; i++) {
        const int c = tid + i * 128;
        const int r = c / 12, x = c % 12;
        cp16(s2u(&vs_[r][x * 8]), vsrc + (size_t)r * (2 * CDIM) + x * 8);
    }
    #pragma unroll
    for (int i = 0; i < 9; i++) {
        const int c = tid + i * 128;
        const int r = c / 12, x = c % 12;
        cp16(s2u(&as_[r][x * 8]), asrc + r * HDd + x * 8);
    }
    cp_commit();
    cp_wait<0>();
    __syncthreads();

    const uint32_t v_row = w * 32 + (lane & 15);
    const uint32_t v_coff = (lane >> 4) * 8;
    const uint32_t b_row = (lane & 7) + ((lane >> 4) & 1) * 8;
    const uint32_t b_coff = ((lane >> 3) & 1) * 8;

    float acc[2][12][4];
    #pragma unroll
    for (int i = 0; i < 2; i++)
        #pragma unroll
        for (int j = 0; j < 12; j++)
            #pragma unroll
            for (int c = 0; c < 4; c++) acc[i][j][c] = 0.f;

    #pragma unroll
    for (int ech = 0; ech < 6; ech++) {
        uint32_t af[2][4];
        #pragma unroll
        for (int mi = 0; mi < 2; mi++)
            ldsm4(af[mi][0], af[mi][1], af[mi][2], af[mi][3],
                  s2u(&vs_[v_row + mi * 16][ech * 16 + v_coff]));
        uint32_t bf[12][2];
        #pragma unroll
        for (int p = 0; p < 6; p++)
            ldsm4(bf[2*p][0], bf[2*p][1], bf[2*p+1][0], bf[2*p+1][1],
                  s2u(&as_[p * 16 + b_row][ech * 16 + b_coff]));
        #pragma unroll
        for (int mi = 0; mi < 2; mi++)
            #pragma unroll
            for (int nj = 0; nj < 12; nj++)
                mma_f16(acc[mi][nj][0], acc[mi][nj][1], acc[mi][nj][2], acc[mi][nj][3],
                        af[mi][0], af[mi][1], af[mi][2], af[mi][3],
                        bf[nj][0], bf[nj][1]);
    }

    #pragma unroll
    for (int mi = 0; mi < 2; mi++) {
        const int tok = row0 + w * 32 + mi * 16 + (lane >> 2);
        #pragma unroll
        for (int nj = 0; nj < 12; nj++) {
            const int d = nj * 8 + (lane & 3) * 2;
            __half2 v0 = { __float2half_rn(acc[mi][nj][0]), __float2half_rn(acc[mi][nj][1]) };
            __half2 v1 = { __float2half_rn(acc[mi][nj][2]), __float2half_rn(acc[mi][nj][3]) };
            *reinterpret_cast<__half2*>(g_xf + (size_t)tok * CDIM + h * HDd + d) = v0;
            *reinterpret_cast<__half2*>(g_xf + (size_t)(tok + 8) * CDIM + h * HDd + d) = v1;
        }
    }
}

// ============================================================
extern "C" void kernel_launch(void* const* d_in, const int* in_sizes, int n_in,
                              void* d_out, int out_size)
{
    const float* cx  = (const float*)d_in[0];
    const float* dx  = (const float*)d_in[1];
    const float* Wq  = (const float*)d_in[2];
    const float* Wkv = (const float*)d_in[3];
    const float* Wp  = (const float*)d_in[4];
    const float* bp  = (const float*)d_in[5];
    float* out = (float*)d_out;

    cudaFuncSetAttribute(gemm_mma<true>,  cudaFuncAttributeMaxDynamicSharedMemorySize, GSMEM);
    cudaFuncSetAttribute(gemm_mma<false>, cudaFuncAttributeMaxDynamicSharedMemorySize, GSMEM);

    __half *a1f, *a2f, *xf, *wqf, *wkf, *wpf, *qh, *kvh;
    cudaGetSymbolAddress((void**)&a1f, g_a1f);
    cudaGetSymbolAddress((void**)&a2f, g_a2f);
    cudaGetSymbolAddress((void**)&xf,  g_xf);
    cudaGetSymbolAddress((void**)&wqf, g_wqf);
    cudaGetSymbolAddress((void**)&wkf, g_wkf);
    cudaGetSymbolAddress((void**)&wpf, g_wpf);
    cudaGetSymbolAddress((void**)&qh,  g_qh);
    cudaGetSymbolAddress((void**)&kvh, g_kvh);

    const int n4 = MROWS * CDIM / 4;
    tofp16_kernel<<<(n4 + 255) / 256, 256>>>(cx, a1f, n4);
    tofp16_kernel<<<(n4 + 255) / 256, 256>>>(dx, a2f, n4);
    tfp16_kernel<<<dim3(CDIM / 32, CDIM / 32), 256>>>(Wq,  wqf, CDIM, CDIM);
    tfp16_kernel<<<dim3(2 * CDIM / 32, CDIM / 32), 256>>>(Wkv, wkf, CDIM, 2 * CDIM);
    tfp16_kernel<<<dim3(CDIM / 32, CDIM / 32), 256>>>(Wp,  wpf, CDIM, CDIM);

    // q = cx @ Wq  (fp16 out)
    gemm_mma<true><<<dim3(CDIM / 128, MROWS / 128), 256, GSMEM>>>(a1f, wqf, nullptr, qh, CDIM);
    // kv = dx @ Wkv  (fp16 out)
    gemm_mma<true><<<dim3(2 * CDIM / 128, MROWS / 128), 256, GSMEM>>>(a2f, wkf, nullptr, kvh, 2 * CDIM);
    // attention core (tensor cores)
    sumsq_kernel<<<dim3(3, Bq, SPLIT), 256>>>();
    gram_tc<<<dim3(BHn, SPLIT), 192>>>();
    softmax2_kernel<<<dim3(BHn, HDd), 96>>>();
    av_tc<<<dim3(128, Hh), 128>>>();
    // out = x @ Wproj + b  (fp32 out)
    gemm_mma<false><<<dim3(CDIM / 128, MROWS / 128), 256, GSMEM>>>(xf, wpf, bp, out, CDIM);
}

// round 6
// speedup vs baseline: 5.5192x; 1.1120x over previous
#include <cuda_runtime.h>
#include <cuda_fp16.h>
#include <cstdint>
#include <cstddef>

// ---------------- problem constants ----------------
#define Bq    4
#define NTOK  4096
#define CDIM  768
#define Hh    8
#define HDd   96
#define MROWS (Bq * NTOK)          // 16384
#define SPLIT 8
#define BHn   (Bq * Hh)            // 32
#define SCALE_F 0.10206207261596577f
#define EPSN 1e-12f

// ---------------- scratch (device globals) ----------------
__device__ __half g_a1f[(size_t)MROWS * CDIM];       // fp16 context_x
__device__ __half g_a2f[(size_t)MROWS * CDIM];       // fp16 depth_x
__device__ __half g_qh [(size_t)MROWS * CDIM];       // fp16 q
__device__ __half g_kvh[(size_t)MROWS * 2 * CDIM];   // fp16 kv
__device__ __half g_xf [(size_t)MROWS * CDIM];       // fp16 attn output
__device__ __half g_wqf[CDIM * CDIM];
__device__ __half g_wkf[2 * CDIM * CDIM];
__device__ __half g_wpf[CDIM * CDIM];
__device__ __half g_attnh[BHn * HDd * HDd];          // fp16 softmaxed attn
__device__ float g_part[SPLIT * BHn * HDd * HDd];
__device__ float g_qsq [SPLIT * BHn * HDd];
__device__ float g_ksq [SPLIT * BHn * HDd];

// ---------------- helpers ----------------
__device__ __forceinline__ uint32_t s2u(const void* p) {
    uint32_t a;
    asm("{ .reg .u64 t; cvta.to.shared.u64 t, %1; cvt.u32.u64 %0, t; }" : "=r"(a) : "l"(p));
    return a;
}
__device__ __forceinline__ void cp16(uint32_t dst, const void* src) {
    asm volatile("cp.async.cg.shared.global [%0], [%1], 16;" :: "r"(dst), "l"(src));
}
__device__ __forceinline__ void cp_commit() { asm volatile("cp.async.commit_group;"); }
template <int N>
__device__ __forceinline__ void cp_wait() { asm volatile("cp.async.wait_group %0;" :: "n"(N)); }

__device__ __forceinline__ void ldsm4(uint32_t& r0, uint32_t& r1, uint32_t& r2, uint32_t& r3,
                                      uint32_t addr) {
    asm volatile("ldmatrix.sync.aligned.m8n8.x4.shared.b16 {%0,%1,%2,%3}, [%4];"
                 : "=r"(r0), "=r"(r1), "=r"(r2), "=r"(r3) : "r"(addr));
}
__device__ __forceinline__ void ldsm4t(uint32_t& r0, uint32_t& r1, uint32_t& r2, uint32_t& r3,
                                       uint32_t addr) {
    asm volatile("ldmatrix.sync.aligned.m8n8.x4.trans.shared.b16 {%0,%1,%2,%3}, [%4];"
                 : "=r"(r0), "=r"(r1), "=r"(r2), "=r"(r3) : "r"(addr));
}
__device__ __forceinline__ void mma_f16(float& c0, float& c1, float& c2, float& c3,
                                        uint32_t a0, uint32_t a1, uint32_t a2, uint32_t a3,
                                        uint32_t b0, uint32_t b1) {
    asm volatile(
        "mma.sync.aligned.m16n8k16.row.col.f32.f16.f16.f32 "
        "{%0,%1,%2,%3}, {%4,%5,%6,%7}, {%8,%9}, {%0,%1,%2,%3};"
        : "+f"(c0), "+f"(c1), "+f"(c2), "+f"(c3)
        : "r"(a0), "r"(a1), "r"(a2), "r"(a3), "r"(b0), "r"(b1));
}

// ============================================================
// fp16 mma.sync GEMM: C[M,Nc] = A[M,768] @ B[Nc,768]^T (+bias)
// CTA 128x128, Ktile=64, 3-stage cp.async, 2 CTAs/SM
// ============================================================
#define PIPE      3
#define TILE_B    16384
#define STAGE_B   (2 * TILE_B)
#define GSMEM     (PIPE * STAGE_B)     // 98304
#define NKT       12

template <bool HALF_OUT>
__global__ __launch_bounds__(256, 2) void gemm_mma(
    const __half* __restrict__ A, const __half* __restrict__ B,
    const float* __restrict__ bias, void* __restrict__ outv, int Nc)
{
    extern __shared__ __align__(1024) char smem[];
    const uint32_t sbase = s2u(smem);

    const int tid  = threadIdx.x;
    const int lane = tid & 31;
    const int wid  = tid >> 5;
    const int m0 = blockIdx.y * 128;
    const int n0 = blockIdx.x * 128;
    const int wm = (wid >> 2) * 64;
    const int wn = (wid & 3) * 32;

    const uint32_t a_row   = wm + (lane & 15);
    const uint32_t a_swz   = (lane & 7) * 16;
    const uint32_t a_xhalf = (lane >> 4) * 16;
    const int l8 = lane & 7;
    const int lg = lane >> 3;
    const uint32_t b_row_base = wn + (lg >> 1) * 8 + l8;
    const uint32_t b_khalf    = (lg & 1) * 16;
    const uint32_t b_swz      = l8 * 16;

    float acc[4][4][4];
    #pragma unroll
    for (int i = 0; i < 4; i++)
        #pragma unroll
        for (int j = 0; j < 4; j++)
            #pragma unroll
            for (int c = 0; c < 4; c++) acc[i][j][c] = 0.f;

    auto issue = [&](int kt, int slot) {
        const int k0 = kt * 64;
        const uint32_t sA = sbase + slot * STAGE_B;
        const uint32_t sB = sA + TILE_B;
        #pragma unroll
        for (int i = 0; i < 8; i++) {
            const int c = tid + i * 256;
            const int row = (c >> 3) & 127;
            const int x16 = c & 7;
            const uint32_t off = (uint32_t)(row * 128 + ((x16 * 16) ^ ((row & 7) * 16)));
            if (c < 1024) cp16(sA + off, A + (size_t)(m0 + row) * CDIM + k0 + x16 * 8);
            else          cp16(sB + off, B + (size_t)(n0 + row) * CDIM + k0 + x16 * 8);
        }
        cp_commit();
    };

    issue(0, 0); issue(1, 1);

    for (int kt = 0; kt < NKT; kt++) {
        const int slot = kt % 3;
        cp_wait<PIPE - 2>();
        __syncthreads();
        if (kt + 2 < NKT) issue(kt + 2, (kt + 2) % 3);

        const uint32_t sA = sbase + slot * STAGE_B;
        const uint32_t sB = sA + TILE_B;

        #pragma unroll
        for (int ks = 0; ks < 4; ks++) {
            uint32_t af[4][4];
            #pragma unroll
            for (int mi = 0; mi < 4; mi++) {
                const uint32_t addr = sA + (a_row + mi * 16) * 128
                                    + ((ks * 32 + a_xhalf) ^ a_swz);
                ldsm4(af[mi][0], af[mi][1], af[mi][2], af[mi][3], addr);
            }
            uint32_t bf[4][2];
            #pragma unroll
            for (int p = 0; p < 2; p++) {
                const uint32_t addr = sB + (b_row_base + p * 16) * 128
                                    + ((ks * 32 + b_khalf) ^ b_swz);
                ldsm4(bf[2*p][0], bf[2*p][1], bf[2*p+1][0], bf[2*p+1][1], addr);
            }
            #pragma unroll
            for (int mi = 0; mi < 4; mi++)
                #pragma unroll
                for (int nj = 0; nj < 4; nj++)
                    mma_f16(acc[mi][nj][0], acc[mi][nj][1], acc[mi][nj][2], acc[mi][nj][3],
                            af[mi][0], af[mi][1], af[mi][2], af[mi][3],
                            bf[nj][0], bf[nj][1]);
        }
    }

    #pragma unroll
    for (int mi = 0; mi < 4; mi++) {
        const int r0 = m0 + wm + mi * 16 + (lane >> 2);
        #pragma unroll
        for (int nj = 0; nj < 4; nj++) {
            const int c = n0 + wn + nj * 8 + (lane & 3) * 2;
            float b0 = 0.f, b1 = 0.f;
            if (bias) { b0 = bias[c]; b1 = bias[c + 1]; }
            if (HALF_OUT) {
                __half* H = (__half*)outv;
                __half2 v0 = { __float2half_rn(acc[mi][nj][0] + b0),
                               __float2half_rn(acc[mi][nj][1] + b1) };
                __half2 v1 = { __float2half_rn(acc[mi][nj][2] + b0),
                               __float2half_rn(acc[mi][nj][3] + b1) };
                *reinterpret_cast<__half2*>(H + (size_t)r0 * Nc + c) = v0;
                *reinterpret_cast<__half2*>(H + (size_t)(r0 + 8) * Nc + c) = v1;
            } else {
                float* F = (float*)outv;
                float2 v0 = { acc[mi][nj][0] + b0, acc[mi][nj][1] + b1 };
                float2 v1 = { acc[mi][nj][2] + b0, acc[mi][nj][3] + b1 };
                *reinterpret_cast<float2*>(F + (size_t)r0 * Nc + c) = v0;
                *reinterpret_cast<float2*>(F + (size_t)(r0 + 8) * Nc + c) = v1;
            }
        }
    }
}

// ============================================================
// fp32 -> fp16 convert
// ============================================================
__global__ __launch_bounds__(256) void tofp16_kernel(
    const float* __restrict__ in, __half* __restrict__ out, int n4)
{
    const int i = blockIdx.x * 256 + threadIdx.x;
    if (i >= n4) return;
    const float4 v = reinterpret_cast<const float4*>(in)[i];
    __half2 h0 = { __float2half_rn(v.x), __float2half_rn(v.y) };
    __half2 h1 = { __float2half_rn(v.z), __float2half_rn(v.w) };
    reinterpret_cast<__half2*>(out)[i * 2 + 0] = h0;
    reinterpret_cast<__half2*>(out)[i * 2 + 1] = h1;
}

// ============================================================
// transpose W[K,Nc] -> T[Nc,K] fp16
// ============================================================
__global__ __launch_bounds__(256) void tfp16_kernel(
    const float* __restrict__ W, __half* __restrict__ T, int K, int Nc)
{
    __shared__ float t[32][33];
    const int n0 = blockIdx.x * 32, k0 = blockIdx.y * 32;
    const int tx = threadIdx.x & 31, ty = threadIdx.x >> 5;
    #pragma unroll
    for (int i = 0; i < 32; i += 8)
        t[ty + i][tx] = W[(size_t)(k0 + ty + i) * Nc + n0 + tx];
    __syncthreads();
    #pragma unroll
    for (int i = 0; i < 32; i += 8)
        T[(size_t)(n0 + ty + i) * K + k0 + tx] = __float2half_rn(t[tx][ty + i]);
}

// ============================================================
// Column sum-of-squares partials over token splits
// ============================================================
__global__ __launch_bounds__(256) void sumsq_kernel()
{
    const int c = blockIdx.x * 256 + threadIdx.x;
    const int b = blockIdx.y;
    const int sp = blockIdx.z;
    const int n0 = sp * (NTOK / SPLIT);

    const __half* qp = g_qh  + (size_t)(b * NTOK + n0) * CDIM + c;
    const __half* kp = g_kvh + (size_t)(b * NTOK + n0) * (2 * CDIM) + c;
    float sq = 0.f, sk = 0.f;
    #pragma unroll 4
    for (int n = 0; n < NTOK / SPLIT; n++) {
        const float qv = __half2float(qp[(size_t)n * CDIM]);
        const float kv = __half2float(kp[(size_t)n * 2 * CDIM]);
        sq += qv * qv;
        sk += kv * kv;
    }
    const int bh = b * Hh + c / HDd;
    const int d  = c % HDd;
    const int po = sp * BHn + bh;
    g_qsq[po * HDd + d] = sq;
    g_ksq[po * HDd + d] = sk;
}

// ============================================================
// Tensor-core Gram partials: part[d,e] = sum_n q[n,d] k[n,e]
// ============================================================
#define GPITCH 104
#define GNI    32

__global__ __launch_bounds__(192) void gram_tc()
{
    __shared__ __half qs[3][16][GPITCH];
    __shared__ __half ks[3][16][GPITCH];

    const int bh = blockIdx.x;
    const int b  = bh >> 3;
    const int h  = bh & 7;
    const int sp = blockIdx.y;
    const int nbase = b * NTOK + sp * (NTOK / SPLIT);

    const int tid  = threadIdx.x;
    const int lane = tid & 31;
    const int w    = tid >> 5;
    const int e0   = w * 16;

    const __half* qbase = g_qh  + (size_t)nbase * CDIM + h * HDd;
    const __half* kbase = g_kvh + (size_t)nbase * (2 * CDIM) + h * HDd;

    const int lrow = tid / 12;
    const int lx   = tid % 12;

    auto issue = [&](int it, int s) {
        const int n0 = it * 16;
        cp16(s2u(&qs[s][lrow][lx * 8]),
             qbase + (size_t)(n0 + lrow) * CDIM + lx * 8);
        cp16(s2u(&ks[s][lrow][lx * 8]),
             kbase + (size_t)(n0 + lrow) * (2 * CDIM) + lx * 8);
        cp_commit();
    };

    const uint32_t a_row = (lane & 7) + ((lane >> 4) & 1) * 8;
    const uint32_t a_coff = ((lane >> 3) & 1) * 8;
    const uint32_t b_row = (lane & 7) + ((lane >> 3) & 1) * 8;
    const uint32_t b_coff = ((lane >> 4) & 1) * 8;

    float acc[6][2][4];
    #pragma unroll
    for (int i = 0; i < 6; i++)
        #pragma unroll
        for (int j = 0; j < 2; j++)
            #pragma unroll
            for (int c = 0; c < 4; c++) acc[i][j][c] = 0.f;

    issue(0, 0); issue(1, 1);

    for (int it = 0; it < GNI; it++) {
        const int s = it % 3;
        if (it + 1 < GNI) cp_wait<1>(); else cp_wait<0>();
        __syncthreads();
        if (it + 2 < GNI) issue(it + 2, (it + 2) % 3);

        uint32_t bf[4];
        ldsm4t(bf[0], bf[1], bf[2], bf[3], s2u(&ks[s][b_row][e0 + b_coff]));
        uint32_t af[6][4];
        #pragma unroll
        for (int mi = 0; mi < 6; mi++)
            ldsm4t(af[mi][0], af[mi][1], af[mi][2], af[mi][3],
                   s2u(&qs[s][a_row][mi * 16 + a_coff]));
        #pragma unroll
        for (int mi = 0; mi < 6; mi++)
            #pragma unroll
            for (int nj = 0; nj < 2; nj++)
                mma_f16(acc[mi][nj][0], acc[mi][nj][1], acc[mi][nj][2], acc[mi][nj][3],
                        af[mi][0], af[mi][1], af[mi][2], af[mi][3],
                        bf[nj * 2], bf[nj * 2 + 1]);
    }

    float* op = g_part + (size_t)(sp * BHn + bh) * (HDd * HDd);
    #pragma unroll
    for (int mi = 0; mi < 6; mi++) {
        const int d = mi * 16 + (lane >> 2);
        #pragma unroll
        for (int nj = 0; nj < 2; nj++) {
            const int e = e0 + nj * 8 + (lane & 3) * 2;
            float2 v0 = { acc[mi][nj][0], acc[mi][nj][1] };
            float2 v1 = { acc[mi][nj][2], acc[mi][nj][3] };
            *reinterpret_cast<float2*>(op + d * HDd + e) = v0;
            *reinterpret_cast<float2*>(op + (d + 8) * HDd + e) = v1;
        }
    }
}

// ============================================================
// softmax -> fp16 attn
// ============================================================
__global__ __launch_bounds__(96) void softmax2_kernel()
{
    const int bh = blockIdx.x;
    const int d  = blockIdx.y;
    const int e  = threadIdx.x;
    const int w  = e >> 5, lane = e & 31;

    __shared__ float s_nq;
    __shared__ float s_m[3], s_s[3];

    float sk = 0.f, sp = 0.f;
    #pragma unroll
    for (int p = 0; p < SPLIT; p++) {
        sk += g_ksq[(p * BHn + bh) * HDd + e];
        sp += g_part[(size_t)(p * BHn + bh) * (HDd * HDd) + d * HDd + e];
    }
    if (e == 0) {
        float sq = 0.f;
        #pragma unroll
        for (int p = 0; p < SPLIT; p++) sq += g_qsq[(p * BHn + bh) * HDd + d];
        s_nq = fmaxf(sqrtf(sq), EPSN);
    }
    __syncthreads();

    const float a = sp * (SCALE_F / s_nq) / fmaxf(sqrtf(sk), EPSN);

    float m = a;
    #pragma unroll
    for (int o = 16; o > 0; o >>= 1) m = fmaxf(m, __shfl_xor_sync(0xffffffffu, m, o));
    if (lane == 0) s_m[w] = m;
    __syncthreads();
    m = fmaxf(fmaxf(s_m[0], s_m[1]), s_m[2]);

    const float ex = __expf(a - m);
    float s = ex;
    #pragma unroll
    for (int o = 16; o > 0; o >>= 1) s += __shfl_xor_sync(0xffffffffu, s, o);
    if (lane == 0) s_s[w] = s;
    __syncthreads();
    s = s_s[0] + s_s[1] + s_s[2];

    g_attnh[(size_t)bh * (HDd * HDd) + d * HDd + e] = __float2half_rn(ex / s);
}

// ============================================================
// Tensor-core AV: x[n,d] = sum_e attn[d,e] v[n,e]
// ============================================================
#define APITCH 104

__global__ __launch_bounds__(128) void av_tc()
{
    __shared__ __half vs_[128][APITCH];
    __shared__ __half as_[96][APITCH];

    const int tile = blockIdx.x;
    const int h    = blockIdx.y;
    const int b    = tile >> 5;
    const int bh   = b * Hh + h;
    const int row0 = tile * 128;

    const int tid  = threadIdx.x;
    const int lane = tid & 31;
    const int w    = tid >> 5;

    const __half* vsrc = g_kvh + (size_t)row0 * (2 * CDIM) + CDIM + h * HDd;
    const __half* asrc = g_attnh + (size_t)bh * (HDd * HDd);
    #pragma unroll
    for (int i = 0; i < 12; i++) {
        const int c = tid + i * 128;
        const int r = c / 12, x = c % 12;
        cp16(s2u(&vs_[r][x * 8]), vsrc + (size_t)r * (2 * CDIM) + x * 8);
    }
    #pragma unroll
    for (int i = 0; i < 9; i++) {
        const int c = tid + i * 128;
        const int r = c / 12, x = c % 12;
        cp16(s2u(&as_[r][x * 8]), asrc + r * HDd + x * 8);
    }
    cp_commit();
    cp_wait<0>();
    __syncthreads();

    const uint32_t v_row = w * 32 + (lane & 15);
    const uint32_t v_coff = (lane >> 4) * 8;
    const uint32_t b_row = (lane & 7) + ((lane >> 4) & 1) * 8;
    const uint32_t b_coff = ((lane >> 3) & 1) * 8;

    float acc[2][12][4];
    #pragma unroll
    for (int i = 0; i < 2; i++)
        #pragma unroll
        for (int j = 0; j < 12; j++)
            #pragma unroll
            for (int c = 0; c < 4; c++) acc[i][j][c] = 0.f;

    #pragma unroll
    for (int ech = 0; ech < 6; ech++) {
        uint32_t af[2][4];
        #pragma unroll
        for (int mi = 0; mi < 2; mi++)
            ldsm4(af[mi][0], af[mi][1], af[mi][2], af[mi][3],
                  s2u(&vs_[v_row + mi * 16][ech * 16 + v_coff]));
        uint32_t bf[12][2];
        #pragma unroll
        for (int p = 0; p < 6; p++)
            ldsm4(bf[2*p][0], bf[2*p][1], bf[2*p+1][0], bf[2*p+1][1],
                  s2u(&as_[p * 16 + b_row][ech * 16 + b_coff]));
        #pragma unroll
        for (int mi = 0; mi < 2; mi++)
            #pragma unroll
            for (int nj = 0; nj < 12; nj++)
                mma_f16(acc[mi][nj][0], acc[mi][nj][1], acc[mi][nj][2], acc[mi][nj][3],
                        af[mi][0], af[mi][1], af[mi][2], af[mi][3],
                        bf[nj][0], bf[nj][1]);
    }

    #pragma unroll
    for (int mi = 0; mi < 2; mi++) {
        const int tok = row0 + w * 32 + mi * 16 + (lane >> 2);
        #pragma unroll
        for (int nj = 0; nj < 12; nj++) {
            const int d = nj * 8 + (lane & 3) * 2;
            __half2 v0 = { __float2half_rn(acc[mi][nj][0]), __float2half_rn(acc[mi][nj][1]) };
            __half2 v1 = { __float2half_rn(acc[mi][nj][2]), __float2half_rn(acc[mi][nj][3]) };
            *reinterpret_cast<__half2*>(g_xf + (size_t)tok * CDIM + h * HDd + d) = v0;
            *reinterpret_cast<__half2*>(g_xf + (size_t)(tok + 8) * CDIM + h * HDd + d) = v1;
        }
    }
}

// ============================================================
extern "C" void kernel_launch(void* const* d_in, const int* in_sizes, int n_in,
                              void* d_out, int out_size)
{
    const float* cx  = (const float*)d_in[0];
    const float* dx  = (const float*)d_in[1];
    const float* Wq  = (const float*)d_in[2];
    const float* Wkv = (const float*)d_in[3];
    const float* Wp  = (const float*)d_in[4];
    const float* bp  = (const float*)d_in[5];
    float* out = (float*)d_out;

    cudaFuncSetAttribute(gemm_mma<true>,  cudaFuncAttributeMaxDynamicSharedMemorySize, GSMEM);
    cudaFuncSetAttribute(gemm_mma<false>, cudaFuncAttributeMaxDynamicSharedMemorySize, GSMEM);

    __half *a1f, *a2f, *xf, *wqf, *wkf, *wpf, *qh, *kvh;
    cudaGetSymbolAddress((void**)&a1f, g_a1f);
    cudaGetSymbolAddress((void**)&a2f, g_a2f);
    cudaGetSymbolAddress((void**)&xf,  g_xf);
    cudaGetSymbolAddress((void**)&wqf, g_wqf);
    cudaGetSymbolAddress((void**)&wkf, g_wkf);
    cudaGetSymbolAddress((void**)&wpf, g_wpf);
    cudaGetSymbolAddress((void**)&qh,  g_qh);
    cudaGetSymbolAddress((void**)&kvh, g_kvh);

    const int n4 = MROWS * CDIM / 4;
    tofp16_kernel<<<(n4 + 255) / 256, 256>>>(cx, a1f, n4);
    tofp16_kernel<<<(n4 + 255) / 256, 256>>>(dx, a2f, n4);
    tfp16_kernel<<<dim3(CDIM / 32, CDIM / 32), 256>>>(Wq,  wqf, CDIM, CDIM);
    tfp16_kernel<<<dim3(2 * CDIM / 32, CDIM / 32), 256>>>(Wkv, wkf, CDIM, 2 * CDIM);
    tfp16_kernel<<<dim3(CDIM / 32, CDIM / 32), 256>>>(Wp,  wpf, CDIM, CDIM);

    // q = cx @ Wq  (fp16 out)
    gemm_mma<true><<<dim3(CDIM / 128, MROWS / 128), 256, GSMEM>>>(a1f, wqf, nullptr, qh, CDIM);
    // kv = dx @ Wkv  (fp16 out)
    gemm_mma<true><<<dim3(2 * CDIM / 128, MROWS / 128), 256, GSMEM>>>(a2f, wkf, nullptr, kvh, 2 * CDIM);
    // attention core (tensor cores)
    sumsq_kernel<<<dim3(3, Bq, SPLIT), 256>>>();
    gram_tc<<<dim3(BHn, SPLIT), 192>>>();
    softmax2_kernel<<<dim3(BHn, HDd), 96>>>();
    av_tc<<<dim3(128, Hh), 128>>>();
    // out = x @ Wproj + b  (fp32 out)
    gemm_mma<false><<<dim3(CDIM / 128, MROWS / 128), 256, GSMEM>>>(xf, wpf, bp, out, CDIM);
}

// round 7
// speedup vs baseline: 5.6681x; 1.0270x over previous
#include <cuda_runtime.h>
#include <cuda_fp16.h>
#include <cstdint>
#include <cstddef>

// ---------------- problem constants ----------------
#define Bq    4
#define NTOK  4096
#define CDIM  768
#define Hh    8
#define HDd   96
#define MROWS (Bq * NTOK)          // 16384
#define SPLIT 8
#define BHn   (Bq * Hh)            // 32
#define SCALE_F 0.10206207261596577f
#define EPSN 1e-12f

// ---------------- scratch (device globals) ----------------
__device__ __half g_a1f[(size_t)MROWS * CDIM];       // fp16 context_x
__device__ __half g_a2f[(size_t)MROWS * CDIM];       // fp16 depth_x
__device__ __half g_qh [(size_t)MROWS * CDIM];       // fp16 q
__device__ __half g_kvh[(size_t)MROWS * 2 * CDIM];   // fp16 kv
__device__ __half g_xf [(size_t)MROWS * CDIM];       // fp16 attn output
__device__ __half g_wqf[CDIM * CDIM];
__device__ __half g_wkf[2 * CDIM * CDIM];
__device__ __half g_wpf[CDIM * CDIM];
__device__ __half g_attnh[BHn * HDd * HDd];          // fp16 softmaxed attn
__device__ float g_part[SPLIT * BHn * HDd * HDd];
__device__ float g_qsq [SPLIT * BHn * HDd];
__device__ float g_ksq [SPLIT * BHn * HDd];

// ---------------- helpers ----------------
__device__ __forceinline__ uint32_t s2u(const void* p) {
    uint32_t a;
    asm("{ .reg .u64 t; cvta.to.shared.u64 t, %1; cvt.u32.u64 %0, t; }" : "=r"(a) : "l"(p));
    return a;
}
__device__ __forceinline__ void cp16(uint32_t dst, const void* src) {
    asm volatile("cp.async.cg.shared.global [%0], [%1], 16;" :: "r"(dst), "l"(src));
}
__device__ __forceinline__ void cp_commit() { asm volatile("cp.async.commit_group;"); }
template <int N>
__device__ __forceinline__ void cp_wait() { asm volatile("cp.async.wait_group %0;" :: "n"(N)); }

__device__ __forceinline__ void ldsm4(uint32_t& r0, uint32_t& r1, uint32_t& r2, uint32_t& r3,
                                      uint32_t addr) {
    asm volatile("ldmatrix.sync.aligned.m8n8.x4.shared.b16 {%0,%1,%2,%3}, [%4];"
                 : "=r"(r0), "=r"(r1), "=r"(r2), "=r"(r3) : "r"(addr));
}
__device__ __forceinline__ void ldsm4t(uint32_t& r0, uint32_t& r1, uint32_t& r2, uint32_t& r3,
                                       uint32_t addr) {
    asm volatile("ldmatrix.sync.aligned.m8n8.x4.trans.shared.b16 {%0,%1,%2,%3}, [%4];"
                 : "=r"(r0), "=r"(r1), "=r"(r2), "=r"(r3) : "r"(addr));
}
__device__ __forceinline__ void mma_f16(float& c0, float& c1, float& c2, float& c3,
                                        uint32_t a0, uint32_t a1, uint32_t a2, uint32_t a3,
                                        uint32_t b0, uint32_t b1) {
    asm volatile(
        "mma.sync.aligned.m16n8k16.row.col.f32.f16.f16.f32 "
        "{%0,%1,%2,%3}, {%4,%5,%6,%7}, {%8,%9}, {%0,%1,%2,%3};"
        : "+f"(c0), "+f"(c1), "+f"(c2), "+f"(c3)
        : "r"(a0), "r"(a1), "r"(a2), "r"(a3), "r"(b0), "r"(b1));
}

// ============================================================
// GEMM core config
// ============================================================
#define PIPE      3
#define TILE_B    16384
#define STAGE_B   (2 * TILE_B)
#define GSMEM     (PIPE * STAGE_B)     // 98304
#define NKT       12
#define NT1       6                    // n-tiles of q GEMM (768/128)

// ============================================================
// Fused projection GEMM: job1 = q (Nc=768), job2 = kv (Nc=1536)
// grid (18, 128); fp16 output, no bias
// ============================================================
__global__ __launch_bounds__(256, 2) void gemm_proj(
    const __half* __restrict__ A1, const __half* __restrict__ B1, __half* __restrict__ O1,
    const __half* __restrict__ A2, const __half* __restrict__ B2, __half* __restrict__ O2)
{
    extern __shared__ __align__(1024) char smem[];
    const uint32_t sbase = s2u(smem);

    const bool j2 = blockIdx.x >= NT1;
    const __half* __restrict__ A = j2 ? A2 : A1;
    const __half* __restrict__ B = j2 ? B2 : B1;
    __half* __restrict__ O = j2 ? O2 : O1;
    const int Nc = j2 ? 2 * CDIM : CDIM;
    const int n0 = (j2 ? (int)blockIdx.x - NT1 : (int)blockIdx.x) * 128;
    const int m0 = blockIdx.y * 128;

    const int tid  = threadIdx.x;
    const int lane = tid & 31;
    const int wid  = tid >> 5;
    const int wm = (wid >> 2) * 64;
    const int wn = (wid & 3) * 32;

    const uint32_t a_row   = wm + (lane & 15);
    const uint32_t a_swz   = (lane & 7) * 16;
    const uint32_t a_xhalf = (lane >> 4) * 16;
    const int l8 = lane & 7;
    const int lg = lane >> 3;
    const uint32_t b_row_base = wn + (lg >> 1) * 8 + l8;
    const uint32_t b_khalf    = (lg & 1) * 16;
    const uint32_t b_swz      = l8 * 16;

    float acc[4][4][4];
    #pragma unroll
    for (int i = 0; i < 4; i++)
        #pragma unroll
        for (int j = 0; j < 4; j++)
            #pragma unroll
            for (int c = 0; c < 4; c++) acc[i][j][c] = 0.f;

    auto issue = [&](int kt, int slot) {
        const int k0 = kt * 64;
        const uint32_t sA = sbase + slot * STAGE_B;
        const uint32_t sB = sA + TILE_B;
        #pragma unroll
        for (int i = 0; i < 8; i++) {
            const int c = tid + i * 256;
            const int row = (c >> 3) & 127;
            const int x16 = c & 7;
            const uint32_t off = (uint32_t)(row * 128 + ((x16 * 16) ^ ((row & 7) * 16)));
            if (c < 1024) cp16(sA + off, A + (size_t)(m0 + row) * CDIM + k0 + x16 * 8);
            else          cp16(sB + off, B + (size_t)(n0 + row) * CDIM + k0 + x16 * 8);
        }
        cp_commit();
    };

    issue(0, 0); issue(1, 1);

    for (int kt = 0; kt < NKT; kt++) {
        const int slot = kt % 3;
        cp_wait<PIPE - 2>();
        __syncthreads();
        if (kt + 2 < NKT) issue(kt + 2, (kt + 2) % 3);

        const uint32_t sA = sbase + slot * STAGE_B;
        const uint32_t sB = sA + TILE_B;

        #pragma unroll
        for (int ks = 0; ks < 4; ks++) {
            uint32_t af[4][4];
            #pragma unroll
            for (int mi = 0; mi < 4; mi++) {
                const uint32_t addr = sA + (a_row + mi * 16) * 128
                                    + ((ks * 32 + a_xhalf) ^ a_swz);
                ldsm4(af[mi][0], af[mi][1], af[mi][2], af[mi][3], addr);
            }
            uint32_t bf[4][2];
            #pragma unroll
            for (int p = 0; p < 2; p++) {
                const uint32_t addr = sB + (b_row_base + p * 16) * 128
                                    + ((ks * 32 + b_khalf) ^ b_swz);
                ldsm4(bf[2*p][0], bf[2*p][1], bf[2*p+1][0], bf[2*p+1][1], addr);
            }
            #pragma unroll
            for (int mi = 0; mi < 4; mi++)
                #pragma unroll
                for (int nj = 0; nj < 4; nj++)
                    mma_f16(acc[mi][nj][0], acc[mi][nj][1], acc[mi][nj][2], acc[mi][nj][3],
                            af[mi][0], af[mi][1], af[mi][2], af[mi][3],
                            bf[nj][0], bf[nj][1]);
        }
    }

    #pragma unroll
    for (int mi = 0; mi < 4; mi++) {
        const int r0 = m0 + wm + mi * 16 + (lane >> 2);
        #pragma unroll
        for (int nj = 0; nj < 4; nj++) {
            const int c = n0 + wn + nj * 8 + (lane & 3) * 2;
            __half2 v0 = { __float2half_rn(acc[mi][nj][0]), __float2half_rn(acc[mi][nj][1]) };
            __half2 v1 = { __float2half_rn(acc[mi][nj][2]), __float2half_rn(acc[mi][nj][3]) };
            *reinterpret_cast<__half2*>(O + (size_t)r0 * Nc + c) = v0;
            *reinterpret_cast<__half2*>(O + (size_t)(r0 + 8) * Nc + c) = v1;
        }
    }
}

// ============================================================
// Final GEMM: out = x @ Wp^T + bias, fp32 output
// ============================================================
__global__ __launch_bounds__(256, 2) void gemm_out(
    const __half* __restrict__ A, const __half* __restrict__ B,
    const float* __restrict__ bias, float* __restrict__ Cout)
{
    extern __shared__ __align__(1024) char smem[];
    const uint32_t sbase = s2u(smem);
    const int Nc = CDIM;

    const int tid  = threadIdx.x;
    const int lane = tid & 31;
    const int wid  = tid >> 5;
    const int m0 = blockIdx.y * 128;
    const int n0 = blockIdx.x * 128;
    const int wm = (wid >> 2) * 64;
    const int wn = (wid & 3) * 32;

    const uint32_t a_row   = wm + (lane & 15);
    const uint32_t a_swz   = (lane & 7) * 16;
    const uint32_t a_xhalf = (lane >> 4) * 16;
    const int l8 = lane & 7;
    const int lg = lane >> 3;
    const uint32_t b_row_base = wn + (lg >> 1) * 8 + l8;
    const uint32_t b_khalf    = (lg & 1) * 16;
    const uint32_t b_swz      = l8 * 16;

    float acc[4][4][4];
    #pragma unroll
    for (int i = 0; i < 4; i++)
        #pragma unroll
        for (int j = 0; j < 4; j++)
            #pragma unroll
            for (int c = 0; c < 4; c++) acc[i][j][c] = 0.f;

    auto issue = [&](int kt, int slot) {
        const int k0 = kt * 64;
        const uint32_t sA = sbase + slot * STAGE_B;
        const uint32_t sB = sA + TILE_B;
        #pragma unroll
        for (int i = 0; i < 8; i++) {
            const int c = tid + i * 256;
            const int row = (c >> 3) & 127;
            const int x16 = c & 7;
            const uint32_t off = (uint32_t)(row * 128 + ((x16 * 16) ^ ((row & 7) * 16)));
            if (c < 1024) cp16(sA + off, A + (size_t)(m0 + row) * CDIM + k0 + x16 * 8);
            else          cp16(sB + off, B + (size_t)(n0 + row) * CDIM + k0 + x16 * 8);
        }
        cp_commit();
    };

    issue(0, 0); issue(1, 1);

    for (int kt = 0; kt < NKT; kt++) {
        const int slot = kt % 3;
        cp_wait<PIPE - 2>();
        __syncthreads();
        if (kt + 2 < NKT) issue(kt + 2, (kt + 2) % 3);

        const uint32_t sA = sbase + slot * STAGE_B;
        const uint32_t sB = sA + TILE_B;

        #pragma unroll
        for (int ks = 0; ks < 4; ks++) {
            uint32_t af[4][4];
            #pragma unroll
            for (int mi = 0; mi < 4; mi++) {
                const uint32_t addr = sA + (a_row + mi * 16) * 128
                                    + ((ks * 32 + a_xhalf) ^ a_swz);
                ldsm4(af[mi][0], af[mi][1], af[mi][2], af[mi][3], addr);
            }
            uint32_t bf[4][2];
            #pragma unroll
            for (int p = 0; p < 2; p++) {
                const uint32_t addr = sB + (b_row_base + p * 16) * 128
                                    + ((ks * 32 + b_khalf) ^ b_swz);
                ldsm4(bf[2*p][0], bf[2*p][1], bf[2*p+1][0], bf[2*p+1][1], addr);
            }
            #pragma unroll
            for (int mi = 0; mi < 4; mi++)
                #pragma unroll
                for (int nj = 0; nj < 4; nj++)
                    mma_f16(acc[mi][nj][0], acc[mi][nj][1], acc[mi][nj][2], acc[mi][nj][3],
                            af[mi][0], af[mi][1], af[mi][2], af[mi][3],
                            bf[nj][0], bf[nj][1]);
        }
    }

    #pragma unroll
    for (int mi = 0; mi < 4; mi++) {
        const int r0 = m0 + wm + mi * 16 + (lane >> 2);
        #pragma unroll
        for (int nj = 0; nj < 4; nj++) {
            const int c = n0 + wn + nj * 8 + (lane & 3) * 2;
            const float b0 = bias[c], b1 = bias[c + 1];
            float2 v0 = { acc[mi][nj][0] + b0, acc[mi][nj][1] + b1 };
            float2 v1 = { acc[mi][nj][2] + b0, acc[mi][nj][3] + b1 };
            *reinterpret_cast<float2*>(Cout + (size_t)r0 * Nc + c) = v0;
            *reinterpret_cast<float2*>(Cout + (size_t)(r0 + 8) * Nc + c) = v1;
        }
    }
}

// ============================================================
// fp32 -> fp16 convert, both inputs in one launch (grid.y selects)
// ============================================================
__global__ __launch_bounds__(256) void tofp16_dual(
    const float* __restrict__ in0, __half* __restrict__ out0,
    const float* __restrict__ in1, __half* __restrict__ out1, int n4)
{
    const int i = blockIdx.x * 256 + threadIdx.x;
    if (i >= n4) return;
    const float* in = blockIdx.y ? in1 : in0;
    __half* out = blockIdx.y ? out1 : out0;
    const float4 v = reinterpret_cast<const float4*>(in)[i];
    __half2 h0 = { __float2half_rn(v.x), __float2half_rn(v.y) };
    __half2 h1 = { __float2half_rn(v.z), __float2half_rn(v.w) };
    reinterpret_cast<__half2*>(out)[i * 2 + 0] = h0;
    reinterpret_cast<__half2*>(out)[i * 2 + 1] = h1;
}

// ============================================================
// Fused weight transpose: Wq | Wkv | Wp  ->  wqf | wkf | wpf
// grid (96, 24): bx<24 Wq, bx<72 Wkv, else Wp. 32x32 tiles.
// ============================================================
__global__ __launch_bounds__(256) void tfp16_all(
    const float* __restrict__ Wq, const float* __restrict__ Wkv,
    const float* __restrict__ Wp,
    __half* __restrict__ Tq, __half* __restrict__ Tk, __half* __restrict__ Tp)
{
    __shared__ float t[32][33];
    const int bx = blockIdx.x;
    const float* W; __half* T; int Nc, nt0;
    if (bx < 24)      { W = Wq;  T = Tq; Nc = CDIM;     nt0 = 0; }
    else if (bx < 72) { W = Wkv; T = Tk; Nc = 2 * CDIM; nt0 = 24; }
    else              { W = Wp;  T = Tp; Nc = CDIM;     nt0 = 72; }
    const int n0 = (bx - nt0) * 32, k0 = blockIdx.y * 32;
    const int tx = threadIdx.x & 31, ty = threadIdx.x >> 5;
    #pragma unroll
    for (int i = 0; i < 32; i += 8)
        t[ty + i][tx] = W[(size_t)(k0 + ty + i) * Nc + n0 + tx];
    __syncthreads();
    #pragma unroll
    for (int i = 0; i < 32; i += 8)
        T[(size_t)(n0 + ty + i) * CDIM + k0 + tx] = __float2half_rn(t[tx][ty + i]);
}

// ============================================================
// Column sum-of-squares partials over token splits
// ============================================================
__global__ __launch_bounds__(256) void sumsq_kernel()
{
    const int c = blockIdx.x * 256 + threadIdx.x;
    const int b = blockIdx.y;
    const int sp = blockIdx.z;
    const int n0 = sp * (NTOK / SPLIT);

    const __half* qp = g_qh  + (size_t)(b * NTOK + n0) * CDIM + c;
    const __half* kp = g_kvh + (size_t)(b * NTOK + n0) * (2 * CDIM) + c;
    float sq = 0.f, sk = 0.f;
    #pragma unroll 4
    for (int n = 0; n < NTOK / SPLIT; n++) {
        const float qv = __half2float(qp[(size_t)n * CDIM]);
        const float kv = __half2float(kp[(size_t)n * 2 * CDIM]);
        sq += qv * qv;
        sk += kv * kv;
    }
    const int bh = b * Hh + c / HDd;
    const int d  = c % HDd;
    const int po = sp * BHn + bh;
    g_qsq[po * HDd + d] = sq;
    g_ksq[po * HDd + d] = sk;
}

// ============================================================
// Tensor-core Gram partials: part[d,e] = sum_n q[n,d] k[n,e]
// ============================================================
#define GPITCH 104
#define GNI    32

__global__ __launch_bounds__(192) void gram_tc()
{
    __shared__ __half qs[3][16][GPITCH];
    __shared__ __half ks[3][16][GPITCH];

    const int bh = blockIdx.x;
    const int b  = bh >> 3;
    const int h  = bh & 7;
    const int sp = blockIdx.y;
    const int nbase = b * NTOK + sp * (NTOK / SPLIT);

    const int tid  = threadIdx.x;
    const int lane = tid & 31;
    const int w    = tid >> 5;
    const int e0   = w * 16;

    const __half* qbase = g_qh  + (size_t)nbase * CDIM + h * HDd;
    const __half* kbase = g_kvh + (size_t)nbase * (2 * CDIM) + h * HDd;

    const int lrow = tid / 12;
    const int lx   = tid % 12;

    auto issue = [&](int it, int s) {
        const int n0 = it * 16;
        cp16(s2u(&qs[s][lrow][lx * 8]),
             qbase + (size_t)(n0 + lrow) * CDIM + lx * 8);
        cp16(s2u(&ks[s][lrow][lx * 8]),
             kbase + (size_t)(n0 + lrow) * (2 * CDIM) + lx * 8);
        cp_commit();
    };

    const uint32_t a_row = (lane & 7) + ((lane >> 4) & 1) * 8;
    const uint32_t a_coff = ((lane >> 3) & 1) * 8;
    const uint32_t b_row = (lane & 7) + ((lane >> 3) & 1) * 8;
    const uint32_t b_coff = ((lane >> 4) & 1) * 8;

    float acc[6][2][4];
    #pragma unroll
    for (int i = 0; i < 6; i++)
        #pragma unroll
        for (int j = 0; j < 2; j++)
            #pragma unroll
            for (int c = 0; c < 4; c++) acc[i][j][c] = 0.f;

    issue(0, 0); issue(1, 1);

    for (int it = 0; it < GNI; it++) {
        const int s = it % 3;
        if (it + 1 < GNI) cp_wait<1>(); else cp_wait<0>();
        __syncthreads();
        if (it + 2 < GNI) issue(it + 2, (it + 2) % 3);

        uint32_t bf[4];
        ldsm4t(bf[0], bf[1], bf[2], bf[3], s2u(&ks[s][b_row][e0 + b_coff]));
        uint32_t af[6][4];
        #pragma unroll
        for (int mi = 0; mi < 6; mi++)
            ldsm4t(af[mi][0], af[mi][1], af[mi][2], af[mi][3],
                   s2u(&qs[s][a_row][mi * 16 + a_coff]));
        #pragma unroll
        for (int mi = 0; mi < 6; mi++)
            #pragma unroll
            for (int nj = 0; nj < 2; nj++)
                mma_f16(acc[mi][nj][0], acc[mi][nj][1], acc[mi][nj][2], acc[mi][nj][3],
                        af[mi][0], af[mi][1], af[mi][2], af[mi][3],
                        bf[nj * 2], bf[nj * 2 + 1]);
    }

    float* op = g_part + (size_t)(sp * BHn + bh) * (HDd * HDd);
    #pragma unroll
    for (int mi = 0; mi < 6; mi++) {
        const int d = mi * 16 + (lane >> 2);
        #pragma unroll
        for (int nj = 0; nj < 2; nj++) {
            const int e = e0 + nj * 8 + (lane & 3) * 2;
            float2 v0 = { acc[mi][nj][0], acc[mi][nj][1] };
            float2 v1 = { acc[mi][nj][2], acc[mi][nj][3] };
            *reinterpret_cast<float2*>(op + d * HDd + e) = v0;
            *reinterpret_cast<float2*>(op + (d + 8) * HDd + e) = v1;
        }
    }
}

// ============================================================
// softmax -> fp16 attn
// ============================================================
__global__ __launch_bounds__(96) void softmax2_kernel()
{
    const int bh = blockIdx.x;
    const int d  = blockIdx.y;
    const int e  = threadIdx.x;
    const int w  = e >> 5, lane = e & 31;

    __shared__ float s_nq;
    __shared__ float s_m[3], s_s[3];

    float sk = 0.f, sp = 0.f;
    #pragma unroll
    for (int p = 0; p < SPLIT; p++) {
        sk += g_ksq[(p * BHn + bh) * HDd + e];
        sp += g_part[(size_t)(p * BHn + bh) * (HDd * HDd) + d * HDd + e];
    }
    if (e == 0) {
        float sq = 0.f;
        #pragma unroll
        for (int p = 0; p < SPLIT; p++) sq += g_qsq[(p * BHn + bh) * HDd + d];
        s_nq = fmaxf(sqrtf(sq), EPSN);
    }
    __syncthreads();

    const float a = sp * (SCALE_F / s_nq) / fmaxf(sqrtf(sk), EPSN);

    float m = a;
    #pragma unroll
    for (int o = 16; o > 0; o >>= 1) m = fmaxf(m, __shfl_xor_sync(0xffffffffu, m, o));
    if (lane == 0) s_m[w] = m;
    __syncthreads();
    m = fmaxf(fmaxf(s_m[0], s_m[1]), s_m[2]);

    const float ex = __expf(a - m);
    float s = ex;
    #pragma unroll
    for (int o = 16; o > 0; o >>= 1) s += __shfl_xor_sync(0xffffffffu, s, o);
    if (lane == 0) s_s[w] = s;
    __syncthreads();
    s = s_s[0] + s_s[1] + s_s[2];

    g_attnh[(size_t)bh * (HDd * HDd) + d * HDd + e] = __float2half_rn(ex / s);
}

// ============================================================
// Tensor-core AV: x[n,d] = sum_e attn[d,e] v[n,e]
// ============================================================
#define APITCH 104

__global__ __launch_bounds__(128) void av_tc()
{
    __shared__ __half vs_[128][APITCH];
    __shared__ __half as_[96][APITCH];

    const int tile = blockIdx.x;
    const int h    = blockIdx.y;
    const int b    = tile >> 5;
    const int bh   = b * Hh + h;
    const int row0 = tile * 128;

    const int tid  = threadIdx.x;
    const int lane = tid & 31;
    const int w    = tid >> 5;

    const __half* vsrc = g_kvh + (size_t)row0 * (2 * CDIM) + CDIM + h * HDd;
    const __half* asrc = g_attnh + (size_t)bh * (HDd * HDd);
    #pragma unroll
    for (int i = 0; i < 12; i++) {
        const int c = tid + i * 128;
        const int r = c / 12, x = c % 12;
        cp16(s2u(&vs_[r][x * 8]), vsrc + (size_t)r * (2 * CDIM) + x * 8);
    }
    #pragma unroll
    for (int i = 0; i < 9; i++) {
        const int c = tid + i * 128;
        const int r = c / 12, x = c % 12;
        cp16(s2u(&as_[r][x * 8]), asrc + r * HDd + x * 8);
    }
    cp_commit();
    cp_wait<0>();
    __syncthreads();

    const uint32_t v_row = w * 32 + (lane & 15);
    const uint32_t v_coff = (lane >> 4) * 8;
    const uint32_t b_row = (lane & 7) + ((lane >> 4) & 1) * 8;
    const uint32_t b_coff = ((lane >> 3) & 1) * 8;

    float acc[2][12][4];
    #pragma unroll
    for (int i = 0; i < 2; i++)
        #pragma unroll
        for (int j = 0; j < 12; j++)
            #pragma unroll
            for (int c = 0; c < 4; c++) acc[i][j][c] = 0.f;

    #pragma unroll
    for (int ech = 0; ech < 6; ech++) {
        uint32_t af[2][4];
        #pragma unroll
        for (int mi = 0; mi < 2; mi++)
            ldsm4(af[mi][0], af[mi][1], af[mi][2], af[mi][3],
                  s2u(&vs_[v_row + mi * 16][ech * 16 + v_coff]));
        uint32_t bf[12][2];
        #pragma unroll
        for (int p = 0; p < 6; p++)
            ldsm4(bf[2*p][0], bf[2*p][1], bf[2*p+1][0], bf[2*p+1][1],
                  s2u(&as_[p * 16 + b_row][ech * 16 + b_coff]));
        #pragma unroll
        for (int mi = 0; mi < 2; mi++)
            #pragma unroll
            for (int nj = 0; nj < 12; nj++)
                mma_f16(acc[mi][nj][0], acc[mi][nj][1], acc[mi][nj][2], acc[mi][nj][3],
                        af[mi][0], af[mi][1], af[mi][2], af[mi][3],
                        bf[nj][0], bf[nj][1]);
    }

    #pragma unroll
    for (int mi = 0; mi < 2; mi++) {
        const int tok = row0 + w * 32 + mi * 16 + (lane >> 2);
        #pragma unroll
        for (int nj = 0; nj < 12; nj++) {
            const int d = nj * 8 + (lane & 3) * 2;
            __half2 v0 = { __float2half_rn(acc[mi][nj][0]), __float2half_rn(acc[mi][nj][1]) };
            __half2 v1 = { __float2half_rn(acc[mi][nj][2]), __float2half_rn(acc[mi][nj][3]) };
            *reinterpret_cast<__half2*>(g_xf + (size_t)tok * CDIM + h * HDd + d) = v0;
            *reinterpret_cast<__half2*>(g_xf + (size_t)(tok + 8) * CDIM + h * HDd + d) = v1;
        }
    }
}

// ============================================================
extern "C" void kernel_launch(void* const* d_in, const int* in_sizes, int n_in,
                              void* d_out, int out_size)
{
    const float* cx  = (const float*)d_in[0];
    const float* dx  = (const float*)d_in[1];
    const float* Wq  = (const float*)d_in[2];
    const float* Wkv = (const float*)d_in[3];
    const float* Wp  = (const float*)d_in[4];
    const float* bp  = (const float*)d_in[5];
    float* out = (float*)d_out;

    cudaFuncSetAttribute(gemm_proj, cudaFuncAttributeMaxDynamicSharedMemorySize, GSMEM);
    cudaFuncSetAttribute(gemm_out,  cudaFuncAttributeMaxDynamicSharedMemorySize, GSMEM);

    __half *a1f, *a2f, *xf, *wqf, *wkf, *wpf, *qh, *kvh;
    cudaGetSymbolAddress((void**)&a1f, g_a1f);
    cudaGetSymbolAddress((void**)&a2f, g_a2f);
    cudaGetSymbolAddress((void**)&xf,  g_xf);
    cudaGetSymbolAddress((void**)&wqf, g_wqf);
    cudaGetSymbolAddress((void**)&wkf, g_wkf);
    cudaGetSymbolAddress((void**)&wpf, g_wpf);
    cudaGetSymbolAddress((void**)&qh,  g_qh);
    cudaGetSymbolAddress((void**)&kvh, g_kvh);

    const int n4 = MROWS * CDIM / 4;
    tofp16_dual<<<dim3((n4 + 255) / 256, 2), 256>>>(cx, a1f, dx, a2f, n4);
    tfp16_all<<<dim3(96, 24), 256>>>(Wq, Wkv, Wp, wqf, wkf, wpf);

    // q and kv projections in one launch
    gemm_proj<<<dim3(18, MROWS / 128), 256, GSMEM>>>(a1f, wqf, qh, a2f, wkf, kvh);

    // attention core (tensor cores)
    sumsq_kernel<<<dim3(3, Bq, SPLIT), 256>>>();
    gram_tc<<<dim3(BHn, SPLIT), 192>>>();
    softmax2_kernel<<<dim3(BHn, HDd), 96>>>();
    av_tc<<<dim3(128, Hh), 128>>>();

    // out = x @ Wproj + b
    gemm_out<<<dim3(CDIM / 128, MROWS / 128), 256, GSMEM>>>(xf, wpf, bp, out);
}

// round 8
// speedup vs baseline: 6.8387x; 1.2065x over previous
#include <cuda_runtime.h>
#include <cuda_fp16.h>
#include <cstdint>
#include <cstddef>

// ---------------- problem constants ----------------
#define Bq    4
#define NTOK  4096
#define CDIM  768
#define Hh    8
#define HDd   96
#define MROWS (Bq * NTOK)          // 16384
#define SPLIT 8
#define SSPLIT 64
#define BHn   (Bq * Hh)            // 32
#define SCALE_F 0.10206207261596577f
#define EPSN 1e-12f

// ---------------- scratch (device globals) ----------------
__device__ __half g_a1f[(size_t)MROWS * CDIM];       // fp16 context_x
__device__ __half g_a2f[(size_t)MROWS * CDIM];       // fp16 depth_x
__device__ __half g_qh [(size_t)MROWS * CDIM];       // fp16 q
__device__ __half g_kvh[(size_t)MROWS * 2 * CDIM];   // fp16 kv
__device__ __half g_xf [(size_t)MROWS * CDIM];       // fp16 attn output
__device__ __half g_wqf[CDIM * CDIM];
__device__ __half g_wkf[2 * CDIM * CDIM];
__device__ __half g_wpf[CDIM * CDIM];
__device__ __half g_attnh[BHn * HDd * HDd];          // fp16 softmaxed attn
__device__ float g_part[SPLIT * BHn * HDd * HDd];
__device__ float g_qsq [SSPLIT * BHn * HDd];
__device__ float g_ksq [SSPLIT * BHn * HDd];
__device__ float g_inq [BHn * HDd];                  // 1/max(||q_d||,eps)
__device__ float g_ink [BHn * HDd];                  // 1/max(||k_e||,eps)

// ---------------- helpers ----------------
__device__ __forceinline__ uint32_t s2u(const void* p) {
    uint32_t a;
    asm("{ .reg .u64 t; cvta.to.shared.u64 t, %1; cvt.u32.u64 %0, t; }" : "=r"(a) : "l"(p));
    return a;
}
__device__ __forceinline__ void cp16(uint32_t dst, const void* src) {
    asm volatile("cp.async.cg.shared.global [%0], [%1], 16;" :: "r"(dst), "l"(src));
}
__device__ __forceinline__ void cp_commit() { asm volatile("cp.async.commit_group;"); }
template <int N>
__device__ __forceinline__ void cp_wait() { asm volatile("cp.async.wait_group %0;" :: "n"(N)); }

__device__ __forceinline__ void ldsm4(uint32_t& r0, uint32_t& r1, uint32_t& r2, uint32_t& r3,
                                      uint32_t addr) {
    asm volatile("ldmatrix.sync.aligned.m8n8.x4.shared.b16 {%0,%1,%2,%3}, [%4];"
                 : "=r"(r0), "=r"(r1), "=r"(r2), "=r"(r3) : "r"(addr));
}
__device__ __forceinline__ void ldsm4t(uint32_t& r0, uint32_t& r1, uint32_t& r2, uint32_t& r3,
                                       uint32_t addr) {
    asm volatile("ldmatrix.sync.aligned.m8n8.x4.trans.shared.b16 {%0,%1,%2,%3}, [%4];"
                 : "=r"(r0), "=r"(r1), "=r"(r2), "=r"(r3) : "r"(addr));
}
__device__ __forceinline__ void mma_f16(float& c0, float& c1, float& c2, float& c3,
                                        uint32_t a0, uint32_t a1, uint32_t a2, uint32_t a3,
                                        uint32_t b0, uint32_t b1) {
    asm volatile(
        "mma.sync.aligned.m16n8k16.row.col.f32.f16.f16.f32 "
        "{%0,%1,%2,%3}, {%4,%5,%6,%7}, {%8,%9}, {%0,%1,%2,%3};"
        : "+f"(c0), "+f"(c1), "+f"(c2), "+f"(c3)
        : "r"(a0), "r"(a1), "r"(a2), "r"(a3), "r"(b0), "r"(b1));
}

// ============================================================
// GEMM core config
// ============================================================
#define PIPE      3
#define TILE_B    16384
#define STAGE_B   (2 * TILE_B)
#define GSMEM     (PIPE * STAGE_B)     // 98304
#define NKT       12
#define NT1       6

// ============================================================
// Fused projection GEMM: job1 = q (Nc=768), job2 = kv (Nc=1536)
// ============================================================
__global__ __launch_bounds__(256, 2) void gemm_proj(
    const __half* __restrict__ A1, const __half* __restrict__ B1, __half* __restrict__ O1,
    const __half* __restrict__ A2, const __half* __restrict__ B2, __half* __restrict__ O2)
{
    extern __shared__ __align__(1024) char smem[];
    const uint32_t sbase = s2u(smem);

    const bool j2 = blockIdx.x >= NT1;
    const __half* __restrict__ A = j2 ? A2 : A1;
    const __half* __restrict__ B = j2 ? B2 : B1;
    __half* __restrict__ O = j2 ? O2 : O1;
    const int Nc = j2 ? 2 * CDIM : CDIM;
    const int n0 = (j2 ? (int)blockIdx.x - NT1 : (int)blockIdx.x) * 128;
    const int m0 = blockIdx.y * 128;

    const int tid  = threadIdx.x;
    const int lane = tid & 31;
    const int wid  = tid >> 5;
    const int wm = (wid >> 2) * 64;
    const int wn = (wid & 3) * 32;

    const uint32_t a_row   = wm + (lane & 15);
    const uint32_t a_swz   = (lane & 7) * 16;
    const uint32_t a_xhalf = (lane >> 4) * 16;
    const int l8 = lane & 7;
    const int lg = lane >> 3;
    const uint32_t b_row_base = wn + (lg >> 1) * 8 + l8;
    const uint32_t b_khalf    = (lg & 1) * 16;
    const uint32_t b_swz      = l8 * 16;

    float acc[4][4][4];
    #pragma unroll
    for (int i = 0; i < 4; i++)
        #pragma unroll
        for (int j = 0; j < 4; j++)
            #pragma unroll
            for (int c = 0; c < 4; c++) acc[i][j][c] = 0.f;

    auto issue = [&](int kt, int slot) {
        const int k0 = kt * 64;
        const uint32_t sA = sbase + slot * STAGE_B;
        const uint32_t sB = sA + TILE_B;
        #pragma unroll
        for (int i = 0; i < 8; i++) {
            const int c = tid + i * 256;
            const int row = (c >> 3) & 127;
            const int x16 = c & 7;
            const uint32_t off = (uint32_t)(row * 128 + ((x16 * 16) ^ ((row & 7) * 16)));
            if (c < 1024) cp16(sA + off, A + (size_t)(m0 + row) * CDIM + k0 + x16 * 8);
            else          cp16(sB + off, B + (size_t)(n0 + row) * CDIM + k0 + x16 * 8);
        }
        cp_commit();
    };

    issue(0, 0); issue(1, 1);

    for (int kt = 0; kt < NKT; kt++) {
        const int slot = kt % 3;
        cp_wait<PIPE - 2>();
        __syncthreads();
        if (kt + 2 < NKT) issue(kt + 2, (kt + 2) % 3);

        const uint32_t sA = sbase + slot * STAGE_B;
        const uint32_t sB = sA + TILE_B;

        #pragma unroll
        for (int ks = 0; ks < 4; ks++) {
            uint32_t af[4][4];
            #pragma unroll
            for (int mi = 0; mi < 4; mi++) {
                const uint32_t addr = sA + (a_row + mi * 16) * 128
                                    + ((ks * 32 + a_xhalf) ^ a_swz);
                ldsm4(af[mi][0], af[mi][1], af[mi][2], af[mi][3], addr);
            }
            uint32_t bf[4][2];
            #pragma unroll
            for (int p = 0; p < 2; p++) {
                const uint32_t addr = sB + (b_row_base + p * 16) * 128
                                    + ((ks * 32 + b_khalf) ^ b_swz);
                ldsm4(bf[2*p][0], bf[2*p][1], bf[2*p+1][0], bf[2*p+1][1], addr);
            }
            #pragma unroll
            for (int mi = 0; mi < 4; mi++)
                #pragma unroll
                for (int nj = 0; nj < 4; nj++)
                    mma_f16(acc[mi][nj][0], acc[mi][nj][1], acc[mi][nj][2], acc[mi][nj][3],
                            af[mi][0], af[mi][1], af[mi][2], af[mi][3],
                            bf[nj][0], bf[nj][1]);
        }
    }

    #pragma unroll
    for (int mi = 0; mi < 4; mi++) {
        const int r0 = m0 + wm + mi * 16 + (lane >> 2);
        #pragma unroll
        for (int nj = 0; nj < 4; nj++) {
            const int c = n0 + wn + nj * 8 + (lane & 3) * 2;
            __half2 v0 = { __float2half_rn(acc[mi][nj][0]), __float2half_rn(acc[mi][nj][1]) };
            __half2 v1 = { __float2half_rn(acc[mi][nj][2]), __float2half_rn(acc[mi][nj][3]) };
            *reinterpret_cast<__half2*>(O + (size_t)r0 * Nc + c) = v0;
            *reinterpret_cast<__half2*>(O + (size_t)(r0 + 8) * Nc + c) = v1;
        }
    }
}

// ============================================================
// Final GEMM: out = x @ Wp^T + bias, fp32 output
// ============================================================
__global__ __launch_bounds__(256, 2) void gemm_out(
    const __half* __restrict__ A, const __half* __restrict__ B,
    const float* __restrict__ bias, float* __restrict__ Cout)
{
    extern __shared__ __align__(1024) char smem[];
    const uint32_t sbase = s2u(smem);
    const int Nc = CDIM;

    const int tid  = threadIdx.x;
    const int lane = tid & 31;
    const int wid  = tid >> 5;
    const int m0 = blockIdx.y * 128;
    const int n0 = blockIdx.x * 128;
    const int wm = (wid >> 2) * 64;
    const int wn = (wid & 3) * 32;

    const uint32_t a_row   = wm + (lane & 15);
    const uint32_t a_swz   = (lane & 7) * 16;
    const uint32_t a_xhalf = (lane >> 4) * 16;
    const int l8 = lane & 7;
    const int lg = lane >> 3;
    const uint32_t b_row_base = wn + (lg >> 1) * 8 + l8;
    const uint32_t b_khalf    = (lg & 1) * 16;
    const uint32_t b_swz      = l8 * 16;

    float acc[4][4][4];
    #pragma unroll
    for (int i = 0; i < 4; i++)
        #pragma unroll
        for (int j = 0; j < 4; j++)
            #pragma unroll
            for (int c = 0; c < 4; c++) acc[i][j][c] = 0.f;

    auto issue = [&](int kt, int slot) {
        const int k0 = kt * 64;
        const uint32_t sA = sbase + slot * STAGE_B;
        const uint32_t sB = sA + TILE_B;
        #pragma unroll
        for (int i = 0; i < 8; i++) {
            const int c = tid + i * 256;
            const int row = (c >> 3) & 127;
            const int x16 = c & 7;
            const uint32_t off = (uint32_t)(row * 128 + ((x16 * 16) ^ ((row & 7) * 16)));
            if (c < 1024) cp16(sA + off, A + (size_t)(m0 + row) * CDIM + k0 + x16 * 8);
            else          cp16(sB + off, B + (size_t)(n0 + row) * CDIM + k0 + x16 * 8);
        }
        cp_commit();
    };

    issue(0, 0); issue(1, 1);

    for (int kt = 0; kt < NKT; kt++) {
        const int slot = kt % 3;
        cp_wait<PIPE - 2>();
        __syncthreads();
        if (kt + 2 < NKT) issue(kt + 2, (kt + 2) % 3);

        const uint32_t sA = sbase + slot * STAGE_B;
        const uint32_t sB = sA + TILE_B;

        #pragma unroll
        for (int ks = 0; ks < 4; ks++) {
            uint32_t af[4][4];
            #pragma unroll
            for (int mi = 0; mi < 4; mi++) {
                const uint32_t addr = sA + (a_row + mi * 16) * 128
                                    + ((ks * 32 + a_xhalf) ^ a_swz);
                ldsm4(af[mi][0], af[mi][1], af[mi][2], af[mi][3], addr);
            }
            uint32_t bf[4][2];
            #pragma unroll
            for (int p = 0; p < 2; p++) {
                const uint32_t addr = sB + (b_row_base + p * 16) * 128
                                    + ((ks * 32 + b_khalf) ^ b_swz);
                ldsm4(bf[2*p][0], bf[2*p][1], bf[2*p+1][0], bf[2*p+1][1], addr);
            }
            #pragma unroll
            for (int mi = 0; mi < 4; mi++)
                #pragma unroll
                for (int nj = 0; nj < 4; nj++)
                    mma_f16(acc[mi][nj][0], acc[mi][nj][1], acc[mi][nj][2], acc[mi][nj][3],
                            af[mi][0], af[mi][1], af[mi][2], af[mi][3],
                            bf[nj][0], bf[nj][1]);
        }
    }

    #pragma unroll
    for (int mi = 0; mi < 4; mi++) {
        const int r0 = m0 + wm + mi * 16 + (lane >> 2);
        #pragma unroll
        for (int nj = 0; nj < 4; nj++) {
            const int c = n0 + wn + nj * 8 + (lane & 3) * 2;
            const float b0 = bias[c], b1 = bias[c + 1];
            float2 v0 = { acc[mi][nj][0] + b0, acc[mi][nj][1] + b1 };
            float2 v1 = { acc[mi][nj][2] + b0, acc[mi][nj][3] + b1 };
            *reinterpret_cast<float2*>(Cout + (size_t)r0 * Nc + c) = v0;
            *reinterpret_cast<float2*>(Cout + (size_t)(r0 + 8) * Nc + c) = v1;
        }
    }
}

// ============================================================
// fp32 -> fp16 convert, both inputs in one launch
// ============================================================
__global__ __launch_bounds__(256) void tofp16_dual(
    const float* __restrict__ in0, __half* __restrict__ out0,
    const float* __restrict__ in1, __half* __restrict__ out1, int n4)
{
    const int i = blockIdx.x * 256 + threadIdx.x;
    if (i >= n4) return;
    const float* in = blockIdx.y ? in1 : in0;
    __half* out = blockIdx.y ? out1 : out0;
    const float4 v = reinterpret_cast<const float4*>(in)[i];
    __half2 h0 = { __float2half_rn(v.x), __float2half_rn(v.y) };
    __half2 h1 = { __float2half_rn(v.z), __float2half_rn(v.w) };
    reinterpret_cast<__half2*>(out)[i * 2 + 0] = h0;
    reinterpret_cast<__half2*>(out)[i * 2 + 1] = h1;
}

// ============================================================
// Fused weight transpose
// ============================================================
__global__ __launch_bounds__(256) void tfp16_all(
    const float* __restrict__ Wq, const float* __restrict__ Wkv,
    const float* __restrict__ Wp,
    __half* __restrict__ Tq, __half* __restrict__ Tk, __half* __restrict__ Tp)
{
    __shared__ float t[32][33];
    const int bx = blockIdx.x;
    const float* W; __half* T; int Nc, nt0;
    if (bx < 24)      { W = Wq;  T = Tq; Nc = CDIM;     nt0 = 0; }
    else if (bx < 72) { W = Wkv; T = Tk; Nc = 2 * CDIM; nt0 = 24; }
    else              { W = Wp;  T = Tp; Nc = CDIM;     nt0 = 72; }
    const int n0 = (bx - nt0) * 32, k0 = blockIdx.y * 32;
    const int tx = threadIdx.x & 31, ty = threadIdx.x >> 5;
    #pragma unroll
    for (int i = 0; i < 32; i += 8)
        t[ty + i][tx] = W[(size_t)(k0 + ty + i) * Nc + n0 + tx];
    __syncthreads();
    #pragma unroll
    for (int i = 0; i < 32; i += 8)
        T[(size_t)(n0 + ty + i) * CDIM + k0 + tx] = __float2half_rn(t[tx][ty + i]);
}

// ============================================================
// Column sum-of-squares partials: 64-way token split
// grid (3, Bq, SSPLIT), 256 thr; each block: 64 tokens x 256 cols
// ============================================================
__global__ __launch_bounds__(256) void sumsq_kernel()
{
    const int c = blockIdx.x * 256 + threadIdx.x;
    const int b = blockIdx.y;
    const int sp = blockIdx.z;
    const int n0 = sp * (NTOK / SSPLIT);

    const __half* qp = g_qh  + (size_t)(b * NTOK + n0) * CDIM + c;
    const __half* kp = g_kvh + (size_t)(b * NTOK + n0) * (2 * CDIM) + c;
    float sq = 0.f, sk = 0.f;
    #pragma unroll 8
    for (int n = 0; n < NTOK / SSPLIT; n++) {
        const float qv = __half2float(qp[(size_t)n * CDIM]);
        const float kv = __half2float(kp[(size_t)n * 2 * CDIM]);
        sq += qv * qv;
        sk += kv * kv;
    }
    const int bh = b * Hh + c / HDd;
    const int d  = c % HDd;
    const int po = sp * BHn + bh;
    g_qsq[po * HDd + d] = sq;
    g_ksq[po * HDd + d] = sk;
}

// ============================================================
// Reduce 64 partials -> reciprocal norms
// grid BHn, 96 threads
// ============================================================
__global__ __launch_bounds__(96) void norm_reduce()
{
    const int bh = blockIdx.x;
    const int d  = threadIdx.x;
    float sq = 0.f, sk = 0.f;
    #pragma unroll 8
    for (int p = 0; p < SSPLIT; p++) {
        sq += g_qsq[(p * BHn + bh) * HDd + d];
        sk += g_ksq[(p * BHn + bh) * HDd + d];
    }
    g_inq[bh * HDd + d] = 1.f / fmaxf(sqrtf(sq), EPSN);
    g_ink[bh * HDd + d] = 1.f / fmaxf(sqrtf(sk), EPSN);
}

// ============================================================
// Tensor-core Gram partials: part[d,e] = sum_n q[n,d] k[n,e]
// ============================================================
#define GPITCH 104
#define GNI    32

__global__ __launch_bounds__(192) void gram_tc()
{
    __shared__ __half qs[3][16][GPITCH];
    __shared__ __half ks[3][16][GPITCH];

    const int bh = blockIdx.x;
    const int b  = bh >> 3;
    const int h  = bh & 7;
    const int sp = blockIdx.y;
    const int nbase = b * NTOK + sp * (NTOK / SPLIT);

    const int tid  = threadIdx.x;
    const int lane = tid & 31;
    const int w    = tid >> 5;
    const int e0   = w * 16;

    const __half* qbase = g_qh  + (size_t)nbase * CDIM + h * HDd;
    const __half* kbase = g_kvh + (size_t)nbase * (2 * CDIM) + h * HDd;

    const int lrow = tid / 12;
    const int lx   = tid % 12;

    auto issue = [&](int it, int s) {
        const int n0 = it * 16;
        cp16(s2u(&qs[s][lrow][lx * 8]),
             qbase + (size_t)(n0 + lrow) * CDIM + lx * 8);
        cp16(s2u(&ks[s][lrow][lx * 8]),
             kbase + (size_t)(n0 + lrow) * (2 * CDIM) + lx * 8);
        cp_commit();
    };

    const uint32_t a_row = (lane & 7) + ((lane >> 4) & 1) * 8;
    const uint32_t a_coff = ((lane >> 3) & 1) * 8;
    const uint32_t b_row = (lane & 7) + ((lane >> 3) & 1) * 8;
    const uint32_t b_coff = ((lane >> 4) & 1) * 8;

    float acc[6][2][4];
    #pragma unroll
    for (int i = 0; i < 6; i++)
        #pragma unroll
        for (int j = 0; j < 2; j++)
            #pragma unroll
            for (int c = 0; c < 4; c++) acc[i][j][c] = 0.f;

    issue(0, 0); issue(1, 1);

    for (int it = 0; it < GNI; it++) {
        const int s = it % 3;
        if (it + 1 < GNI) cp_wait<1>(); else cp_wait<0>();
        __syncthreads();
        if (it + 2 < GNI) issue(it + 2, (it + 2) % 3);

        uint32_t bf[4];
        ldsm4t(bf[0], bf[1], bf[2], bf[3], s2u(&ks[s][b_row][e0 + b_coff]));
        uint32_t af[6][4];
        #pragma unroll
        for (int mi = 0; mi < 6; mi++)
            ldsm4t(af[mi][0], af[mi][1], af[mi][2], af[mi][3],
                   s2u(&qs[s][a_row][mi * 16 + a_coff]));
        #pragma unroll
        for (int mi = 0; mi < 6; mi++)
            #pragma unroll
            for (int nj = 0; nj < 2; nj++)
                mma_f16(acc[mi][nj][0], acc[mi][nj][1], acc[mi][nj][2], acc[mi][nj][3],
                        af[mi][0], af[mi][1], af[mi][2], af[mi][3],
                        bf[nj * 2], bf[nj * 2 + 1]);
    }

    float* op = g_part + (size_t)(sp * BHn + bh) * (HDd * HDd);
    #pragma unroll
    for (int mi = 0; mi < 6; mi++) {
        const int d = mi * 16 + (lane >> 2);
        #pragma unroll
        for (int nj = 0; nj < 2; nj++) {
            const int e = e0 + nj * 8 + (lane & 3) * 2;
            float2 v0 = { acc[mi][nj][0], acc[mi][nj][1] };
            float2 v1 = { acc[mi][nj][2], acc[mi][nj][3] };
            *reinterpret_cast<float2*>(op + d * HDd + e) = v0;
            *reinterpret_cast<float2*>(op + (d + 8) * HDd + e) = v1;
        }
    }
}

// ============================================================
// softmax -> fp16 attn (uses precomputed reciprocal norms)
// ============================================================
__global__ __launch_bounds__(96) void softmax2_kernel()
{
    const int bh = blockIdx.x;
    const int d  = blockIdx.y;
    const int e  = threadIdx.x;
    const int w  = e >> 5, lane = e & 31;

    __shared__ float s_m[3], s_s[3];

    float sp = 0.f;
    #pragma unroll
    for (int p = 0; p < SPLIT; p++)
        sp += g_part[(size_t)(p * BHn + bh) * (HDd * HDd) + d * HDd + e];

    const float a = sp * SCALE_F * g_inq[bh * HDd + d] * g_ink[bh * HDd + e];

    float m = a;
    #pragma unroll
    for (int o = 16; o > 0; o >>= 1) m = fmaxf(m, __shfl_xor_sync(0xffffffffu, m, o));
    if (lane == 0) s_m[w] = m;
    __syncthreads();
    m = fmaxf(fmaxf(s_m[0], s_m[1]), s_m[2]);

    const float ex = __expf(a - m);
    float s = ex;
    #pragma unroll
    for (int o = 16; o > 0; o >>= 1) s += __shfl_xor_sync(0xffffffffu, s, o);
    if (lane == 0) s_s[w] = s;
    __syncthreads();
    s = s_s[0] + s_s[1] + s_s[2];

    g_attnh[(size_t)bh * (HDd * HDd) + d * HDd + e] = __float2half_rn(ex / s);
}

// ============================================================
// Tensor-core AV: x[n,d] = sum_e attn[d,e] v[n,e]
// ============================================================
#define APITCH 104

__global__ __launch_bounds__(128) void av_tc()
{
    __shared__ __half vs_[128][APITCH];
    __shared__ __half as_[96][APITCH];

    const int tile = blockIdx.x;
    const int h    = blockIdx.y;
    const int b    = tile >> 5;
    const int bh   = b * Hh + h;
    const int row0 = tile * 128;

    const int tid  = threadIdx.x;
    const int lane = tid & 31;
    const int w    = tid >> 5;

    const __half* vsrc = g_kvh + (size_t)row0 * (2 * CDIM) + CDIM + h * HDd;
    const __half* asrc = g_attnh + (size_t)bh * (HDd * HDd);
    #pragma unroll
    for (int i = 0; i < 12; i++) {
        const int c = tid + i * 128;
        const int r = c / 12, x = c % 12;
        cp16(s2u(&vs_[r][x * 8]), vsrc + (size_t)r * (2 * CDIM) + x * 8);
    }
    #pragma unroll
    for (int i = 0; i < 9; i++) {
        const int c = tid + i * 128;
        const int r = c / 12, x = c % 12;
        cp16(s2u(&as_[r][x * 8]), asrc + r * HDd + x * 8);
    }
    cp_commit();
    cp_wait<0>();
    __syncthreads();

    const uint32_t v_row = w * 32 + (lane & 15);
    const uint32_t v_coff = (lane >> 4) * 8;
    const uint32_t b_row = (lane & 7) + ((lane >> 4) & 1) * 8;
    const uint32_t b_coff = ((lane >> 3) & 1) * 8;

    float acc[2][12][4];
    #pragma unroll
    for (int i = 0; i < 2; i++)
        #pragma unroll
        for (int j = 0; j < 12; j++)
            #pragma unroll
            for (int c = 0; c < 4; c++) acc[i][j][c] = 0.f;

    #pragma unroll
    for (int ech = 0; ech < 6; ech++) {
        uint32_t af[2][4];
        #pragma unroll
        for (int mi = 0; mi < 2; mi++)
            ldsm4(af[mi][0], af[mi][1], af[mi][2], af[mi][3],
                  s2u(&vs_[v_row + mi * 16][ech * 16 + v_coff]));
        uint32_t bf[12][2];
        #pragma unroll
        for (int p = 0; p < 6; p++)
            ldsm4(bf[2*p][0], bf[2*p][1], bf[2*p+1][0], bf[2*p+1][1],
                  s2u(&as_[p * 16 + b_row][ech * 16 + b_coff]));
        #pragma unroll
        for (int mi = 0; mi < 2; mi++)
            #pragma unroll
            for (int nj = 0; nj < 12; nj++)
                mma_f16(acc[mi][nj][0], acc[mi][nj][1], acc[mi][nj][2], acc[mi][nj][3],
                        af[mi][0], af[mi][1], af[mi][2], af[mi][3],
                        bf[nj][0], bf[nj][1]);
    }

    #pragma unroll
    for (int mi = 0; mi < 2; mi++) {
        const int tok = row0 + w * 32 + mi * 16 + (lane >> 2);
        #pragma unroll
        for (int nj = 0; nj < 12; nj++) {
            const int d = nj * 8 + (lane & 3) * 2;
            __half2 v0 = { __float2half_rn(acc[mi][nj][0]), __float2half_rn(acc[mi][nj][1]) };
            __half2 v1 = { __float2half_rn(acc[mi][nj][2]), __float2half_rn(acc[mi][nj][3]) };
            *reinterpret_cast<__half2*>(g_xf + (size_t)tok * CDIM + h * HDd + d) = v0;
            *reinterpret_cast<__half2*>(g_xf + (size_t)(tok + 8) * CDIM + h * HDd + d) = v1;
        }
    }
}

// ============================================================
extern "C" void kernel_launch(void* const* d_in, const int* in_sizes, int n_in,
                              void* d_out, int out_size)
{
    const float* cx  = (const float*)d_in[0];
    const float* dx  = (const float*)d_in[1];
    const float* Wq  = (const float*)d_in[2];
    const float* Wkv = (const float*)d_in[3];
    const float* Wp  = (const float*)d_in[4];
    const float* bp  = (const float*)d_in[5];
    float* out = (float*)d_out;

    cudaFuncSetAttribute(gemm_proj, cudaFuncAttributeMaxDynamicSharedMemorySize, GSMEM);
    cudaFuncSetAttribute(gemm_out,  cudaFuncAttributeMaxDynamicSharedMemorySize, GSMEM);

    __half *a1f, *a2f, *xf, *wqf, *wkf, *wpf, *qh, *kvh;
    cudaGetSymbolAddress((void**)&a1f, g_a1f);
    cudaGetSymbolAddress((void**)&a2f, g_a2f);
    cudaGetSymbolAddress((void**)&xf,  g_xf);
    cudaGetSymbolAddress((void**)&wqf, g_wqf);
    cudaGetSymbolAddress((void**)&wkf, g_wkf);
    cudaGetSymbolAddress((void**)&wpf, g_wpf);
    cudaGetSymbolAddress((void**)&qh,  g_qh);
    cudaGetSymbolAddress((void**)&kvh, g_kvh);

    const int n4 = MROWS * CDIM / 4;
    tofp16_dual<<<dim3((n4 + 255) / 256, 2), 256>>>(cx, a1f, dx, a2f, n4);
    tfp16_all<<<dim3(96, 24), 256>>>(Wq, Wkv, Wp, wqf, wkf, wpf);

    // q and kv projections in one launch
    gemm_proj<<<dim3(18, MROWS / 128), 256, GSMEM>>>(a1f, wqf, qh, a2f, wkf, kvh);

    // attention core
    sumsq_kernel<<<dim3(3, Bq, SSPLIT), 256>>>();
    norm_reduce<<<BHn, 96>>>();
    gram_tc<<<dim3(BHn, SPLIT), 192>>>();
    softmax2_kernel<<<dim3(BHn, HDd), 96>>>();
    av_tc<<<dim3(128, Hh), 128>>>();

    // out = x @ Wproj + b
    gemm_out<<<dim3(CDIM / 128, MROWS / 128), 256, GSMEM>>>(xf, wpf, bp, out);
}

// round 9
// speedup vs baseline: 7.2809x; 1.0647x over previous
#include <cuda_runtime.h>
#include <cuda_fp16.h>
#include <cstdint>
#include <cstddef>

// ---------------- problem constants ----------------
#define Bq    4
#define NTOK  4096
#define CDIM  768
#define Hh    8
#define HDd   96
#define MROWS (Bq * NTOK)          // 16384
#define SPLIT 16
#define BHn   (Bq * Hh)            // 32
#define MT    (MROWS / 128)        // 128 m-tiles
#define SCALE_F 0.10206207261596577f
#define EPSN 1e-12f

// ---------------- scratch (device globals) ----------------
__device__ __half g_a1f[(size_t)MROWS * CDIM];       // fp16 context_x
__device__ __half g_a2f[(size_t)MROWS * CDIM];       // fp16 depth_x
__device__ __half g_qh [(size_t)MROWS * CDIM];       // fp16 q
__device__ __half g_kvh[(size_t)MROWS * 2 * CDIM];   // fp16 kv
__device__ __half g_xf [(size_t)MROWS * CDIM];       // fp16 attn output
__device__ __half g_wqf[CDIM * CDIM];
__device__ __half g_wkf[2 * CDIM * CDIM];
__device__ __half g_wpf[CDIM * CDIM];
__device__ __half g_attnh[BHn * HDd * HDd];          // fp16 softmaxed attn
__device__ float g_part[SPLIT * BHn * HDd * HDd];
__device__ float g_qsqp[MT * CDIM];                  // per-mtile col sumsq (q)
__device__ float g_ksqp[MT * CDIM];                  // per-mtile col sumsq (k)
__device__ float g_inq [BHn * HDd];                  // 1/max(||q_d||,eps)
__device__ float g_ink [BHn * HDd];                  // 1/max(||k_e||,eps)

// ---------------- helpers ----------------
__device__ __forceinline__ uint32_t s2u(const void* p) {
    uint32_t a;
    asm("{ .reg .u64 t; cvta.to.shared.u64 t, %1; cvt.u32.u64 %0, t; }" : "=r"(a) : "l"(p));
    return a;
}
__device__ __forceinline__ void cp16(uint32_t dst, const void* src) {
    asm volatile("cp.async.cg.shared.global [%0], [%1], 16;" :: "r"(dst), "l"(src));
}
__device__ __forceinline__ void cp_commit() { asm volatile("cp.async.commit_group;"); }
template <int N>
__device__ __forceinline__ void cp_wait() { asm volatile("cp.async.wait_group %0;" :: "n"(N)); }

__device__ __forceinline__ void ldsm4(uint32_t& r0, uint32_t& r1, uint32_t& r2, uint32_t& r3,
                                      uint32_t addr) {
    asm volatile("ldmatrix.sync.aligned.m8n8.x4.shared.b16 {%0,%1,%2,%3}, [%4];"
                 : "=r"(r0), "=r"(r1), "=r"(r2), "=r"(r3) : "r"(addr));
}
__device__ __forceinline__ void ldsm4t(uint32_t& r0, uint32_t& r1, uint32_t& r2, uint32_t& r3,
                                       uint32_t addr) {
    asm volatile("ldmatrix.sync.aligned.m8n8.x4.trans.shared.b16 {%0,%1,%2,%3}, [%4];"
                 : "=r"(r0), "=r"(r1), "=r"(r2), "=r"(r3) : "r"(addr));
}
__device__ __forceinline__ void mma_f16(float& c0, float& c1, float& c2, float& c3,
                                        uint32_t a0, uint32_t a1, uint32_t a2, uint32_t a3,
                                        uint32_t b0, uint32_t b1) {
    asm volatile(
        "mma.sync.aligned.m16n8k16.row.col.f32.f16.f16.f32 "
        "{%0,%1,%2,%3}, {%4,%5,%6,%7}, {%8,%9}, {%0,%1,%2,%3};"
        : "+f"(c0), "+f"(c1), "+f"(c2), "+f"(c3)
        : "r"(a0), "r"(a1), "r"(a2), "r"(a3), "r"(b0), "r"(b1));
}

// ============================================================
// GEMM core config
// ============================================================
#define PIPE      3
#define TILE_B    16384
#define STAGE_B   (2 * TILE_B)
#define GSMEM     (PIPE * STAGE_B)     // 98304
#define NKT       12
#define NT1       6

// ============================================================
// Fused projection GEMM + column sumsq partials
// job1 = q (Nc=768), job2 = kv (Nc=1536)
// ============================================================
__global__ __launch_bounds__(256, 2) void gemm_proj(
    const __half* __restrict__ A1, const __half* __restrict__ B1, __half* __restrict__ O1,
    const __half* __restrict__ A2, const __half* __restrict__ B2, __half* __restrict__ O2)
{
    extern __shared__ __align__(1024) char smem[];
    const uint32_t sbase = s2u(smem);

    const bool j2 = blockIdx.x >= NT1;
    const __half* __restrict__ A = j2 ? A2 : A1;
    const __half* __restrict__ B = j2 ? B2 : B1;
    __half* __restrict__ O = j2 ? O2 : O1;
    const int Nc = j2 ? 2 * CDIM : CDIM;
    const int n0 = (j2 ? (int)blockIdx.x - NT1 : (int)blockIdx.x) * 128;
    const int m0 = blockIdx.y * 128;

    const int tid  = threadIdx.x;
    const int lane = tid & 31;
    const int wid  = tid >> 5;
    const int wm = (wid >> 2) * 64;
    const int wn = (wid & 3) * 32;

    const uint32_t a_row   = wm + (lane & 15);
    const uint32_t a_swz   = (lane & 7) * 16;
    const uint32_t a_xhalf = (lane >> 4) * 16;
    const int l8 = lane & 7;
    const int lg = lane >> 3;
    const uint32_t b_row_base = wn + (lg >> 1) * 8 + l8;
    const uint32_t b_khalf    = (lg & 1) * 16;
    const uint32_t b_swz      = l8 * 16;

    float acc[4][4][4];
    #pragma unroll
    for (int i = 0; i < 4; i++)
        #pragma unroll
        for (int j = 0; j < 4; j++)
            #pragma unroll
            for (int c = 0; c < 4; c++) acc[i][j][c] = 0.f;

    auto issue = [&](int kt, int slot) {
        const int k0 = kt * 64;
        const uint32_t sA = sbase + slot * STAGE_B;
        const uint32_t sB = sA + TILE_B;
        #pragma unroll
        for (int i = 0; i < 8; i++) {
            const int c = tid + i * 256;
            const int row = (c >> 3) & 127;
            const int x16 = c & 7;
            const uint32_t off = (uint32_t)(row * 128 + ((x16 * 16) ^ ((row & 7) * 16)));
            if (c < 1024) cp16(sA + off, A + (size_t)(m0 + row) * CDIM + k0 + x16 * 8);
            else          cp16(sB + off, B + (size_t)(n0 + row) * CDIM + k0 + x16 * 8);
        }
        cp_commit();
    };

    issue(0, 0); issue(1, 1);

    for (int kt = 0; kt < NKT; kt++) {
        const int slot = kt % 3;
        cp_wait<PIPE - 2>();
        __syncthreads();
        if (kt + 2 < NKT) issue(kt + 2, (kt + 2) % 3);

        const uint32_t sA = sbase + slot * STAGE_B;
        const uint32_t sB = sA + TILE_B;

        #pragma unroll
        for (int ks = 0; ks < 4; ks++) {
            uint32_t af[4][4];
            #pragma unroll
            for (int mi = 0; mi < 4; mi++) {
                const uint32_t addr = sA + (a_row + mi * 16) * 128
                                    + ((ks * 32 + a_xhalf) ^ a_swz);
                ldsm4(af[mi][0], af[mi][1], af[mi][2], af[mi][3], addr);
            }
            uint32_t bf[4][2];
            #pragma unroll
            for (int p = 0; p < 2; p++) {
                const uint32_t addr = sB + (b_row_base + p * 16) * 128
                                    + ((ks * 32 + b_khalf) ^ b_swz);
                ldsm4(bf[2*p][0], bf[2*p][1], bf[2*p+1][0], bf[2*p+1][1], addr);
            }
            #pragma unroll
            for (int mi = 0; mi < 4; mi++)
                #pragma unroll
                for (int nj = 0; nj < 4; nj++)
                    mma_f16(acc[mi][nj][0], acc[mi][nj][1], acc[mi][nj][2], acc[mi][nj][3],
                            af[mi][0], af[mi][1], af[mi][2], af[mi][3],
                            bf[nj][0], bf[nj][1]);
        }
    }

    #pragma unroll
    for (int mi = 0; mi < 4; mi++) {
        const int r0 = m0 + wm + mi * 16 + (lane >> 2);
        #pragma unroll
        for (int nj = 0; nj < 4; nj++) {
            const int c = n0 + wn + nj * 8 + (lane & 3) * 2;
            __half2 v0 = { __float2half_rn(acc[mi][nj][0]), __float2half_rn(acc[mi][nj][1]) };
            __half2 v1 = { __float2half_rn(acc[mi][nj][2]), __float2half_rn(acc[mi][nj][3]) };
            *reinterpret_cast<__half2*>(O + (size_t)r0 * Nc + c) = v0;
            *reinterpret_cast<__half2*>(O + (size_t)(r0 + 8) * Nc + c) = v1;
        }
    }

    // ---- fused column sum-of-squares (q columns, or k columns of kv) ----
    const bool need_sq = (!j2) || (n0 < CDIM);
    if (need_sq) {
        float* colsq = reinterpret_cast<float*>(smem);   // [2][128]
        __syncthreads();       // all warps done with smem stages
        #pragma unroll
        for (int nj = 0; nj < 4; nj++) {
            float s0 = 0.f, s1 = 0.f;
            #pragma unroll
            for (int mi = 0; mi < 4; mi++) {
                s0 += acc[mi][nj][0] * acc[mi][nj][0] + acc[mi][nj][2] * acc[mi][nj][2];
                s1 += acc[mi][nj][1] * acc[mi][nj][1] + acc[mi][nj][3] * acc[mi][nj][3];
            }
            #pragma unroll
            for (int o = 4; o < 32; o <<= 1) {
                s0 += __shfl_xor_sync(0xffffffffu, s0, o);
                s1 += __shfl_xor_sync(0xffffffffu, s1, o);
            }
            if (lane < 4) {
                const int col = wn + nj * 8 + lane * 2;
                colsq[(wm >> 6) * 128 + col]     = s0;
                colsq[(wm >> 6) * 128 + col + 1] = s1;
            }
        }
        __syncthreads();
        if (tid < 128) {
            const float tot = colsq[tid] + colsq[128 + tid];
            float* dst = j2 ? g_ksqp : g_qsqp;
            dst[(size_t)blockIdx.y * CDIM + n0 + tid] = tot;
        }
    }
}

// ============================================================
// Final GEMM: out = x @ Wp^T + bias, fp32 output
// ============================================================
__global__ __launch_bounds__(256, 2) void gemm_out(
    const __half* __restrict__ A, const __half* __restrict__ B,
    const float* __restrict__ bias, float* __restrict__ Cout)
{
    extern __shared__ __align__(1024) char smem[];
    const uint32_t sbase = s2u(smem);
    const int Nc = CDIM;

    const int tid  = threadIdx.x;
    const int lane = tid & 31;
    const int wid  = tid >> 5;
    const int m0 = blockIdx.y * 128;
    const int n0 = blockIdx.x * 128;
    const int wm = (wid >> 2) * 64;
    const int wn = (wid & 3) * 32;

    const uint32_t a_row   = wm + (lane & 15);
    const uint32_t a_swz   = (lane & 7) * 16;
    const uint32_t a_xhalf = (lane >> 4) * 16;
    const int l8 = lane & 7;
    const int lg = lane >> 3;
    const uint32_t b_row_base = wn + (lg >> 1) * 8 + l8;
    const uint32_t b_khalf    = (lg & 1) * 16;
    const uint32_t b_swz      = l8 * 16;

    float acc[4][4][4];
    #pragma unroll
    for (int i = 0; i < 4; i++)
        #pragma unroll
        for (int j = 0; j < 4; j++)
            #pragma unroll
            for (int c = 0; c < 4; c++) acc[i][j][c] = 0.f;

    auto issue = [&](int kt, int slot) {
        const int k0 = kt * 64;
        const uint32_t sA = sbase + slot * STAGE_B;
        const uint32_t sB = sA + TILE_B;
        #pragma unroll
        for (int i = 0; i < 8; i++) {
            const int c = tid + i * 256;
            const int row = (c >> 3) & 127;
            const int x16 = c & 7;
            const uint32_t off = (uint32_t)(row * 128 + ((x16 * 16) ^ ((row & 7) * 16)));
            if (c < 1024) cp16(sA + off, A + (size_t)(m0 + row) * CDIM + k0 + x16 * 8);
            else          cp16(sB + off, B + (size_t)(n0 + row) * CDIM + k0 + x16 * 8);
        }
        cp_commit();
    };

    issue(0, 0); issue(1, 1);

    for (int kt = 0; kt < NKT; kt++) {
        const int slot = kt % 3;
        cp_wait<PIPE - 2>();
        __syncthreads();
        if (kt + 2 < NKT) issue(kt + 2, (kt + 2) % 3);

        const uint32_t sA = sbase + slot * STAGE_B;
        const uint32_t sB = sA + TILE_B;

        #pragma unroll
        for (int ks = 0; ks < 4; ks++) {
            uint32_t af[4][4];
            #pragma unroll
            for (int mi = 0; mi < 4; mi++) {
                const uint32_t addr = sA + (a_row + mi * 16) * 128
                                    + ((ks * 32 + a_xhalf) ^ a_swz);
                ldsm4(af[mi][0], af[mi][1], af[mi][2], af[mi][3], addr);
            }
            uint32_t bf[4][2];
            #pragma unroll
            for (int p = 0; p < 2; p++) {
                const uint32_t addr = sB + (b_row_base + p * 16) * 128
                                    + ((ks * 32 + b_khalf) ^ b_swz);
                ldsm4(bf[2*p][0], bf[2*p][1], bf[2*p+1][0], bf[2*p+1][1], addr);
            }
            #pragma unroll
            for (int mi = 0; mi < 4; mi++)
                #pragma unroll
                for (int nj = 0; nj < 4; nj++)
                    mma_f16(acc[mi][nj][0], acc[mi][nj][1], acc[mi][nj][2], acc[mi][nj][3],
                            af[mi][0], af[mi][1], af[mi][2], af[mi][3],
                            bf[nj][0], bf[nj][1]);
        }
    }

    #pragma unroll
    for (int mi = 0; mi < 4; mi++) {
        const int r0 = m0 + wm + mi * 16 + (lane >> 2);
        #pragma unroll
        for (int nj = 0; nj < 4; nj++) {
            const int c = n0 + wn + nj * 8 + (lane & 3) * 2;
            const float b0 = bias[c], b1 = bias[c + 1];
            float2 v0 = { acc[mi][nj][0] + b0, acc[mi][nj][1] + b1 };
            float2 v1 = { acc[mi][nj][2] + b0, acc[mi][nj][3] + b1 };
            *reinterpret_cast<float2*>(Cout + (size_t)r0 * Nc + c) = v0;
            *reinterpret_cast<float2*>(Cout + (size_t)(r0 + 8) * Nc + c) = v1;
        }
    }
}

// ============================================================
// Fused prep: fp32->fp16 converts (2 tensors) + weight transposes
// grid 1-D: [0,12288) cx, [12288,24576) dx, [24576,26880) weights
// ============================================================
#define NBC 12288      // (MROWS*CDIM/4)/256

__global__ __launch_bounds__(256) void prep_all(
    const float* __restrict__ cx, __half* __restrict__ a1f,
    const float* __restrict__ dx, __half* __restrict__ a2f,
    const float* __restrict__ Wq, const float* __restrict__ Wkv,
    const float* __restrict__ Wp,
    __half* __restrict__ Tq, __half* __restrict__ Tk, __half* __restrict__ Tp)
{
    const int bx = blockIdx.x;
    if (bx < 2 * NBC) {
        const bool sec = bx >= NBC;
        const float* in = sec ? dx : cx;
        __half* out = sec ? a2f : a1f;
        const int i = (sec ? bx - NBC : bx) * 256 + threadIdx.x;
        const float4 v = reinterpret_cast<const float4*>(in)[i];
        __half2 h0 = { __float2half_rn(v.x), __float2half_rn(v.y) };
        __half2 h1 = { __float2half_rn(v.z), __float2half_rn(v.w) };
        reinterpret_cast<__half2*>(out)[i * 2 + 0] = h0;
        reinterpret_cast<__half2*>(out)[i * 2 + 1] = h1;
        return;
    }
    // weight transpose: 2304 blocks, 96 n-tiles x 24 k-tiles
    __shared__ float t[32][33];
    const int w = bx - 2 * NBC;
    const int bnx = w % 96;
    const int k0 = (w / 96) * 32;
    const float* W; __half* T; int Nc, nt0;
    if (bnx < 24)      { W = Wq;  T = Tq; Nc = CDIM;     nt0 = 0; }
    else if (bnx < 72) { W = Wkv; T = Tk; Nc = 2 * CDIM; nt0 = 24; }
    else               { W = Wp;  T = Tp; Nc = CDIM;     nt0 = 72; }
    const int n0 = (bnx - nt0) * 32;
    const int tx = threadIdx.x & 31, ty = threadIdx.x >> 5;
    #pragma unroll
    for (int i = 0; i < 32; i += 8)
        t[ty + i][tx] = W[(size_t)(k0 + ty + i) * Nc + n0 + tx];
    __syncthreads();
    #pragma unroll
    for (int i = 0; i < 32; i += 8)
        T[(size_t)(n0 + ty + i) * CDIM + k0 + tx] = __float2half_rn(t[tx][ty + i]);
}

// ============================================================
// Reduce 32 per-mtile partials -> reciprocal norms
// grid BHn, 96 threads
// ============================================================
__global__ __launch_bounds__(96) void norm_reduce()
{
    const int bh = blockIdx.x;
    const int b  = bh >> 3;
    const int h  = bh & 7;
    const int d  = threadIdx.x;
    const int col = h * HDd + d;
    float sq = 0.f, sk = 0.f;
    #pragma unroll 8
    for (int j = 0; j < 32; j++) {
        sq += g_qsqp[(size_t)(b * 32 + j) * CDIM + col];
        sk += g_ksqp[(size_t)(b * 32 + j) * CDIM + col];
    }
    g_inq[bh * HDd + d] = 1.f / fmaxf(sqrtf(sq), EPSN);
    g_ink[bh * HDd + d] = 1.f / fmaxf(sqrtf(sk), EPSN);
}

// ============================================================
// Tensor-core Gram partials: part[d,e] = sum_n q[n,d] k[n,e]
// grid (BHn, SPLIT=16); 256 tokens per block
// ============================================================
#define GPITCH 104
#define GNI    (NTOK / SPLIT / 16)    // 16

__global__ __launch_bounds__(192) void gram_tc()
{
    __shared__ __half qs[3][16][GPITCH];
    __shared__ __half ks[3][16][GPITCH];

    const int bh = blockIdx.x;
    const int b  = bh >> 3;
    const int h  = bh & 7;
    const int sp = blockIdx.y;
    const int nbase = b * NTOK + sp * (NTOK / SPLIT);

    const int tid  = threadIdx.x;
    const int lane = tid & 31;
    const int w    = tid >> 5;
    const int e0   = w * 16;

    const __half* qbase = g_qh  + (size_t)nbase * CDIM + h * HDd;
    const __half* kbase = g_kvh + (size_t)nbase * (2 * CDIM) + h * HDd;

    const int lrow = tid / 12;
    const int lx   = tid % 12;

    auto issue = [&](int it, int s) {
        const int n0 = it * 16;
        cp16(s2u(&qs[s][lrow][lx * 8]),
             qbase + (size_t)(n0 + lrow) * CDIM + lx * 8);
        cp16(s2u(&ks[s][lrow][lx * 8]),
             kbase + (size_t)(n0 + lrow) * (2 * CDIM) + lx * 8);
        cp_commit();
    };

    const uint32_t a_row = (lane & 7) + ((lane >> 4) & 1) * 8;
    const uint32_t a_coff = ((lane >> 3) & 1) * 8;
    const uint32_t b_row = (lane & 7) + ((lane >> 3) & 1) * 8;
    const uint32_t b_coff = ((lane >> 4) & 1) * 8;

    float acc[6][2][4];
    #pragma unroll
    for (int i = 0; i < 6; i++)
        #pragma unroll
        for (int j = 0; j < 2; j++)
            #pragma unroll
            for (int c = 0; c < 4; c++) acc[i][j][c] = 0.f;

    issue(0, 0); issue(1, 1);

    for (int it = 0; it < GNI; it++) {
        const int s = it % 3;
        if (it + 1 < GNI) cp_wait<1>(); else cp_wait<0>();
        __syncthreads();
        if (it + 2 < GNI) issue(it + 2, (it + 2) % 3);

        uint32_t bf[4];
        ldsm4t(bf[0], bf[1], bf[2], bf[3], s2u(&ks[s][b_row][e0 + b_coff]));
        uint32_t af[6][4];
        #pragma unroll
        for (int mi = 0; mi < 6; mi++)
            ldsm4t(af[mi][0], af[mi][1], af[mi][2], af[mi][3],
                   s2u(&qs[s][a_row][mi * 16 + a_coff]));
        #pragma unroll
        for (int mi = 0; mi < 6; mi++)
            #pragma unroll
            for (int nj = 0; nj < 2; nj++)
                mma_f16(acc[mi][nj][0], acc[mi][nj][1], acc[mi][nj][2], acc[mi][nj][3],
                        af[mi][0], af[mi][1], af[mi][2], af[mi][3],
                        bf[nj * 2], bf[nj * 2 + 1]);
    }

    float* op = g_part + (size_t)(sp * BHn + bh) * (HDd * HDd);
    #pragma unroll
    for (int mi = 0; mi < 6; mi++) {
        const int d = mi * 16 + (lane >> 2);
        #pragma unroll
        for (int nj = 0; nj < 2; nj++) {
            const int e = e0 + nj * 8 + (lane & 3) * 2;
            float2 v0 = { acc[mi][nj][0], acc[mi][nj][1] };
            float2 v1 = { acc[mi][nj][2], acc[mi][nj][3] };
            *reinterpret_cast<float2*>(op + d * HDd + e) = v0;
            *reinterpret_cast<float2*>(op + (d + 8) * HDd + e) = v1;
        }
    }
}

// ============================================================
// softmax -> fp16 attn (uses precomputed reciprocal norms)
// ============================================================
__global__ __launch_bounds__(96) void softmax2_kernel()
{
    const int bh = blockIdx.x;
    const int d  = blockIdx.y;
    const int e  = threadIdx.x;
    const int w  = e >> 5, lane = e & 31;

    __shared__ float s_m[3], s_s[3];

    float sp = 0.f;
    #pragma unroll
    for (int p = 0; p < SPLIT; p++)
        sp += g_part[(size_t)(p * BHn + bh) * (HDd * HDd) + d * HDd + e];

    const float a = sp * SCALE_F * g_inq[bh * HDd + d] * g_ink[bh * HDd + e];

    float m = a;
    #pragma unroll
    for (int o = 16; o > 0; o >>= 1) m = fmaxf(m, __shfl_xor_sync(0xffffffffu, m, o));
    if (lane == 0) s_m[w] = m;
    __syncthreads();
    m = fmaxf(fmaxf(s_m[0], s_m[1]), s_m[2]);

    const float ex = __expf(a - m);
    float s = ex;
    #pragma unroll
    for (int o = 16; o > 0; o >>= 1) s += __shfl_xor_sync(0xffffffffu, s, o);
    if (lane == 0) s_s[w] = s;
    __syncthreads();
    s = s_s[0] + s_s[1] + s_s[2];

    g_attnh[(size_t)bh * (HDd * HDd) + d * HDd + e] = __float2half_rn(ex / s);
}

// ============================================================
// Tensor-core AV: x[n,d] = sum_e attn[d,e] v[n,e]
// ============================================================
#define APITCH 104

__global__ __launch_bounds__(128) void av_tc()
{
    __shared__ __half vs_[128][APITCH];
    __shared__ __half as_[96][APITCH];

    const int tile = blockIdx.x;
    const int h    = blockIdx.y;
    const int b    = tile >> 5;
    const int bh   = b * Hh + h;
    const int row0 = tile * 128;

    const int tid  = threadIdx.x;
    const int lane = tid & 31;
    const int w    = tid >> 5;

    const __half* vsrc = g_kvh + (size_t)row0 * (2 * CDIM) + CDIM + h * HDd;
    const __half* asrc = g_attnh + (size_t)bh * (HDd * HDd);
    #pragma unroll
    for (int i = 0; i < 12; i++) {
        const int c = tid + i * 128;
        const int r = c / 12, x = c % 12;
        cp16(s2u(&vs_[r][x * 8]), vsrc + (size_t)r * (2 * CDIM) + x * 8);
    }
    #pragma unroll
    for (int i = 0; i < 9; i++) {
        const int c = tid + i * 128;
        const int r = c / 12, x = c % 12;
        cp16(s2u(&as_[r][x * 8]), asrc + r * HDd + x * 8);
    }
    cp_commit();
    cp_wait<0>();
    __syncthreads();

    const uint32_t v_row = w * 32 + (lane & 15);
    const uint32_t v_coff = (lane >> 4) * 8;
    const uint32_t b_row = (lane & 7) + ((lane >> 4) & 1) * 8;
    const uint32_t b_coff = ((lane >> 3) & 1) * 8;

    float acc[2][12][4];
    #pragma unroll
    for (int i = 0; i < 2; i++)
        #pragma unroll
        for (int j = 0; j < 12; j++)
            #pragma unroll
            for (int c = 0; c < 4; c++) acc[i][j][c] = 0.f;

    #pragma unroll
    for (int ech = 0; ech < 6; ech++) {
        uint32_t af[2][4];
        #pragma unroll
        for (int mi = 0; mi < 2; mi++)
            ldsm4(af[mi][0], af[mi][1], af[mi][2], af[mi][3],
                  s2u(&vs_[v_row + mi * 16][ech * 16 + v_coff]));
        uint32_t bf[12][2];
        #pragma unroll
        for (int p = 0; p < 6; p++)
            ldsm4(bf[2*p][0], bf[2*p][1], bf[2*p+1][0], bf[2*p+1][1],
                  s2u(&as_[p * 16 + b_row][ech * 16 + b_coff]));
        #pragma unroll
        for (int mi = 0; mi < 2; mi++)
            #pragma unroll
            for (int nj = 0; nj < 12; nj++)
                mma_f16(acc[mi][nj][0], acc[mi][nj][1], acc[mi][nj][2], acc[mi][nj][3],
                        af[mi][0], af[mi][1], af[mi][2], af[mi][3],
                        bf[nj][0], bf[nj][1]);
    }

    #pragma unroll
    for (int mi = 0; mi < 2; mi++) {
        const int tok = row0 + w * 32 + mi * 16 + (lane >> 2);
        #pragma unroll
        for (int nj = 0; nj < 12; nj++) {
            const int d = nj * 8 + (lane & 3) * 2;
            __half2 v0 = { __float2half_rn(acc[mi][nj][0]), __float2half_rn(acc[mi][nj][1]) };
            __half2 v1 = { __float2half_rn(acc[mi][nj][2]), __float2half_rn(acc[mi][nj][3]) };
            *reinterpret_cast<__half2*>(g_xf + (size_t)tok * CDIM + h * HDd + d) = v0;
            *reinterpret_cast<__half2*>(g_xf + (size_t)(tok + 8) * CDIM + h * HDd + d) = v1;
        }
    }
}

// ============================================================
extern "C" void kernel_launch(void* const* d_in, const int* in_sizes, int n_in,
                              void* d_out, int out_size)
{
    const float* cx  = (const float*)d_in[0];
    const float* dx  = (const float*)d_in[1];
    const float* Wq  = (const float*)d_in[2];
    const float* Wkv = (const float*)d_in[3];
    const float* Wp  = (const float*)d_in[4];
    const float* bp  = (const float*)d_in[5];
    float* out = (float*)d_out;

    cudaFuncSetAttribute(gemm_proj, cudaFuncAttributeMaxDynamicSharedMemorySize, GSMEM);
    cudaFuncSetAttribute(gemm_out,  cudaFuncAttributeMaxDynamicSharedMemorySize, GSMEM);

    __half *a1f, *a2f, *xf, *wqf, *wkf, *wpf, *qh, *kvh;
    cudaGetSymbolAddress((void**)&a1f, g_a1f);
    cudaGetSymbolAddress((void**)&a2f, g_a2f);
    cudaGetSymbolAddress((void**)&xf,  g_xf);
    cudaGetSymbolAddress((void**)&wqf, g_wqf);
    cudaGetSymbolAddress((void**)&wkf, g_wkf);
    cudaGetSymbolAddress((void**)&wpf, g_wpf);
    cudaGetSymbolAddress((void**)&qh,  g_qh);
    cudaGetSymbolAddress((void**)&kvh, g_kvh);

    // all prep in one launch
    prep_all<<<2 * NBC + 2304, 256>>>(cx, a1f, dx, a2f, Wq, Wkv, Wp, wqf, wkf, wpf);

    // q and kv projections + sumsq partials in one launch
    gemm_proj<<<dim3(18, MROWS / 128), 256, GSMEM>>>(a1f, wqf, qh, a2f, wkf, kvh);

    // attention core
    norm_reduce<<<BHn, 96>>>();
    gram_tc<<<dim3(BHn, SPLIT), 192>>>();
    softmax2_kernel<<<dim3(BHn, HDd), 96>>>();
    av_tc<<<dim3(128, Hh), 128>>>();

    // out = x @ Wproj + b
    gemm_out<<<dim3(CDIM / 128, MROWS / 128), 256, GSMEM>>>(xf, wpf, bp, out);
}

// round 10
// speedup vs baseline: 7.6007x; 1.0439x over previous
#include <cuda_runtime.h>
#include <cuda_fp16.h>
#include <cstdint>
#include <cstddef>

// ---------------- problem constants ----------------
#define Bq    4
#define NTOK  4096
#define CDIM  768
#define Hh    8
#define HDd   96
#define MROWS (Bq * NTOK)          // 16384
#define SPLIT 16
#define BHn   (Bq * Hh)            // 32
#define MT    (MROWS / 128)        // 128 m-tiles
#define SCALE_F 0.10206207261596577f
#define EPSN 1e-12f

// ---------------- scratch (device globals) ----------------
__device__ __half g_a1f[(size_t)MROWS * CDIM];       // fp16 context_x
__device__ __half g_a2f[(size_t)MROWS * CDIM];       // fp16 depth_x
__device__ __half g_qh [(size_t)MROWS * CDIM];       // fp16 q
__device__ __half g_kvh[(size_t)MROWS * 2 * CDIM];   // fp16 kv
__device__ __half g_wqf[CDIM * CDIM];
__device__ __half g_wkf[2 * CDIM * CDIM];
__device__ __half g_wpf[CDIM * CDIM];
__device__ __half g_attnh[BHn * HDd * HDd];          // fp16 softmaxed attn
__device__ __half g_mt  [Bq * CDIM * CDIM];          // per-batch folded weights M^T
__device__ float g_part[SPLIT * BHn * HDd * HDd];
__device__ float g_qsqp[MT * CDIM];                  // per-mtile col sumsq (q)
__device__ float g_ksqp[MT * CDIM];                  // per-mtile col sumsq (k)
__device__ float g_inq [BHn * HDd];
__device__ float g_ink [BHn * HDd];

// ---------------- helpers ----------------
__device__ __forceinline__ uint32_t s2u(const void* p) {
    uint32_t a;
    asm("{ .reg .u64 t; cvta.to.shared.u64 t, %1; cvt.u32.u64 %0, t; }" : "=r"(a) : "l"(p));
    return a;
}
__device__ __forceinline__ void cp16(uint32_t dst, const void* src) {
    asm volatile("cp.async.cg.shared.global [%0], [%1], 16;" :: "r"(dst), "l"(src));
}
__device__ __forceinline__ void cp_commit() { asm volatile("cp.async.commit_group;"); }
template <int N>
__device__ __forceinline__ void cp_wait() { asm volatile("cp.async.wait_group %0;" :: "n"(N)); }

__device__ __forceinline__ void ldsm4(uint32_t& r0, uint32_t& r1, uint32_t& r2, uint32_t& r3,
                                      uint32_t addr) {
    asm volatile("ldmatrix.sync.aligned.m8n8.x4.shared.b16 {%0,%1,%2,%3}, [%4];"
                 : "=r"(r0), "=r"(r1), "=r"(r2), "=r"(r3) : "r"(addr));
}
__device__ __forceinline__ void ldsm4t(uint32_t& r0, uint32_t& r1, uint32_t& r2, uint32_t& r3,
                                       uint32_t addr) {
    asm volatile("ldmatrix.sync.aligned.m8n8.x4.trans.shared.b16 {%0,%1,%2,%3}, [%4];"
                 : "=r"(r0), "=r"(r1), "=r"(r2), "=r"(r3) : "r"(addr));
}
__device__ __forceinline__ void mma_f16(float& c0, float& c1, float& c2, float& c3,
                                        uint32_t a0, uint32_t a1, uint32_t a2, uint32_t a3,
                                        uint32_t b0, uint32_t b1) {
    asm volatile(
        "mma.sync.aligned.m16n8k16.row.col.f32.f16.f16.f32 "
        "{%0,%1,%2,%3}, {%4,%5,%6,%7}, {%8,%9}, {%0,%1,%2,%3};"
        : "+f"(c0), "+f"(c1), "+f"(c2), "+f"(c3)
        : "r"(a0), "r"(a1), "r"(a2), "r"(a3), "r"(b0), "r"(b1));
}

// ============================================================
// GEMM core config
// ============================================================
#define PIPE      3
#define TILE_B    16384
#define STAGE_B   (2 * TILE_B)
#define GSMEM     (PIPE * STAGE_B)     // 98304
#define NKT       12
#define NT1       6

// ============================================================
// Fused projection GEMM + column sumsq partials
// ============================================================
__global__ __launch_bounds__(256, 2) void gemm_proj(
    const __half* __restrict__ A1, const __half* __restrict__ B1, __half* __restrict__ O1,
    const __half* __restrict__ A2, const __half* __restrict__ B2, __half* __restrict__ O2)
{
    extern __shared__ __align__(1024) char smem[];
    const uint32_t sbase = s2u(smem);

    const bool j2 = blockIdx.x >= NT1;
    const __half* __restrict__ A = j2 ? A2 : A1;
    const __half* __restrict__ B = j2 ? B2 : B1;
    __half* __restrict__ O = j2 ? O2 : O1;
    const int Nc = j2 ? 2 * CDIM : CDIM;
    const int n0 = (j2 ? (int)blockIdx.x - NT1 : (int)blockIdx.x) * 128;
    const int m0 = blockIdx.y * 128;

    const int tid  = threadIdx.x;
    const int lane = tid & 31;
    const int wid  = tid >> 5;
    const int wm = (wid >> 2) * 64;
    const int wn = (wid & 3) * 32;

    const uint32_t a_row   = wm + (lane & 15);
    const uint32_t a_swz   = (lane & 7) * 16;
    const uint32_t a_xhalf = (lane >> 4) * 16;
    const int l8 = lane & 7;
    const int lg = lane >> 3;
    const uint32_t b_row_base = wn + (lg >> 1) * 8 + l8;
    const uint32_t b_khalf    = (lg & 1) * 16;
    const uint32_t b_swz      = l8 * 16;

    float acc[4][4][4];
    #pragma unroll
    for (int i = 0; i < 4; i++)
        #pragma unroll
        for (int j = 0; j < 4; j++)
            #pragma unroll
            for (int c = 0; c < 4; c++) acc[i][j][c] = 0.f;

    auto issue = [&](int kt, int slot) {
        const int k0 = kt * 64;
        const uint32_t sA = sbase + slot * STAGE_B;
        const uint32_t sB = sA + TILE_B;
        #pragma unroll
        for (int i = 0; i < 8; i++) {
            const int c = tid + i * 256;
            const int row = (c >> 3) & 127;
            const int x16 = c & 7;
            const uint32_t off = (uint32_t)(row * 128 + ((x16 * 16) ^ ((row & 7) * 16)));
            if (c < 1024) cp16(sA + off, A + (size_t)(m0 + row) * CDIM + k0 + x16 * 8);
            else          cp16(sB + off, B + (size_t)(n0 + row) * CDIM + k0 + x16 * 8);
        }
        cp_commit();
    };

    issue(0, 0); issue(1, 1);

    for (int kt = 0; kt < NKT; kt++) {
        const int slot = kt % 3;
        cp_wait<PIPE - 2>();
        __syncthreads();
        if (kt + 2 < NKT) issue(kt + 2, (kt + 2) % 3);

        const uint32_t sA = sbase + slot * STAGE_B;
        const uint32_t sB = sA + TILE_B;

        #pragma unroll
        for (int ks = 0; ks < 4; ks++) {
            uint32_t af[4][4];
            #pragma unroll
            for (int mi = 0; mi < 4; mi++) {
                const uint32_t addr = sA + (a_row + mi * 16) * 128
                                    + ((ks * 32 + a_xhalf) ^ a_swz);
                ldsm4(af[mi][0], af[mi][1], af[mi][2], af[mi][3], addr);
            }
            uint32_t bf[4][2];
            #pragma unroll
            for (int p = 0; p < 2; p++) {
                const uint32_t addr = sB + (b_row_base + p * 16) * 128
                                    + ((ks * 32 + b_khalf) ^ b_swz);
                ldsm4(bf[2*p][0], bf[2*p][1], bf[2*p+1][0], bf[2*p+1][1], addr);
            }
            #pragma unroll
            for (int mi = 0; mi < 4; mi++)
                #pragma unroll
                for (int nj = 0; nj < 4; nj++)
                    mma_f16(acc[mi][nj][0], acc[mi][nj][1], acc[mi][nj][2], acc[mi][nj][3],
                            af[mi][0], af[mi][1], af[mi][2], af[mi][3],
                            bf[nj][0], bf[nj][1]);
        }
    }

    #pragma unroll
    for (int mi = 0; mi < 4; mi++) {
        const int r0 = m0 + wm + mi * 16 + (lane >> 2);
        #pragma unroll
        for (int nj = 0; nj < 4; nj++) {
            const int c = n0 + wn + nj * 8 + (lane & 3) * 2;
            __half2 v0 = { __float2half_rn(acc[mi][nj][0]), __float2half_rn(acc[mi][nj][1]) };
            __half2 v1 = { __float2half_rn(acc[mi][nj][2]), __float2half_rn(acc[mi][nj][3]) };
            *reinterpret_cast<__half2*>(O + (size_t)r0 * Nc + c) = v0;
            *reinterpret_cast<__half2*>(O + (size_t)(r0 + 8) * Nc + c) = v1;
        }
    }

    // ---- fused column sum-of-squares ----
    const bool need_sq = (!j2) || (n0 < CDIM);
    if (need_sq) {
        float* colsq = reinterpret_cast<float*>(smem);   // [2][128]
        __syncthreads();
        #pragma unroll
        for (int nj = 0; nj < 4; nj++) {
            float s0 = 0.f, s1 = 0.f;
            #pragma unroll
            for (int mi = 0; mi < 4; mi++) {
                s0 += acc[mi][nj][0] * acc[mi][nj][0] + acc[mi][nj][2] * acc[mi][nj][2];
                s1 += acc[mi][nj][1] * acc[mi][nj][1] + acc[mi][nj][3] * acc[mi][nj][3];
            }
            #pragma unroll
            for (int o = 4; o < 32; o <<= 1) {
                s0 += __shfl_xor_sync(0xffffffffu, s0, o);
                s1 += __shfl_xor_sync(0xffffffffu, s1, o);
            }
            if (lane < 4) {
                const int col = wn + nj * 8 + lane * 2;
                colsq[(wm >> 6) * 128 + col]     = s0;
                colsq[(wm >> 6) * 128 + col + 1] = s1;
            }
        }
        __syncthreads();
        if (tid < 128) {
            const float tot = colsq[tid] + colsq[128 + tid];
            float* dst = j2 ? g_ksqp : g_qsqp;
            dst[(size_t)blockIdx.y * CDIM + n0 + tid] = tot;
        }
    }
}

// ============================================================
// Final GEMM: out = V @ M_b^T-layout + bias, fp32 output
// A = v half of kvh (row stride 2C, offset +C); B = g_mt[b]
// ============================================================
__global__ __launch_bounds__(256, 2) void gemm_out(
    const float* __restrict__ bias, float* __restrict__ Cout)
{
    extern __shared__ __align__(1024) char smem[];
    const uint32_t sbase = s2u(smem);
    const int Nc = CDIM;

    const int tid  = threadIdx.x;
    const int lane = tid & 31;
    const int wid  = tid >> 5;
    const int m0 = blockIdx.y * 128;
    const int n0 = blockIdx.x * 128;
    const int wm = (wid >> 2) * 64;
    const int wn = (wid & 3) * 32;

    const __half* __restrict__ A = g_kvh + CDIM;          // v half, row stride 2C
    const __half* __restrict__ B = g_mt + (size_t)(blockIdx.y >> 5) * CDIM * CDIM;

    const uint32_t a_row   = wm + (lane & 15);
    const uint32_t a_swz   = (lane & 7) * 16;
    const uint32_t a_xhalf = (lane >> 4) * 16;
    const int l8 = lane & 7;
    const int lg = lane >> 3;
    const uint32_t b_row_base = wn + (lg >> 1) * 8 + l8;
    const uint32_t b_khalf    = (lg & 1) * 16;
    const uint32_t b_swz      = l8 * 16;

    float acc[4][4][4];
    #pragma unroll
    for (int i = 0; i < 4; i++)
        #pragma unroll
        for (int j = 0; j < 4; j++)
            #pragma unroll
            for (int c = 0; c < 4; c++) acc[i][j][c] = 0.f;

    auto issue = [&](int kt, int slot) {
        const int k0 = kt * 64;
        const uint32_t sA = sbase + slot * STAGE_B;
        const uint32_t sB = sA + TILE_B;
        #pragma unroll
        for (int i = 0; i < 8; i++) {
            const int c = tid + i * 256;
            const int row = (c >> 3) & 127;
            const int x16 = c & 7;
            const uint32_t off = (uint32_t)(row * 128 + ((x16 * 16) ^ ((row & 7) * 16)));
            if (c < 1024) cp16(sA + off, A + (size_t)(m0 + row) * (2 * CDIM) + k0 + x16 * 8);
            else          cp16(sB + off, B + (size_t)(n0 + row) * CDIM + k0 + x16 * 8);
        }
        cp_commit();
    };

    issue(0, 0); issue(1, 1);

    for (int kt = 0; kt < NKT; kt++) {
        const int slot = kt % 3;
        cp_wait<PIPE - 2>();
        __syncthreads();
        if (kt + 2 < NKT) issue(kt + 2, (kt + 2) % 3);

        const uint32_t sA = sbase + slot * STAGE_B;
        const uint32_t sB = sA + TILE_B;

        #pragma unroll
        for (int ks = 0; ks < 4; ks++) {
            uint32_t af[4][4];
            #pragma unroll
            for (int mi = 0; mi < 4; mi++) {
                const uint32_t addr = sA + (a_row + mi * 16) * 128
                                    + ((ks * 32 + a_xhalf) ^ a_swz);
                ldsm4(af[mi][0], af[mi][1], af[mi][2], af[mi][3], addr);
            }
            uint32_t bf[4][2];
            #pragma unroll
            for (int p = 0; p < 2; p++) {
                const uint32_t addr = sB + (b_row_base + p * 16) * 128
                                    + ((ks * 32 + b_khalf) ^ b_swz);
                ldsm4(bf[2*p][0], bf[2*p][1], bf[2*p+1][0], bf[2*p+1][1], addr);
            }
            #pragma unroll
            for (int mi = 0; mi < 4; mi++)
                #pragma unroll
                for (int nj = 0; nj < 4; nj++)
                    mma_f16(acc[mi][nj][0], acc[mi][nj][1], acc[mi][nj][2], acc[mi][nj][3],
                            af[mi][0], af[mi][1], af[mi][2], af[mi][3],
                            bf[nj][0], bf[nj][1]);
        }
    }

    #pragma unroll
    for (int mi = 0; mi < 4; mi++) {
        const int r0 = m0 + wm + mi * 16 + (lane >> 2);
        #pragma unroll
        for (int nj = 0; nj < 4; nj++) {
            const int c = n0 + wn + nj * 8 + (lane & 3) * 2;
            const float b0 = bias[c], b1 = bias[c + 1];
            float2 v0 = { acc[mi][nj][0] + b0, acc[mi][nj][1] + b1 };
            float2 v1 = { acc[mi][nj][2] + b0, acc[mi][nj][3] + b1 };
            *reinterpret_cast<float2*>(Cout + (size_t)r0 * Nc + c) = v0;
            *reinterpret_cast<float2*>(Cout + (size_t)(r0 + 8) * Nc + c) = v1;
        }
    }
}

// ============================================================
// Fused prep: fp32->fp16 converts + weight transposes
// ============================================================
#define NBC 12288

__global__ __launch_bounds__(256) void prep_all(
    const float* __restrict__ cx, __half* __restrict__ a1f,
    const float* __restrict__ dx, __half* __restrict__ a2f,
    const float* __restrict__ Wq, const float* __restrict__ Wkv,
    const float* __restrict__ Wp,
    __half* __restrict__ Tq, __half* __restrict__ Tk, __half* __restrict__ Tp)
{
    const int bx = blockIdx.x;
    if (bx < 2 * NBC) {
        const bool sec = bx >= NBC;
        const float* in = sec ? dx : cx;
        __half* out = sec ? a2f : a1f;
        const int i = (sec ? bx - NBC : bx) * 256 + threadIdx.x;
        const float4 v = reinterpret_cast<const float4*>(in)[i];
        __half2 h0 = { __float2half_rn(v.x), __float2half_rn(v.y) };
        __half2 h1 = { __float2half_rn(v.z), __float2half_rn(v.w) };
        reinterpret_cast<__half2*>(out)[i * 2 + 0] = h0;
        reinterpret_cast<__half2*>(out)[i * 2 + 1] = h1;
        return;
    }
    __shared__ float t[32][33];
    const int w = bx - 2 * NBC;
    const int bnx = w % 96;
    const int k0 = (w / 96) * 32;
    const float* W; __half* T; int Nc, nt0;
    if (bnx < 24)      { W = Wq;  T = Tq; Nc = CDIM;     nt0 = 0; }
    else if (bnx < 72) { W = Wkv; T = Tk; Nc = 2 * CDIM; nt0 = 24; }
    else               { W = Wp;  T = Tp; Nc = CDIM;     nt0 = 72; }
    const int n0 = (bnx - nt0) * 32;
    const int tx = threadIdx.x & 31, ty = threadIdx.x >> 5;
    #pragma unroll
    for (int i = 0; i < 32; i += 8)
        t[ty + i][tx] = W[(size_t)(k0 + ty + i) * Nc + n0 + tx];
    __syncthreads();
    #pragma unroll
    for (int i = 0; i < 32; i += 8)
        T[(size_t)(n0 + ty + i) * CDIM + k0 + tx] = __float2half_rn(t[tx][ty + i]);
}

// ============================================================
// Reduce per-mtile partials -> reciprocal norms
// ============================================================
__global__ __launch_bounds__(96) void norm_reduce()
{
    const int bh = blockIdx.x;
    const int b  = bh >> 3;
    const int h  = bh & 7;
    const int d  = threadIdx.x;
    const int col = h * HDd + d;
    float sq = 0.f, sk = 0.f;
    #pragma unroll 8
    for (int j = 0; j < 32; j++) {
        sq += g_qsqp[(size_t)(b * 32 + j) * CDIM + col];
        sk += g_ksqp[(size_t)(b * 32 + j) * CDIM + col];
    }
    g_inq[bh * HDd + d] = 1.f / fmaxf(sqrtf(sq), EPSN);
    g_ink[bh * HDd + d] = 1.f / fmaxf(sqrtf(sk), EPSN);
}

// ============================================================
// Tensor-core Gram partials: 6-stage deep pipeline
// grid (BHn, SPLIT=16); 256 tokens per block
// ============================================================
#define GPITCH 104
#define GNI    (NTOK / SPLIT / 16)    // 16
#define GSTG   6

__global__ __launch_bounds__(192) void gram_tc()
{
    __shared__ __half qs[GSTG][16][GPITCH];
    __shared__ __half ks[GSTG][16][GPITCH];

    const int bh = blockIdx.x;
    const int b  = bh >> 3;
    const int h  = bh & 7;
    const int sp = blockIdx.y;
    const int nbase = b * NTOK + sp * (NTOK / SPLIT);

    const int tid  = threadIdx.x;
    const int lane = tid & 31;
    const int w    = tid >> 5;
    const int e0   = w * 16;

    const __half* qbase = g_qh  + (size_t)nbase * CDIM + h * HDd;
    const __half* kbase = g_kvh + (size_t)nbase * (2 * CDIM) + h * HDd;

    const int lrow = tid / 12;
    const int lx   = tid % 12;

    auto issue = [&](int it, int s) {
        const int n0 = it * 16;
        cp16(s2u(&qs[s][lrow][lx * 8]),
             qbase + (size_t)(n0 + lrow) * CDIM + lx * 8);
        cp16(s2u(&ks[s][lrow][lx * 8]),
             kbase + (size_t)(n0 + lrow) * (2 * CDIM) + lx * 8);
        cp_commit();
    };

    const uint32_t a_row = (lane & 7) + ((lane >> 4) & 1) * 8;
    const uint32_t a_coff = ((lane >> 3) & 1) * 8;
    const uint32_t b_row = (lane & 7) + ((lane >> 3) & 1) * 8;
    const uint32_t b_coff = ((lane >> 4) & 1) * 8;

    float acc[6][2][4];
    #pragma unroll
    for (int i = 0; i < 6; i++)
        #pragma unroll
        for (int j = 0; j < 2; j++)
            #pragma unroll
            for (int c = 0; c < 4; c++) acc[i][j][c] = 0.f;

    issue(0, 0); issue(1, 1); issue(2, 2); issue(3, 3); issue(4, 4);

    #pragma unroll 1
    for (int it = 0; it < GNI; it++) {
        const int s = it % GSTG;
        const int rem = GNI - 1 - it;
        if (rem >= 4)      cp_wait<4>();
        else if (rem == 3) cp_wait<3>();
        else if (rem == 2) cp_wait<2>();
        else if (rem == 1) cp_wait<1>();
        else               cp_wait<0>();
        __syncthreads();
        if (it + 5 < GNI) issue(it + 5, (it + 5) % GSTG);

        uint32_t bf[4];
        ldsm4t(bf[0], bf[1], bf[2], bf[3], s2u(&ks[s][b_row][e0 + b_coff]));
        uint32_t af[6][4];
        #pragma unroll
        for (int mi = 0; mi < 6; mi++)
            ldsm4t(af[mi][0], af[mi][1], af[mi][2], af[mi][3],
                   s2u(&qs[s][a_row][mi * 16 + a_coff]));
        #pragma unroll
        for (int mi = 0; mi < 6; mi++)
            #pragma unroll
            for (int nj = 0; nj < 2; nj++)
                mma_f16(acc[mi][nj][0], acc[mi][nj][1], acc[mi][nj][2], acc[mi][nj][3],
                        af[mi][0], af[mi][1], af[mi][2], af[mi][3],
                        bf[nj * 2], bf[nj * 2 + 1]);
    }

    float* op = g_part + (size_t)(sp * BHn + bh) * (HDd * HDd);
    #pragma unroll
    for (int mi = 0; mi < 6; mi++) {
        const int d = mi * 16 + (lane >> 2);
        #pragma unroll
        for (int nj = 0; nj < 2; nj++) {
            const int e = e0 + nj * 8 + (lane & 3) * 2;
            float2 v0 = { acc[mi][nj][0], acc[mi][nj][1] };
            float2 v1 = { acc[mi][nj][2], acc[mi][nj][3] };
            *reinterpret_cast<float2*>(op + d * HDd + e) = v0;
            *reinterpret_cast<float2*>(op + (d + 8) * HDd + e) = v1;
        }
    }
}

// ============================================================
// softmax -> fp16 attn
// ============================================================
__global__ __launch_bounds__(96) void softmax2_kernel()
{
    const int bh = blockIdx.x;
    const int d  = blockIdx.y;
    const int e  = threadIdx.x;
    const int w  = e >> 5, lane = e & 31;

    __shared__ float s_m[3], s_s[3];

    float sp = 0.f;
    #pragma unroll
    for (int p = 0; p < SPLIT; p++)
        sp += g_part[(size_t)(p * BHn + bh) * (HDd * HDd) + d * HDd + e];

    const float a = sp * SCALE_F * g_inq[bh * HDd + d] * g_ink[bh * HDd + e];

    float m = a;
    #pragma unroll
    for (int o = 16; o > 0; o >>= 1) m = fmaxf(m, __shfl_xor_sync(0xffffffffu, m, o));
    if (lane == 0) s_m[w] = m;
    __syncthreads();
    m = fmaxf(fmaxf(s_m[0], s_m[1]), s_m[2]);

    const float ex = __expf(a - m);
    float s = ex;
    #pragma unroll
    for (int o = 16; o > 0; o >>= 1) s += __shfl_xor_sync(0xffffffffu, s, o);
    if (lane == 0) s_s[w] = s;
    __syncthreads();
    s = s_s[0] + s_s[1] + s_s[2];

    g_attnh[(size_t)bh * (HDd * HDd) + d * HDd + e] = __float2half_rn(ex / s);
}

// ============================================================
// mbuild: M^T[b][j][h*96+e] = sum_d attn[b,h,d,e] * Wp[h*96+d, j]
// A = wpf tile [j rows x d cols] (row-major, ldsm4)
// B = attn [d rows x e cols] (col-major k x n via ldsm4t)
// grid (6 j-tiles, 32 bh); 128 thr
// ============================================================
__global__ __launch_bounds__(128) void mbuild()
{
    __shared__ __half ws[128][GPITCH];   // wpf tile [j][d]
    __shared__ __half as_[96][GPITCH];   // attn [d][e]

    const int jt = blockIdx.x;
    const int bh = blockIdx.y;
    const int b  = bh >> 3;
    const int h  = bh & 7;
    const int j0 = jt * 128;

    const int tid  = threadIdx.x;
    const int lane = tid & 31;
    const int w    = tid >> 5;

    const __half* wsrc = g_wpf + (size_t)j0 * CDIM + h * HDd;   // wpf[j][h96+d]
    const __half* asrc = g_attnh + (size_t)bh * (HDd * HDd);
    #pragma unroll
    for (int i = 0; i < 12; i++) {
        const int c = tid + i * 128;
        const int r = c / 12, x = c % 12;
        cp16(s2u(&ws[r][x * 8]), wsrc + (size_t)r * CDIM + x * 8);
    }
    #pragma unroll
    for (int i = 0; i < 9; i++) {
        const int c = tid + i * 128;
        const int r = c / 12, x = c % 12;
        cp16(s2u(&as_[r][x * 8]), asrc + r * HDd + x * 8);
    }
    cp_commit();
    cp_wait<0>();
    __syncthreads();

    const uint32_t aj_row = w * 32 + (lane & 15);
    const uint32_t aj_coff = (lane >> 4) * 8;
    const uint32_t b_row = (lane & 7) + ((lane >> 3) & 1) * 8;
    const uint32_t b_coff = ((lane >> 4) & 1) * 8;

    float acc[2][12][4];
    #pragma unroll
    for (int i = 0; i < 2; i++)
        #pragma unroll
        for (int j = 0; j < 12; j++)
            #pragma unroll
            for (int c = 0; c < 4; c++) acc[i][j][c] = 0.f;

    #pragma unroll
    for (int kc = 0; kc < 6; kc++) {
        uint32_t af[2][4];
        #pragma unroll
        for (int mi = 0; mi < 2; mi++)
            ldsm4(af[mi][0], af[mi][1], af[mi][2], af[mi][3],
                  s2u(&ws[aj_row + mi * 16][kc * 16 + aj_coff]));
        // B fragments: 6 n-tiles of 16 e -> 12 of 8
        uint32_t bf[12][2];
        #pragma unroll
        for (int p = 0; p < 6; p++) {
            uint32_t r0, r1, r2, r3;
            ldsm4t(r0, r1, r2, r3, s2u(&as_[kc * 16 + b_row][p * 16 + b_coff]));
            bf[2*p][0] = r0; bf[2*p][1] = r1;
            bf[2*p+1][0] = r2; bf[2*p+1][1] = r3;
        }
        #pragma unroll
        for (int mi = 0; mi < 2; mi++)
            #pragma unroll
            for (int nj = 0; nj < 12; nj++)
                mma_f16(acc[mi][nj][0], acc[mi][nj][1], acc[mi][nj][2], acc[mi][nj][3],
                        af[mi][0], af[mi][1], af[mi][2], af[mi][3],
                        bf[nj][0], bf[nj][1]);
    }

    __half* mt = g_mt + (size_t)b * CDIM * CDIM;
    #pragma unroll
    for (int mi = 0; mi < 2; mi++) {
        const int j = j0 + w * 32 + mi * 16 + (lane >> 2);
        #pragma unroll
        for (int nj = 0; nj < 12; nj++) {
            const int e = nj * 8 + (lane & 3) * 2;
            __half2 v0 = { __float2half_rn(acc[mi][nj][0]), __float2half_rn(acc[mi][nj][1]) };
            __half2 v1 = { __float2half_rn(acc[mi][nj][2]), __float2half_rn(acc[mi][nj][3]) };
            *reinterpret_cast<__half2*>(mt + (size_t)j * CDIM + h * HDd + e) = v0;
            *reinterpret_cast<__half2*>(mt + (size_t)(j + 8) * CDIM + h * HDd + e) = v1;
        }
    }
}

// ============================================================
extern "C" void kernel_launch(void* const* d_in, const int* in_sizes, int n_in,
                              void* d_out, int out_size)
{
    const float* cx  = (const float*)d_in[0];
    const float* dx  = (const float*)d_in[1];
    const float* Wq  = (const float*)d_in[2];
    const float* Wkv = (const float*)d_in[3];
    const float* Wp  = (const float*)d_in[4];
    const float* bp  = (const float*)d_in[5];
    float* out = (float*)d_out;

    cudaFuncSetAttribute(gemm_proj, cudaFuncAttributeMaxDynamicSharedMemorySize, GSMEM);
    cudaFuncSetAttribute(gemm_out,  cudaFuncAttributeMaxDynamicSharedMemorySize, GSMEM);

    __half *a1f, *a2f, *wqf, *wkf, *wpf, *qh, *kvh;
    cudaGetSymbolAddress((void**)&a1f, g_a1f);
    cudaGetSymbolAddress((void**)&a2f, g_a2f);
    cudaGetSymbolAddress((void**)&wqf, g_wqf);
    cudaGetSymbolAddress((void**)&wkf, g_wkf);
    cudaGetSymbolAddress((void**)&wpf, g_wpf);
    cudaGetSymbolAddress((void**)&qh,  g_qh);
    cudaGetSymbolAddress((void**)&kvh, g_kvh);

    // all prep in one launch
    prep_all<<<2 * NBC + 2304, 256>>>(cx, a1f, dx, a2f, Wq, Wkv, Wp, wqf, wkf, wpf);

    // q and kv projections + sumsq partials
    gemm_proj<<<dim3(18, MROWS / 128), 256, GSMEM>>>(a1f, wqf, qh, a2f, wkf, kvh);

    // attention core
    norm_reduce<<<BHn, 96>>>();
    gram_tc<<<dim3(BHn, SPLIT), 192>>>();
    softmax2_kernel<<<dim3(BHn, HDd), 96>>>();
    mbuild<<<dim3(6, BHn), 128>>>();

    // out = V @ M_b + bias (av folded into weights)
    gemm_out<<<dim3(CDIM / 128, MROWS / 128), 256, GSMEM>>>(bp, out);
}

// round 11
// speedup vs baseline: 7.6103x; 1.0013x over previous
#include <cuda_runtime.h>
#include <cuda_fp16.h>
#include <cstdint>
#include <cstddef>

// ---------------- problem constants ----------------
#define Bq    4
#define NTOK  4096
#define CDIM  768
#define Hh    8
#define HDd   96
#define MROWS (Bq * NTOK)          // 16384
#define SPLIT 16
#define BHn   (Bq * Hh)            // 32
#define MT    (MROWS / 128)        // 128 m-tiles
#define SCALE_F 0.10206207261596577f
#define EPSN 1e-12f

// ---------------- scratch (device globals) ----------------
__device__ __half g_a1f[(size_t)MROWS * CDIM];       // fp16 context_x
__device__ __half g_a2f[(size_t)MROWS * CDIM];       // fp16 depth_x
__device__ __half g_qh [(size_t)MROWS * CDIM];       // fp16 q
__device__ __half g_kvh[(size_t)MROWS * 2 * CDIM];   // fp16 kv
__device__ __half g_wqf[CDIM * CDIM];
__device__ __half g_wkf[2 * CDIM * CDIM];
__device__ __half g_wpf[CDIM * CDIM];
__device__ __half g_attnh[BHn * HDd * HDd];          // fp16 softmaxed attn
__device__ __half g_mt  [Bq * CDIM * CDIM];          // per-batch folded weights M^T
__device__ float g_part[SPLIT * BHn * HDd * HDd];
__device__ float g_qsqp[MT * CDIM];                  // per-mtile col sumsq (q)
__device__ float g_ksqp[MT * CDIM];                  // per-mtile col sumsq (k)
__device__ float g_inq [BHn * HDd];
__device__ float g_ink [BHn * HDd];

// ---------------- helpers ----------------
__device__ __forceinline__ uint32_t s2u(const void* p) {
    uint32_t a;
    asm("{ .reg .u64 t; cvta.to.shared.u64 t, %1; cvt.u32.u64 %0, t; }" : "=r"(a) : "l"(p));
    return a;
}
__device__ __forceinline__ void cp16(uint32_t dst, const void* src) {
    asm volatile("cp.async.cg.shared.global [%0], [%1], 16;" :: "r"(dst), "l"(src));
}
__device__ __forceinline__ void cp_commit() { asm volatile("cp.async.commit_group;"); }
template <int N>
__device__ __forceinline__ void cp_wait() { asm volatile("cp.async.wait_group %0;" :: "n"(N)); }

__device__ __forceinline__ void ldsm4(uint32_t& r0, uint32_t& r1, uint32_t& r2, uint32_t& r3,
                                      uint32_t addr) {
    asm volatile("ldmatrix.sync.aligned.m8n8.x4.shared.b16 {%0,%1,%2,%3}, [%4];"
                 : "=r"(r0), "=r"(r1), "=r"(r2), "=r"(r3) : "r"(addr));
}
__device__ __forceinline__ void ldsm4t(uint32_t& r0, uint32_t& r1, uint32_t& r2, uint32_t& r3,
                                       uint32_t addr) {
    asm volatile("ldmatrix.sync.aligned.m8n8.x4.trans.shared.b16 {%0,%1,%2,%3}, [%4];"
                 : "=r"(r0), "=r"(r1), "=r"(r2), "=r"(r3) : "r"(addr));
}
__device__ __forceinline__ void mma_f16(float& c0, float& c1, float& c2, float& c3,
                                        uint32_t a0, uint32_t a1, uint32_t a2, uint32_t a3,
                                        uint32_t b0, uint32_t b1) {
    asm volatile(
        "mma.sync.aligned.m16n8k16.row.col.f32.f16.f16.f32 "
        "{%0,%1,%2,%3}, {%4,%5,%6,%7}, {%8,%9}, {%0,%1,%2,%3};"
        : "+f"(c0), "+f"(c1), "+f"(c2), "+f"(c3)
        : "r"(a0), "r"(a1), "r"(a2), "r"(a3), "r"(b0), "r"(b1));
}

// ============================================================
// GEMM core config
// ============================================================
#define PIPE      3
#define TILE_B    16384
#define STAGE_B   (2 * TILE_B)
#define GSMEM     (PIPE * STAGE_B)     // 98304
#define NKT       12
#define NT1       6

// ============================================================
// Fused projection GEMM + column sumsq partials
// ============================================================
__global__ __launch_bounds__(256, 2) void gemm_proj(
    const __half* __restrict__ A1, const __half* __restrict__ B1, __half* __restrict__ O1,
    const __half* __restrict__ A2, const __half* __restrict__ B2, __half* __restrict__ O2)
{
    extern __shared__ __align__(1024) char smem[];
    const uint32_t sbase = s2u(smem);

    const bool j2 = blockIdx.x >= NT1;
    const __half* __restrict__ A = j2 ? A2 : A1;
    const __half* __restrict__ B = j2 ? B2 : B1;
    __half* __restrict__ O = j2 ? O2 : O1;
    const int Nc = j2 ? 2 * CDIM : CDIM;
    const int n0 = (j2 ? (int)blockIdx.x - NT1 : (int)blockIdx.x) * 128;
    const int m0 = blockIdx.y * 128;

    const int tid  = threadIdx.x;
    const int lane = tid & 31;
    const int wid  = tid >> 5;
    const int wm = (wid >> 2) * 64;
    const int wn = (wid & 3) * 32;

    const uint32_t a_row   = wm + (lane & 15);
    const uint32_t a_swz   = (lane & 7) * 16;
    const uint32_t a_xhalf = (lane >> 4) * 16;
    const int l8 = lane & 7;
    const int lg = lane >> 3;
    const uint32_t b_row_base = wn + (lg >> 1) * 8 + l8;
    const uint32_t b_khalf    = (lg & 1) * 16;
    const uint32_t b_swz      = l8 * 16;

    float acc[4][4][4];
    #pragma unroll
    for (int i = 0; i < 4; i++)
        #pragma unroll
        for (int j = 0; j < 4; j++)
            #pragma unroll
            for (int c = 0; c < 4; c++) acc[i][j][c] = 0.f;

    auto issue = [&](int kt, int slot) {
        const int k0 = kt * 64;
        const uint32_t sA = sbase + slot * STAGE_B;
        const uint32_t sB = sA + TILE_B;
        #pragma unroll
        for (int i = 0; i < 8; i++) {
            const int c = tid + i * 256;
            const int row = (c >> 3) & 127;
            const int x16 = c & 7;
            const uint32_t off = (uint32_t)(row * 128 + ((x16 * 16) ^ ((row & 7) * 16)));
            if (c < 1024) cp16(sA + off, A + (size_t)(m0 + row) * CDIM + k0 + x16 * 8);
            else          cp16(sB + off, B + (size_t)(n0 + row) * CDIM + k0 + x16 * 8);
        }
        cp_commit();
    };

    issue(0, 0); issue(1, 1);

    for (int kt = 0; kt < NKT; kt++) {
        const int slot = kt % 3;
        cp_wait<PIPE - 2>();
        __syncthreads();
        if (kt + 2 < NKT) issue(kt + 2, (kt + 2) % 3);

        const uint32_t sA = sbase + slot * STAGE_B;
        const uint32_t sB = sA + TILE_B;

        #pragma unroll
        for (int ks = 0; ks < 4; ks++) {
            uint32_t af[4][4];
            #pragma unroll
            for (int mi = 0; mi < 4; mi++) {
                const uint32_t addr = sA + (a_row + mi * 16) * 128
                                    + ((ks * 32 + a_xhalf) ^ a_swz);
                ldsm4(af[mi][0], af[mi][1], af[mi][2], af[mi][3], addr);
            }
            uint32_t bf[4][2];
            #pragma unroll
            for (int p = 0; p < 2; p++) {
                const uint32_t addr = sB + (b_row_base + p * 16) * 128
                                    + ((ks * 32 + b_khalf) ^ b_swz);
                ldsm4(bf[2*p][0], bf[2*p][1], bf[2*p+1][0], bf[2*p+1][1], addr);
            }
            #pragma unroll
            for (int mi = 0; mi < 4; mi++)
                #pragma unroll
                for (int nj = 0; nj < 4; nj++)
                    mma_f16(acc[mi][nj][0], acc[mi][nj][1], acc[mi][nj][2], acc[mi][nj][3],
                            af[mi][0], af[mi][1], af[mi][2], af[mi][3],
                            bf[nj][0], bf[nj][1]);
        }
    }

    #pragma unroll
    for (int mi = 0; mi < 4; mi++) {
        const int r0 = m0 + wm + mi * 16 + (lane >> 2);
        #pragma unroll
        for (int nj = 0; nj < 4; nj++) {
            const int c = n0 + wn + nj * 8 + (lane & 3) * 2;
            __half2 v0 = { __float2half_rn(acc[mi][nj][0]), __float2half_rn(acc[mi][nj][1]) };
            __half2 v1 = { __float2half_rn(acc[mi][nj][2]), __float2half_rn(acc[mi][nj][3]) };
            *reinterpret_cast<__half2*>(O + (size_t)r0 * Nc + c) = v0;
            *reinterpret_cast<__half2*>(O + (size_t)(r0 + 8) * Nc + c) = v1;
        }
    }

    // ---- fused column sum-of-squares ----
    const bool need_sq = (!j2) || (n0 < CDIM);
    if (need_sq) {
        float* colsq = reinterpret_cast<float*>(smem);   // [2][128]
        __syncthreads();
        #pragma unroll
        for (int nj = 0; nj < 4; nj++) {
            float s0 = 0.f, s1 = 0.f;
            #pragma unroll
            for (int mi = 0; mi < 4; mi++) {
                s0 += acc[mi][nj][0] * acc[mi][nj][0] + acc[mi][nj][2] * acc[mi][nj][2];
                s1 += acc[mi][nj][1] * acc[mi][nj][1] + acc[mi][nj][3] * acc[mi][nj][3];
            }
            #pragma unroll
            for (int o = 4; o < 32; o <<= 1) {
                s0 += __shfl_xor_sync(0xffffffffu, s0, o);
                s1 += __shfl_xor_sync(0xffffffffu, s1, o);
            }
            if (lane < 4) {
                const int col = wn + nj * 8 + lane * 2;
                colsq[(wm >> 6) * 128 + col]     = s0;
                colsq[(wm >> 6) * 128 + col + 1] = s1;
            }
        }
        __syncthreads();
        if (tid < 128) {
            const float tot = colsq[tid] + colsq[128 + tid];
            float* dst = j2 ? g_ksqp : g_qsqp;
            dst[(size_t)blockIdx.y * CDIM + n0 + tid] = tot;
        }
    }
}

// ============================================================
// Final GEMM: out = V @ M_b + bias, fp32 output
// ============================================================
__global__ __launch_bounds__(256, 2) void gemm_out(
    const float* __restrict__ bias, float* __restrict__ Cout)
{
    extern __shared__ __align__(1024) char smem[];
    const uint32_t sbase = s2u(smem);
    const int Nc = CDIM;

    const int tid  = threadIdx.x;
    const int lane = tid & 31;
    const int wid  = tid >> 5;
    const int m0 = blockIdx.y * 128;
    const int n0 = blockIdx.x * 128;
    const int wm = (wid >> 2) * 64;
    const int wn = (wid & 3) * 32;

    const __half* __restrict__ A = g_kvh + CDIM;          // v half, row stride 2C
    const __half* __restrict__ B = g_mt + (size_t)(blockIdx.y >> 5) * CDIM * CDIM;

    const uint32_t a_row   = wm + (lane & 15);
    const uint32_t a_swz   = (lane & 7) * 16;
    const uint32_t a_xhalf = (lane >> 4) * 16;
    const int l8 = lane & 7;
    const int lg = lane >> 3;
    const uint32_t b_row_base = wn + (lg >> 1) * 8 + l8;
    const uint32_t b_khalf    = (lg & 1) * 16;
    const uint32_t b_swz      = l8 * 16;

    float acc[4][4][4];
    #pragma unroll
    for (int i = 0; i < 4; i++)
        #pragma unroll
        for (int j = 0; j < 4; j++)
            #pragma unroll
            for (int c = 0; c < 4; c++) acc[i][j][c] = 0.f;

    auto issue = [&](int kt, int slot) {
        const int k0 = kt * 64;
        const uint32_t sA = sbase + slot * STAGE_B;
        const uint32_t sB = sA + TILE_B;
        #pragma unroll
        for (int i = 0; i < 8; i++) {
            const int c = tid + i * 256;
            const int row = (c >> 3) & 127;
            const int x16 = c & 7;
            const uint32_t off = (uint32_t)(row * 128 + ((x16 * 16) ^ ((row & 7) * 16)));
            if (c < 1024) cp16(sA + off, A + (size_t)(m0 + row) * (2 * CDIM) + k0 + x16 * 8);
            else          cp16(sB + off, B + (size_t)(n0 + row) * CDIM + k0 + x16 * 8);
        }
        cp_commit();
    };

    issue(0, 0); issue(1, 1);

    for (int kt = 0; kt < NKT; kt++) {
        const int slot = kt % 3;
        cp_wait<PIPE - 2>();
        __syncthreads();
        if (kt + 2 < NKT) issue(kt + 2, (kt + 2) % 3);

        const uint32_t sA = sbase + slot * STAGE_B;
        const uint32_t sB = sA + TILE_B;

        #pragma unroll
        for (int ks = 0; ks < 4; ks++) {
            uint32_t af[4][4];
            #pragma unroll
            for (int mi = 0; mi < 4; mi++) {
                const uint32_t addr = sA + (a_row + mi * 16) * 128
                                    + ((ks * 32 + a_xhalf) ^ a_swz);
                ldsm4(af[mi][0], af[mi][1], af[mi][2], af[mi][3], addr);
            }
            uint32_t bf[4][2];
            #pragma unroll
            for (int p = 0; p < 2; p++) {
                const uint32_t addr = sB + (b_row_base + p * 16) * 128
                                    + ((ks * 32 + b_khalf) ^ b_swz);
                ldsm4(bf[2*p][0], bf[2*p][1], bf[2*p+1][0], bf[2*p+1][1], addr);
            }
            #pragma unroll
            for (int mi = 0; mi < 4; mi++)
                #pragma unroll
                for (int nj = 0; nj < 4; nj++)
                    mma_f16(acc[mi][nj][0], acc[mi][nj][1], acc[mi][nj][2], acc[mi][nj][3],
                            af[mi][0], af[mi][1], af[mi][2], af[mi][3],
                            bf[nj][0], bf[nj][1]);
        }
    }

    #pragma unroll
    for (int mi = 0; mi < 4; mi++) {
        const int r0 = m0 + wm + mi * 16 + (lane >> 2);
        #pragma unroll
        for (int nj = 0; nj < 4; nj++) {
            const int c = n0 + wn + nj * 8 + (lane & 3) * 2;
            const float b0 = bias[c], b1 = bias[c + 1];
            float2 v0 = { acc[mi][nj][0] + b0, acc[mi][nj][1] + b1 };
            float2 v1 = { acc[mi][nj][2] + b0, acc[mi][nj][3] + b1 };
            *reinterpret_cast<float2*>(Cout + (size_t)r0 * Nc + c) = v0;
            *reinterpret_cast<float2*>(Cout + (size_t)(r0 + 8) * Nc + c) = v1;
        }
    }
}

// ============================================================
// Fused prep: fp32->fp16 converts + weight transposes
// ============================================================
#define NBC 12288

__global__ __launch_bounds__(256) void prep_all(
    const float* __restrict__ cx, __half* __restrict__ a1f,
    const float* __restrict__ dx, __half* __restrict__ a2f,
    const float* __restrict__ Wq, const float* __restrict__ Wkv,
    const float* __restrict__ Wp,
    __half* __restrict__ Tq, __half* __restrict__ Tk, __half* __restrict__ Tp)
{
    const int bx = blockIdx.x;
    if (bx < 2 * NBC) {
        const bool sec = bx >= NBC;
        const float* in = sec ? dx : cx;
        __half* out = sec ? a2f : a1f;
        const int i = (sec ? bx - NBC : bx) * 256 + threadIdx.x;
        const float4 v = reinterpret_cast<const float4*>(in)[i];
        __half2 h0 = { __float2half_rn(v.x), __float2half_rn(v.y) };
        __half2 h1 = { __float2half_rn(v.z), __float2half_rn(v.w) };
        reinterpret_cast<__half2*>(out)[i * 2 + 0] = h0;
        reinterpret_cast<__half2*>(out)[i * 2 + 1] = h1;
        return;
    }
    __shared__ float t[32][33];
    const int w = bx - 2 * NBC;
    const int bnx = w % 96;
    const int k0 = (w / 96) * 32;
    const float* W; __half* T; int Nc, nt0;
    if (bnx < 24)      { W = Wq;  T = Tq; Nc = CDIM;     nt0 = 0; }
    else if (bnx < 72) { W = Wkv; T = Tk; Nc = 2 * CDIM; nt0 = 24; }
    else               { W = Wp;  T = Tp; Nc = CDIM;     nt0 = 72; }
    const int n0 = (bnx - nt0) * 32;
    const int tx = threadIdx.x & 31, ty = threadIdx.x >> 5;
    #pragma unroll
    for (int i = 0; i < 32; i += 8)
        t[ty + i][tx] = W[(size_t)(k0 + ty + i) * Nc + n0 + tx];
    __syncthreads();
    #pragma unroll
    for (int i = 0; i < 32; i += 8)
        T[(size_t)(n0 + ty + i) * CDIM + k0 + tx] = __float2half_rn(t[tx][ty + i]);
}

// ============================================================
// Reduce per-mtile partials -> reciprocal norms
// ============================================================
__global__ __launch_bounds__(96) void norm_reduce()
{
    const int bh = blockIdx.x;
    const int b  = bh >> 3;
    const int h  = bh & 7;
    const int d  = threadIdx.x;
    const int col = h * HDd + d;
    float sq = 0.f, sk = 0.f;
    #pragma unroll 8
    for (int j = 0; j < 32; j++) {
        sq += g_qsqp[(size_t)(b * 32 + j) * CDIM + col];
        sk += g_ksqp[(size_t)(b * 32 + j) * CDIM + col];
    }
    g_inq[bh * HDd + d] = 1.f / fmaxf(sqrtf(sq), EPSN);
    g_ink[bh * HDd + d] = 1.f / fmaxf(sqrtf(sk), EPSN);
}

// ============================================================
// Tensor-core Gram partials: 32-token stages, 3-stage pipe
// grid (BHn, SPLIT=16); 256 tokens per block; GNI=8
// ============================================================
#define GPITCH 104
#define GNI    8
#define GSTG   3

__global__ __launch_bounds__(192) void gram_tc()
{
    __shared__ __half qs[GSTG][32][GPITCH];
    __shared__ __half ks[GSTG][32][GPITCH];

    const int bh = blockIdx.x;
    const int b  = bh >> 3;
    const int h  = bh & 7;
    const int sp = blockIdx.y;
    const int nbase = b * NTOK + sp * (NTOK / SPLIT);

    const int tid  = threadIdx.x;
    const int lane = tid & 31;
    const int w    = tid >> 5;
    const int e0   = w * 16;

    const __half* qbase = g_qh  + (size_t)nbase * CDIM + h * HDd;
    const __half* kbase = g_kvh + (size_t)nbase * (2 * CDIM) + h * HDd;

    auto issue = [&](int it, int s) {
        const int n0 = it * 32;
        #pragma unroll
        for (int r = 0; r < 2; r++) {
            const int c = tid + r * 192;      // 0..383
            const int lrow = c / 12;
            const int lx   = c % 12;
            cp16(s2u(&qs[s][lrow][lx * 8]),
                 qbase + (size_t)(n0 + lrow) * CDIM + lx * 8);
            cp16(s2u(&ks[s][lrow][lx * 8]),
                 kbase + (size_t)(n0 + lrow) * (2 * CDIM) + lx * 8);
        }
        cp_commit();
    };

    const uint32_t a_row = (lane & 7) + ((lane >> 4) & 1) * 8;
    const uint32_t a_coff = ((lane >> 3) & 1) * 8;
    const uint32_t b_row = (lane & 7) + ((lane >> 3) & 1) * 8;
    const uint32_t b_coff = ((lane >> 4) & 1) * 8;

    float acc[6][2][4];
    #pragma unroll
    for (int i = 0; i < 6; i++)
        #pragma unroll
        for (int j = 0; j < 2; j++)
            #pragma unroll
            for (int c = 0; c < 4; c++) acc[i][j][c] = 0.f;

    issue(0, 0); issue(1, 1);

    #pragma unroll 1
    for (int it = 0; it < GNI; it++) {
        const int s = it % GSTG;
        if (it + 1 < GNI) cp_wait<1>(); else cp_wait<0>();
        __syncthreads();
        if (it + 2 < GNI) issue(it + 2, (it + 2) % GSTG);

        #pragma unroll
        for (int hs = 0; hs < 2; hs++) {
            uint32_t bf[4];
            ldsm4t(bf[0], bf[1], bf[2], bf[3],
                   s2u(&ks[s][hs * 16 + b_row][e0 + b_coff]));
            uint32_t af[6][4];
            #pragma unroll
            for (int mi = 0; mi < 6; mi++)
                ldsm4t(af[mi][0], af[mi][1], af[mi][2], af[mi][3],
                       s2u(&qs[s][hs * 16 + a_row][mi * 16 + a_coff]));
            #pragma unroll
            for (int mi = 0; mi < 6; mi++)
                #pragma unroll
                for (int nj = 0; nj < 2; nj++)
                    mma_f16(acc[mi][nj][0], acc[mi][nj][1], acc[mi][nj][2], acc[mi][nj][3],
                            af[mi][0], af[mi][1], af[mi][2], af[mi][3],
                            bf[nj * 2], bf[nj * 2 + 1]);
        }
    }

    float* op = g_part + (size_t)(sp * BHn + bh) * (HDd * HDd);
    #pragma unroll
    for (int mi = 0; mi < 6; mi++) {
        const int d = mi * 16 + (lane >> 2);
        #pragma unroll
        for (int nj = 0; nj < 2; nj++) {
            const int e = e0 + nj * 8 + (lane & 3) * 2;
            float2 v0 = { acc[mi][nj][0], acc[mi][nj][1] };
            float2 v1 = { acc[mi][nj][2], acc[mi][nj][3] };
            *reinterpret_cast<float2*>(op + d * HDd + e) = v0;
            *reinterpret_cast<float2*>(op + (d + 8) * HDd + e) = v1;
        }
    }
}

// ============================================================
// softmax -> fp16 attn (no max pass: |logit| <= ~0.103)
// ============================================================
__global__ __launch_bounds__(96) void softmax2_kernel()
{
    const int bh = blockIdx.x;
    const int d  = blockIdx.y;
    const int e  = threadIdx.x;
    const int w  = e >> 5, lane = e & 31;

    __shared__ float s_s[3];

    float sp = 0.f;
    #pragma unroll
    for (int p = 0; p < SPLIT; p++)
        sp += g_part[(size_t)(p * BHn + bh) * (HDd * HDd) + d * HDd + e];

    const float a = sp * SCALE_F * g_inq[bh * HDd + d] * g_ink[bh * HDd + e];

    const float ex = __expf(a);
    float s = ex;
    #pragma unroll
    for (int o = 16; o > 0; o >>= 1) s += __shfl_xor_sync(0xffffffffu, s, o);
    if (lane == 0) s_s[w] = s;
    __syncthreads();
    s = s_s[0] + s_s[1] + s_s[2];

    g_attnh[(size_t)bh * (HDd * HDd) + d * HDd + e] = __float2half_rn(ex / s);
}

// ============================================================
// mbuild: M^T[b][j][h*96+e] = sum_d attn[b,h,d,e] * Wp[h*96+d, j]
// ============================================================
__global__ __launch_bounds__(128) void mbuild()
{
    __shared__ __half ws[128][GPITCH];   // wpf tile [j][d]
    __shared__ __half as_[96][GPITCH];   // attn [d][e]

    const int jt = blockIdx.x;
    const int bh = blockIdx.y;
    const int b  = bh >> 3;
    const int h  = bh & 7;
    const int j0 = jt * 128;

    const int tid  = threadIdx.x;
    const int lane = tid & 31;
    const int w    = tid >> 5;

    const __half* wsrc = g_wpf + (size_t)j0 * CDIM + h * HDd;
    const __half* asrc = g_attnh + (size_t)bh * (HDd * HDd);
    #pragma unroll
    for (int i = 0; i < 12; i++) {
        const int c = tid + i * 128;
        const int r = c / 12, x = c % 12;
        cp16(s2u(&ws[r][x * 8]), wsrc + (size_t)r * CDIM + x * 8);
    }
    #pragma unroll
    for (int i = 0; i < 9; i++) {
        const int c = tid + i * 128;
        const int r = c / 12, x = c % 12;
        cp16(s2u(&as_[r][x * 8]), asrc + r * HDd + x * 8);
    }
    cp_commit();
    cp_wait<0>();
    __syncthreads();

    const uint32_t aj_row = w * 32 + (lane & 15);
    const uint32_t aj_coff = (lane >> 4) * 8;
    const uint32_t b_row = (lane & 7) + ((lane >> 3) & 1) * 8;
    const uint32_t b_coff = ((lane >> 4) & 1) * 8;

    float acc[2][12][4];
    #pragma unroll
    for (int i = 0; i < 2; i++)
        #pragma unroll
        for (int j = 0; j < 12; j++)
            #pragma unroll
            for (int c = 0; c < 4; c++) acc[i][j][c] = 0.f;

    #pragma unroll
    for (int kc = 0; kc < 6; kc++) {
        uint32_t af[2][4];
        #pragma unroll
        for (int mi = 0; mi < 2; mi++)
            ldsm4(af[mi][0], af[mi][1], af[mi][2], af[mi][3],
                  s2u(&ws[aj_row + mi * 16][kc * 16 + aj_coff]));
        uint32_t bf[12][2];
        #pragma unroll
        for (int p = 0; p < 6; p++) {
            uint32_t r0, r1, r2, r3;
            ldsm4t(r0, r1, r2, r3, s2u(&as_[kc * 16 + b_row][p * 16 + b_coff]));
            bf[2*p][0] = r0; bf[2*p][1] = r1;
            bf[2*p+1][0] = r2; bf[2*p+1][1] = r3;
        }
        #pragma unroll
        for (int mi = 0; mi < 2; mi++)
            #pragma unroll
            for (int nj = 0; nj < 12; nj++)
                mma_f16(acc[mi][nj][0], acc[mi][nj][1], acc[mi][nj][2], acc[mi][nj][3],
                        af[mi][0], af[mi][1], af[mi][2], af[mi][3],
                        bf[nj][0], bf[nj][1]);
    }

    __half* mt = g_mt + (size_t)b * CDIM * CDIM;
    #pragma unroll
    for (int mi = 0; mi < 2; mi++) {
        const int j = j0 + w * 32 + mi * 16 + (lane >> 2);
        #pragma unroll
        for (int nj = 0; nj < 12; nj++) {
            const int e = nj * 8 + (lane & 3) * 2;
            __half2 v0 = { __float2half_rn(acc[mi][nj][0]), __float2half_rn(acc[mi][nj][1]) };
            __half2 v1 = { __float2half_rn(acc[mi][nj][2]), __float2half_rn(acc[mi][nj][3]) };
            *reinterpret_cast<__half2*>(mt + (size_t)j * CDIM + h * HDd + e) = v0;
            *reinterpret_cast<__half2*>(mt + (size_t)(j + 8) * CDIM + h * HDd + e) = v1;
        }
    }
}

// ============================================================
extern "C" void kernel_launch(void* const* d_in, const int* in_sizes, int n_in,
                              void* d_out, int out_size)
{
    const float* cx  = (const float*)d_in[0];
    const float* dx  = (const float*)d_in[1];
    const float* Wq  = (const float*)d_in[2];
    const float* Wkv = (const float*)d_in[3];
    const float* Wp  = (const float*)d_in[4];
    const float* bp  = (const float*)d_in[5];
    float* out = (float*)d_out;

    cudaFuncSetAttribute(gemm_proj, cudaFuncAttributeMaxDynamicSharedMemorySize, GSMEM);
    cudaFuncSetAttribute(gemm_out,  cudaFuncAttributeMaxDynamicSharedMemorySize, GSMEM);

    __half *a1f, *a2f, *wqf, *wkf, *wpf, *qh, *kvh;
    cudaGetSymbolAddress((void**)&a1f, g_a1f);
    cudaGetSymbolAddress((void**)&a2f, g_a2f);
    cudaGetSymbolAddress((void**)&wqf, g_wqf);
    cudaGetSymbolAddress((void**)&wkf, g_wkf);
    cudaGetSymbolAddress((void**)&wpf, g_wpf);
    cudaGetSymbolAddress((void**)&qh,  g_qh);
    cudaGetSymbolAddress((void**)&kvh, g_kvh);

    // all prep in one launch
    prep_all<<<2 * NBC + 2304, 256>>>(cx, a1f, dx, a2f, Wq, Wkv, Wp, wqf, wkf, wpf);

    // q and kv projections + sumsq partials
    gemm_proj<<<dim3(18, MROWS / 128), 256, GSMEM>>>(a1f, wqf, qh, a2f, wkf, kvh);

    // attention core
    norm_reduce<<<BHn, 96>>>();
    gram_tc<<<dim3(BHn, SPLIT), 192>>>();
    softmax2_kernel<<<dim3(BHn, HDd), 96>>>();
    mbuild<<<dim3(6, BHn), 128>>>();

    // out = V @ M_b + bias (av folded into weights)
    gemm_out<<<dim3(CDIM / 128, MROWS / 128), 256, GSMEM>>>(bp, out);
}